// round 1
// baseline (speedup 1.0000x reference)
#include <cuda_runtime.h>
#include <math.h>

// Problem constants
#define Bb 2
#define Tt 2048
#define Cc 1024
#define Hh 16
#define Dd 64
#define Mm (Bb*Tt)           // 4096 tokens
#define ATT_SCALE 0.125f     // D^-0.5

// ---------------- scratch (device globals; no allocations allowed) ----------
__device__ float g_r1[Mm*Cc];
__device__ float g_routed[Mm*Cc];
__device__ float g_q[Mm*Cc];
__device__ float g_k[Mm*Cc];
__device__ float g_v[Mm*Cc];
__device__ float g_att[Mm*Cc];
__device__ float g_part[16*Bb*Cc];
__device__ float g_mean[Bb*Cc];

// ---------------- mean pool (deterministic two-stage) -----------------------
__global__ __launch_bounds__(256) void mean_part_kernel(const float* __restrict__ x) {
    // grid: (Cc/256, 16, Bb)
    int c  = blockIdx.x * 256 + threadIdx.x;
    int b  = blockIdx.z;
    int t0 = blockIdx.y * (Tt / 16);
    float s = 0.f;
    #pragma unroll 8
    for (int tt = 0; tt < Tt / 16; tt++)
        s += x[((size_t)b * Tt + t0 + tt) * Cc + c];
    g_part[((size_t)blockIdx.y * Bb + b) * Cc + c] = s;
}

__global__ __launch_bounds__(256) void mean_reduce_kernel() {
    int idx = blockIdx.x * 256 + threadIdx.x;   // b*Cc + c, 0..2047
    if (idx < Bb * Cc) {
        float s = 0.f;
        #pragma unroll
        for (int u = 0; u < 16; u++) s += g_part[(size_t)u * Bb * Cc + idx];
        g_mean[idx] = s * (1.0f / (float)Tt);
    }
}

// ---------------- SGEMM: Y[M,N] = X[M,K] @ W[N,K]^T + bias (opt tanh) -------
#define BM 128
#define BN 128
#define BK 8

template<bool TANH>
__global__ __launch_bounds__(256) void sgemm_nt(
    const float* __restrict__ A, const float* __restrict__ W,
    const float* __restrict__ bias, float* __restrict__ Cout,
    int M, int N, int K)
{
    __shared__ float As[BK][BM];
    __shared__ float Bs[BK][BN];

    int tid = threadIdx.x;
    int m0 = blockIdx.y * BM;
    int n0 = blockIdx.x * BN;
    int rm = (tid >> 4) * 8;    // 0..120
    int rn = (tid & 15) * 8;    // 0..120

    int lr = tid >> 1;          // 0..127
    int lc = (tid & 1) * 4;     // 0 or 4

    const float* Aptr = A + (size_t)(m0 + lr) * K + lc;
    const float* Wptr = W + (size_t)(n0 + lr) * K + lc;

    float acc[8][8];
    #pragma unroll
    for (int i = 0; i < 8; i++)
        #pragma unroll
        for (int j = 0; j < 8; j++) acc[i][j] = 0.f;

    for (int k0 = 0; k0 < K; k0 += BK) {
        float4 a4 = *(const float4*)(Aptr + k0);
        float4 b4 = *(const float4*)(Wptr + k0);
        __syncthreads();
        As[lc + 0][lr] = a4.x; As[lc + 1][lr] = a4.y;
        As[lc + 2][lr] = a4.z; As[lc + 3][lr] = a4.w;
        Bs[lc + 0][lr] = b4.x; Bs[lc + 1][lr] = b4.y;
        Bs[lc + 2][lr] = b4.z; Bs[lc + 3][lr] = b4.w;
        __syncthreads();
        #pragma unroll
        for (int k = 0; k < BK; k++) {
            float4 a0 = *(const float4*)&As[k][rm];
            float4 a1 = *(const float4*)&As[k][rm + 4];
            float4 b0 = *(const float4*)&Bs[k][rn];
            float4 b1 = *(const float4*)&Bs[k][rn + 4];
            float ar[8] = {a0.x, a0.y, a0.z, a0.w, a1.x, a1.y, a1.z, a1.w};
            float br[8] = {b0.x, b0.y, b0.z, b0.w, b1.x, b1.y, b1.z, b1.w};
            #pragma unroll
            for (int i = 0; i < 8; i++)
                #pragma unroll
                for (int j = 0; j < 8; j++)
                    acc[i][j] = fmaf(ar[i], br[j], acc[i][j]);
        }
    }

    #pragma unroll
    for (int i = 0; i < 8; i++) {
        int m = m0 + rm + i;
        float* crow = Cout + (size_t)m * N + n0 + rn;
        #pragma unroll
        for (int j = 0; j < 8; j++) {
            float val = acc[i][j] + bias[n0 + rn + j];
            if (TANH) val = tanhf(val);
            crow[j] = val;
        }
    }
}

// ---------------- routing: logits -> softmax -> routed memory ---------------
__global__ __launch_bounds__(128) void routing_kernel(
    const float* __restrict__ r1, const float* __restrict__ Wr2,
    const float* __restrict__ br2, const float* __restrict__ x,
    float* __restrict__ routed)
{
    int t = blockIdx.x;         // global token 0..4095
    int b = t >> 11;            // / Tt
    int tid = threadIdx.x;

    const float* rrow = r1 + (size_t)t * Cc;
    float s0 = 0.f, s1 = 0.f, s2 = 0.f;
    for (int c = tid; c < Cc; c += 128) {
        float vv = rrow[c];
        s0 = fmaf(vv, Wr2[c],          s0);
        s1 = fmaf(vv, Wr2[Cc + c],     s1);
        s2 = fmaf(vv, Wr2[2 * Cc + c], s2);
    }
    #pragma unroll
    for (int o = 16; o; o >>= 1) {
        s0 += __shfl_xor_sync(0xffffffffu, s0, o);
        s1 += __shfl_xor_sync(0xffffffffu, s1, o);
        s2 += __shfl_xor_sync(0xffffffffu, s2, o);
    }
    __shared__ float red[3][4];
    __shared__ float wsh[2];
    if ((tid & 31) == 0) {
        red[0][tid >> 5] = s0; red[1][tid >> 5] = s1; red[2][tid >> 5] = s2;
    }
    __syncthreads();
    if (tid == 0) {
        float l0 = red[0][0] + red[0][1] + red[0][2] + red[0][3] + br2[0];
        float l1 = red[1][0] + red[1][1] + red[1][2] + red[1][3] + br2[1];
        float l2 = red[2][0] + red[2][1] + red[2][2] + red[2][3] + br2[2];
        float mx = fmaxf(l0, fmaxf(l1, l2));
        float e0 = expf(l0 - mx), e1 = expf(l1 - mx), e2 = expf(l2 - mx);
        float inv = 1.0f / (e0 + e1 + e2);
        wsh[0] = e0 * inv; wsh[1] = e1 * inv;
    }
    __syncthreads();
    float w0 = wsh[0], w1 = wsh[1];

    const float4* x4 = (const float4*)(x + (size_t)t * Cc);
    const float4* m4 = (const float4*)(g_mean + (size_t)b * Cc);
    float4* o4 = (float4*)(routed + (size_t)t * Cc);
    for (int c4 = tid; c4 < Cc / 4; c4 += 128) {
        float4 xv = x4[c4], mv = m4[c4];
        float4 r;
        r.x = xv.x * w0 + mv.x * w1;
        r.y = xv.y * w0 + mv.y * w1;
        r.z = xv.z * w0 + mv.z * w1;
        r.w = xv.w * w0 + mv.w * w1;
        o4[c4] = r;
    }
}

// ---------------- flash attention (fp32, online softmax) --------------------
// grid: (Tt/128, Hh, Bb), 256 threads
// smem: Qt[64][132] (d-major, q*SCALE), Kt[64][68] (d-major), Vs[64][68], Ps[128][68]
#define FQT_LD 132
#define FK_LD 68
#define FSMEM_FLOATS (64*FQT_LD + 64*FK_LD + 64*FK_LD + 128*FK_LD)

__global__ __launch_bounds__(256) void flash_kernel(
    const float* __restrict__ q, const float* __restrict__ k,
    const float* __restrict__ v, float* __restrict__ o)
{
    extern __shared__ float sm[];
    float* Qt = sm;                        // [64][132]
    float* Kt = Qt + 64 * FQT_LD;          // [64][68]
    float* Vs = Kt + 64 * FK_LD;           // [64][68]
    float* Ps = Vs + 64 * FK_LD;           // [128][68]

    int tid = threadIdx.x;
    int q0 = blockIdx.x * 128;
    int h = blockIdx.y, b = blockIdx.z;

    const float* qb = q + (size_t)b * Tt * Cc + h * Dd;
    const float* kb = k + (size_t)b * Tt * Cc + h * Dd;
    const float* vb = v + (size_t)b * Tt * Cc + h * Dd;

    // load Q tile transposed, pre-scaled: 2048 float4s
    #pragma unroll
    for (int it = 0; it < 8; it++) {
        int idx = tid + it * 256;
        int r = idx >> 4;
        int dc = (idx & 15) << 2;
        float4 qv = *(const float4*)(qb + (size_t)(q0 + r) * Cc + dc);
        Qt[(dc + 0) * FQT_LD + r] = qv.x * ATT_SCALE;
        Qt[(dc + 1) * FQT_LD + r] = qv.y * ATT_SCALE;
        Qt[(dc + 2) * FQT_LD + r] = qv.z * ATT_SCALE;
        Qt[(dc + 3) * FQT_LD + r] = qv.w * ATT_SCALE;
    }

    int r0 = (tid >> 4) * 8;       // 8 query rows per thread
    int c4 = (tid & 15) * 4;       // 4 cols (j in S-phase, d in O-phase)

    float m_i[8], l_i[8], acc[8][4];
    #pragma unroll
    for (int i = 0; i < 8; i++) {
        m_i[i] = -1e30f; l_i[i] = 0.f;
        acc[i][0] = acc[i][1] = acc[i][2] = acc[i][3] = 0.f;
    }

    for (int kt = 0; kt < Tt; kt += 64) {
        __syncthreads();
        // load K (transposed) and V (natural)
        #pragma unroll
        for (int it = 0; it < 4; it++) {
            int idx = tid + it * 256;
            int j = idx >> 4;
            int dc = (idx & 15) << 2;
            float4 kv = *(const float4*)(kb + (size_t)(kt + j) * Cc + dc);
            Kt[(dc + 0) * FK_LD + j] = kv.x;
            Kt[(dc + 1) * FK_LD + j] = kv.y;
            Kt[(dc + 2) * FK_LD + j] = kv.z;
            Kt[(dc + 3) * FK_LD + j] = kv.w;
            float4 vv = *(const float4*)(vb + (size_t)(kt + j) * Cc + dc);
            *(float4*)&Vs[j * FK_LD + dc] = vv;
        }
        __syncthreads();

        // S = (Q*scale) @ K^T  (8x4 tile per thread)
        float s[8][4];
        #pragma unroll
        for (int i = 0; i < 8; i++)
            s[i][0] = s[i][1] = s[i][2] = s[i][3] = 0.f;
        #pragma unroll 4
        for (int d = 0; d < 64; d++) {
            float4 qa = *(const float4*)&Qt[d * FQT_LD + r0];
            float4 qb4 = *(const float4*)&Qt[d * FQT_LD + r0 + 4];
            float4 kk = *(const float4*)&Kt[d * FK_LD + c4];
            float qr[8] = {qa.x, qa.y, qa.z, qa.w, qb4.x, qb4.y, qb4.z, qb4.w};
            float kr[4] = {kk.x, kk.y, kk.z, kk.w};
            #pragma unroll
            for (int i = 0; i < 8; i++)
                #pragma unroll
                for (int jj = 0; jj < 4; jj++)
                    s[i][jj] = fmaf(qr[i], kr[jj], s[i][jj]);
        }

        // online softmax (row stats across the 16-lane group)
        #pragma unroll
        for (int i = 0; i < 8; i++) {
            float mx = fmaxf(fmaxf(s[i][0], s[i][1]), fmaxf(s[i][2], s[i][3]));
            #pragma unroll
            for (int off = 1; off < 16; off <<= 1)
                mx = fmaxf(mx, __shfl_xor_sync(0xffffffffu, mx, off));
            float mnew = fmaxf(m_i[i], mx);
            float corr = __expf(m_i[i] - mnew);
            m_i[i] = mnew;
            float rs = 0.f;
            #pragma unroll
            for (int jj = 0; jj < 4; jj++) {
                float p = __expf(s[i][jj] - mnew);
                Ps[(r0 + i) * FK_LD + c4 + jj] = p;
                rs += p;
            }
            #pragma unroll
            for (int off = 1; off < 16; off <<= 1)
                rs += __shfl_xor_sync(0xffffffffu, rs, off);
            l_i[i] = l_i[i] * corr + rs;
            acc[i][0] *= corr; acc[i][1] *= corr;
            acc[i][2] *= corr; acc[i][3] *= corr;
        }
        __syncthreads();

        // O += P @ V  (chunked over j, row-major P -> broadcast loads)
        #pragma unroll 4
        for (int jc = 0; jc < 64; jc += 4) {
            float4 vv[4];
            #pragma unroll
            for (int u = 0; u < 4; u++)
                vv[u] = *(const float4*)&Vs[(jc + u) * FK_LD + c4];
            #pragma unroll
            for (int i = 0; i < 8; i++) {
                float4 pv = *(const float4*)&Ps[(r0 + i) * FK_LD + jc];
                float pvu[4] = {pv.x, pv.y, pv.z, pv.w};
                #pragma unroll
                for (int u = 0; u < 4; u++) {
                    acc[i][0] = fmaf(pvu[u], vv[u].x, acc[i][0]);
                    acc[i][1] = fmaf(pvu[u], vv[u].y, acc[i][1]);
                    acc[i][2] = fmaf(pvu[u], vv[u].z, acc[i][2]);
                    acc[i][3] = fmaf(pvu[u], vv[u].w, acc[i][3]);
                }
            }
        }
    }

    float* ob = o + (size_t)b * Tt * Cc + h * Dd;
    #pragma unroll
    for (int i = 0; i < 8; i++) {
        float inv = 1.0f / l_i[i];
        float4 res;
        res.x = acc[i][0] * inv; res.y = acc[i][1] * inv;
        res.z = acc[i][2] * inv; res.w = acc[i][3] * inv;
        *(float4*)(ob + (size_t)(q0 + r0 + i) * Cc + c4) = res;
    }
}

// ---------------- host driver -----------------------------------------------
extern "C" void kernel_launch(void* const* d_in, const int* in_sizes, int n_in,
                              void* d_out, int out_size)
{
    const float* x   = (const float*)d_in[0];
    const float* Wq  = (const float*)d_in[1];
    const float* bq  = (const float*)d_in[2];
    const float* Wk  = (const float*)d_in[3];
    const float* bk  = (const float*)d_in[4];
    const float* Wv  = (const float*)d_in[5];
    const float* bv  = (const float*)d_in[6];
    const float* Wo  = (const float*)d_in[7];
    const float* bo  = (const float*)d_in[8];
    const float* Wr1 = (const float*)d_in[9];
    const float* br1 = (const float*)d_in[10];
    const float* Wr2 = (const float*)d_in[11];
    const float* br2 = (const float*)d_in[12];
    float* out = (float*)d_out;

    float *r1, *routed, *qp, *kp, *vp, *att;
    cudaGetSymbolAddress((void**)&r1,     g_r1);
    cudaGetSymbolAddress((void**)&routed, g_routed);
    cudaGetSymbolAddress((void**)&qp,     g_q);
    cudaGetSymbolAddress((void**)&kp,     g_k);
    cudaGetSymbolAddress((void**)&vp,     g_v);
    cudaGetSymbolAddress((void**)&att,    g_att);

    dim3 gemm_grid(Cc / BN, Mm / BM);   // (8, 32)

    mean_part_kernel<<<dim3(Cc / 256, 16, Bb), 256>>>(x);
    mean_reduce_kernel<<<(Bb * Cc) / 256, 256>>>();

    sgemm_nt<true><<<gemm_grid, 256>>>(x, Wr1, br1, r1, Mm, Cc, Cc);
    routing_kernel<<<Mm, 128>>>(r1, Wr2, br2, x, routed);

    sgemm_nt<false><<<gemm_grid, 256>>>(x,      Wq, bq, qp, Mm, Cc, Cc);
    sgemm_nt<false><<<gemm_grid, 256>>>(routed, Wk, bk, kp, Mm, Cc, Cc);
    sgemm_nt<false><<<gemm_grid, 256>>>(routed, Wv, bv, vp, Mm, Cc, Cc);

    int fsmem = FSMEM_FLOATS * (int)sizeof(float);   // 103,424 B
    cudaFuncSetAttribute(flash_kernel, cudaFuncAttributeMaxDynamicSharedMemorySize, fsmem);
    flash_kernel<<<dim3(Tt / 128, Hh, Bb), 256, fsmem>>>(qp, kp, vp, att);

    sgemm_nt<false><<<gemm_grid, 256>>>(att, Wo, bo, out, Mm, Cc, Cc);
}

// round 3
// speedup vs baseline: 1.2933x; 1.2933x over previous
#include <cuda_runtime.h>
#include <cuda_bf16.h>
#include <math.h>
#include <stdint.h>

// Problem constants
#define Bb 2
#define Tt 2048
#define Cc 1024
#define Hh 16
#define Dd 64
#define Mm (Bb*Tt)           // 4096 tokens
#define ATT_SCALE 0.125f     // D^-0.5

// ---------------- scratch (device globals; no allocations allowed) ----------
__device__ float g_r1[Mm*Cc];
__device__ float g_routed[Mm*Cc];
__device__ float g_q[Mm*Cc];
__device__ float g_k[Mm*Cc];
__device__ float g_v[Mm*Cc];
__device__ float g_att[Mm*Cc];
__device__ float g_part[16*Bb*Cc];
__device__ float g_mean[Bb*Cc];

// bf16 hi/lo split buffers
__device__ __nv_bfloat16 g_xhi[Mm*Cc],  g_xlo[Mm*Cc];
__device__ __nv_bfloat16 g_rthi[Mm*Cc], g_rtlo[Mm*Cc];
__device__ __nv_bfloat16 g_athi[Mm*Cc], g_atlo[Mm*Cc];
__device__ __nv_bfloat16 g_wq_hi[Cc*Cc], g_wq_lo[Cc*Cc];
__device__ __nv_bfloat16 g_wk_hi[Cc*Cc], g_wk_lo[Cc*Cc];
__device__ __nv_bfloat16 g_wv_hi[Cc*Cc], g_wv_lo[Cc*Cc];
__device__ __nv_bfloat16 g_wo_hi[Cc*Cc], g_wo_lo[Cc*Cc];
__device__ __nv_bfloat16 g_wr1_hi[Cc*Cc], g_wr1_lo[Cc*Cc];

// ================= PTX helpers (sm_100 baseline ISA only) ====================
__device__ __forceinline__ uint32_t smem_u32(const void* p) {
    uint32_t a;
    asm("{ .reg .u64 t; cvta.to.shared.u64 t, %1; cvt.u32.u64 %0, t; }"
        : "=r"(a) : "l"(p));
    return a;
}
__device__ __forceinline__ void cpasync16(uint32_t dst, const void* src) {
    asm volatile("cp.async.cg.shared.global [%0], [%1], 16;" :: "r"(dst), "l"(src));
}
__device__ __forceinline__ void ldsm4(uint32_t& r0, uint32_t& r1, uint32_t& r2,
                                      uint32_t& r3, uint32_t addr) {
    asm volatile("ldmatrix.sync.aligned.m8n8.x4.shared.b16 {%0,%1,%2,%3}, [%4];"
        : "=r"(r0), "=r"(r1), "=r"(r2), "=r"(r3) : "r"(addr));
}
__device__ __forceinline__ void mma16816(float* d, const uint32_t* a, const uint32_t* b) {
    asm volatile(
        "mma.sync.aligned.m16n8k16.row.col.f32.bf16.bf16.f32 "
        "{%0,%1,%2,%3}, {%4,%5,%6,%7}, {%8,%9}, {%0,%1,%2,%3};"
        : "+f"(d[0]), "+f"(d[1]), "+f"(d[2]), "+f"(d[3])
        : "r"(a[0]), "r"(a[1]), "r"(a[2]), "r"(a[3]), "r"(b[0]), "r"(b[1]));
}

// ---------------- mean pool (deterministic two-stage) -----------------------
__global__ __launch_bounds__(256) void mean_part_kernel(const float* __restrict__ x) {
    int c  = blockIdx.x * 256 + threadIdx.x;
    int b  = blockIdx.z;
    int t0 = blockIdx.y * (Tt / 16);
    float s = 0.f;
    #pragma unroll 8
    for (int tt = 0; tt < Tt / 16; tt++)
        s += x[((size_t)b * Tt + t0 + tt) * Cc + c];
    g_part[((size_t)blockIdx.y * Bb + b) * Cc + c] = s;
}

__global__ __launch_bounds__(256) void mean_reduce_kernel() {
    int idx = blockIdx.x * 256 + threadIdx.x;
    if (idx < Bb * Cc) {
        float s = 0.f;
        #pragma unroll
        for (int u = 0; u < 16; u++) s += g_part[(size_t)u * Bb * Cc + idx];
        g_mean[idx] = s * (1.0f / (float)Tt);
    }
}

// ---------------- fp32 -> bf16 hi/lo split -----------------------------------
__global__ __launch_bounds__(256) void cvt_hilo_kernel(
    const float* __restrict__ x, __nv_bfloat16* __restrict__ hi,
    __nv_bfloat16* __restrict__ lo, int n4)
{
    int i = blockIdx.x * 256 + threadIdx.x;
    if (i >= n4) return;
    float4 v = ((const float4*)x)[i];
    __nv_bfloat16 h0 = __float2bfloat16(v.x);
    __nv_bfloat16 h1 = __float2bfloat16(v.y);
    __nv_bfloat16 h2 = __float2bfloat16(v.z);
    __nv_bfloat16 h3 = __float2bfloat16(v.w);
    __nv_bfloat16 l0 = __float2bfloat16(v.x - __bfloat162float(h0));
    __nv_bfloat16 l1 = __float2bfloat16(v.y - __bfloat162float(h1));
    __nv_bfloat16 l2 = __float2bfloat16(v.z - __bfloat162float(h2));
    __nv_bfloat16 l3 = __float2bfloat16(v.w - __bfloat162float(h3));
    __nv_bfloat162 hh0; hh0.x = h0; hh0.y = h1;
    __nv_bfloat162 hh1; hh1.x = h2; hh1.y = h3;
    __nv_bfloat162 ll0; ll0.x = l0; ll0.y = l1;
    __nv_bfloat162 ll1; ll1.x = l2; ll1.y = l3;
    ((__nv_bfloat162*)hi)[i*2]   = hh0;
    ((__nv_bfloat162*)hi)[i*2+1] = hh1;
    ((__nv_bfloat162*)lo)[i*2]   = ll0;
    ((__nv_bfloat162*)lo)[i*2+1] = ll1;
}

// ================= HMMA GEMM =================================================
// Y[M,N] = A[M,K] @ W[N,K]^T + bias, bf16 split: Ahi*Bhi + Alo*Bhi + Ahi*Blo
// CTA tile 128x128, BK=32 bf16, 256 threads = 8 warps (4M x 2N, 32x64 each).
// cp.async double buffer; 96 chunks = 3 passes x 32.
#define G_NCH 96
#define A_LD 40          // halves per smem row (80B stride, conflict-free ldsm)

template<bool TANH>
__global__ __launch_bounds__(256, 1) void gemm_mma(
    const __nv_bfloat16* __restrict__ Ahi, const __nv_bfloat16* __restrict__ Alo,
    const __nv_bfloat16* __restrict__ Bhi, const __nv_bfloat16* __restrict__ Blo,
    const float* __restrict__ bias, float* __restrict__ out)
{
    __shared__ __nv_bfloat16 As[2][128 * A_LD];
    __shared__ __nv_bfloat16 Bs[2][128 * A_LD];

    int tid = threadIdx.x;
    int wid = tid >> 5;
    int l   = tid & 31;
    int wm  = wid >> 1;          // 0..3 (M)
    int wn  = wid & 1;           // 0..1 (N)
    int m0  = blockIdx.y * 128;
    int n0  = blockIdx.x * 128;

    uint32_t asb = smem_u32(&As[0][0]);
    uint32_t bsb = smem_u32(&Bs[0][0]);
    const uint32_t bufB = 128 * A_LD * 2;     // bytes per buffer

    // loader indices: idx in [0,512): row=idx>>2, chunk16=(idx&3)
    int lrow = tid >> 2;
    int lc16 = tid & 3;

    // ldmatrix per-lane address components
    int arow = wm * 32 + (l & 15);
    int akc  = (l >> 4) * 8;                 // 0 or 8
    int brow_in = (l & 7) + ((l >> 4) & 1) * 8;
    int bkc  = ((l >> 3) & 1) * 8;

    float acc[2][8][4];
    #pragma unroll
    for (int i = 0; i < 2; i++)
        #pragma unroll
        for (int j = 0; j < 8; j++)
            #pragma unroll
            for (int u = 0; u < 4; u++) acc[i][j][u] = 0.f;

    auto load_tile = [&](int c, int buf) {
        int p  = c >> 5;                     // 0: hi*hi, 1: lo*hi, 2: hi*lo
        int k0 = (c & 31) * 32;
        const __nv_bfloat16* ap = (p == 1) ? Alo : Ahi;
        const __nv_bfloat16* bp = (p == 2) ? Blo : Bhi;
        #pragma unroll
        for (int it = 0; it < 2; it++) {
            int row = lrow + it * 64;
            uint32_t da = asb + buf * bufB + (row * A_LD + lc16 * 8) * 2;
            cpasync16(da, ap + (size_t)(m0 + row) * Cc + k0 + lc16 * 8);
            uint32_t db = bsb + buf * bufB + (row * A_LD + lc16 * 8) * 2;
            cpasync16(db, bp + (size_t)(n0 + row) * Cc + k0 + lc16 * 8);
        }
    };

    load_tile(0, 0);
    asm volatile("cp.async.commit_group;");

    for (int c = 0; c < G_NCH; c++) {
        int buf = c & 1;
        if (c + 1 < G_NCH) {
            load_tile(c + 1, (c + 1) & 1);
            asm volatile("cp.async.commit_group;");
            asm volatile("cp.async.wait_group 1;");
        } else {
            asm volatile("cp.async.wait_group 0;");
        }
        __syncthreads();

        uint32_t ab = asb + buf * bufB;
        uint32_t bb = bsb + buf * bufB;
        #pragma unroll
        for (int ks = 0; ks < 2; ks++) {
            uint32_t afr[2][4];
            #pragma unroll
            for (int i = 0; i < 2; i++)
                ldsm4(afr[i][0], afr[i][1], afr[i][2], afr[i][3],
                      ab + ((arow + i * 16) * A_LD + akc + ks * 16) * 2);
            uint32_t bfr[4][4];
            #pragma unroll
            for (int nn = 0; nn < 4; nn++)
                ldsm4(bfr[nn][0], bfr[nn][1], bfr[nn][2], bfr[nn][3],
                      bb + ((wn * 64 + nn * 16 + brow_in) * A_LD + bkc + ks * 16) * 2);
            #pragma unroll
            for (int i = 0; i < 2; i++)
                #pragma unroll
                for (int j = 0; j < 8; j++)
                    mma16816(acc[i][j], afr[i], &bfr[j >> 1][(j & 1) * 2]);
        }
        __syncthreads();
    }

    // epilogue
    #pragma unroll
    for (int i = 0; i < 2; i++) {
        int row = m0 + wm * 32 + i * 16 + (l >> 2);
        #pragma unroll
        for (int j = 0; j < 8; j++) {
            int col = n0 + wn * 64 + j * 8 + (l & 3) * 2;
            float b0v = __ldg(&bias[col]);
            float b1v = __ldg(&bias[col + 1]);
            float v0 = acc[i][j][0] + b0v;
            float v1 = acc[i][j][1] + b1v;
            float v2 = acc[i][j][2] + b0v;
            float v3 = acc[i][j][3] + b1v;
            if (TANH) {
                v0 = tanhf(v0); v1 = tanhf(v1);
                v2 = tanhf(v2); v3 = tanhf(v3);
            }
            float2 p0; p0.x = v0; p0.y = v1;
            float2 p1; p1.x = v2; p1.y = v3;
            *(float2*)(out + (size_t)row * Cc + col) = p0;
            *(float2*)(out + (size_t)(row + 8) * Cc + col) = p1;
        }
    }
}

// ---------------- routing: logits -> softmax -> routed memory ---------------
__global__ __launch_bounds__(128) void routing_kernel(
    const float* __restrict__ r1, const float* __restrict__ Wr2,
    const float* __restrict__ br2, const float* __restrict__ x,
    float* __restrict__ routed)
{
    int t = blockIdx.x;
    int b = t >> 11;
    int tid = threadIdx.x;

    const float* rrow = r1 + (size_t)t * Cc;
    float s0 = 0.f, s1 = 0.f, s2 = 0.f;
    for (int c = tid; c < Cc; c += 128) {
        float vv = rrow[c];
        s0 = fmaf(vv, Wr2[c],          s0);
        s1 = fmaf(vv, Wr2[Cc + c],     s1);
        s2 = fmaf(vv, Wr2[2 * Cc + c], s2);
    }
    #pragma unroll
    for (int o = 16; o; o >>= 1) {
        s0 += __shfl_xor_sync(0xffffffffu, s0, o);
        s1 += __shfl_xor_sync(0xffffffffu, s1, o);
        s2 += __shfl_xor_sync(0xffffffffu, s2, o);
    }
    __shared__ float red[3][4];
    __shared__ float wsh[2];
    if ((tid & 31) == 0) {
        red[0][tid >> 5] = s0; red[1][tid >> 5] = s1; red[2][tid >> 5] = s2;
    }
    __syncthreads();
    if (tid == 0) {
        float l0 = red[0][0] + red[0][1] + red[0][2] + red[0][3] + br2[0];
        float l1 = red[1][0] + red[1][1] + red[1][2] + red[1][3] + br2[1];
        float l2 = red[2][0] + red[2][1] + red[2][2] + red[2][3] + br2[2];
        float mx = fmaxf(l0, fmaxf(l1, l2));
        float e0 = expf(l0 - mx), e1 = expf(l1 - mx), e2 = expf(l2 - mx);
        float inv = 1.0f / (e0 + e1 + e2);
        wsh[0] = e0 * inv; wsh[1] = e1 * inv;
    }
    __syncthreads();
    float w0 = wsh[0], w1 = wsh[1];

    const float4* x4 = (const float4*)(x + (size_t)t * Cc);
    const float4* m4 = (const float4*)(g_mean + (size_t)b * Cc);
    float4* o4 = (float4*)(routed + (size_t)t * Cc);
    for (int c4 = tid; c4 < Cc / 4; c4 += 128) {
        float4 xv = x4[c4], mv = m4[c4];
        float4 r;
        r.x = xv.x * w0 + mv.x * w1;
        r.y = xv.y * w0 + mv.y * w1;
        r.z = xv.z * w0 + mv.z * w1;
        r.w = xv.w * w0 + mv.w * w1;
        o4[c4] = r;
    }
}

// ---------------- flash attention (fp32, online softmax) --------------------
#define FQT_LD 132
#define FK_LD 68
#define FSMEM_FLOATS (64*FQT_LD + 64*FK_LD + 64*FK_LD + 128*FK_LD)

__global__ __launch_bounds__(256) void flash_kernel(
    const float* __restrict__ q, const float* __restrict__ k,
    const float* __restrict__ v, float* __restrict__ o)
{
    extern __shared__ float sm[];
    float* Qt = sm;
    float* Kt = Qt + 64 * FQT_LD;
    float* Vs = Kt + 64 * FK_LD;
    float* Ps = Vs + 64 * FK_LD;

    int tid = threadIdx.x;
    int q0 = blockIdx.x * 128;
    int h = blockIdx.y, b = blockIdx.z;

    const float* qb = q + (size_t)b * Tt * Cc + h * Dd;
    const float* kb = k + (size_t)b * Tt * Cc + h * Dd;
    const float* vb = v + (size_t)b * Tt * Cc + h * Dd;

    #pragma unroll
    for (int it = 0; it < 8; it++) {
        int idx = tid + it * 256;
        int r = idx >> 4;
        int dc = (idx & 15) << 2;
        float4 qv = *(const float4*)(qb + (size_t)(q0 + r) * Cc + dc);
        Qt[(dc + 0) * FQT_LD + r] = qv.x * ATT_SCALE;
        Qt[(dc + 1) * FQT_LD + r] = qv.y * ATT_SCALE;
        Qt[(dc + 2) * FQT_LD + r] = qv.z * ATT_SCALE;
        Qt[(dc + 3) * FQT_LD + r] = qv.w * ATT_SCALE;
    }

    int r0 = (tid >> 4) * 8;
    int c4 = (tid & 15) * 4;

    float m_i[8], l_i[8], acc[8][4];
    #pragma unroll
    for (int i = 0; i < 8; i++) {
        m_i[i] = -1e30f; l_i[i] = 0.f;
        acc[i][0] = acc[i][1] = acc[i][2] = acc[i][3] = 0.f;
    }

    for (int kt = 0; kt < Tt; kt += 64) {
        __syncthreads();
        #pragma unroll
        for (int it = 0; it < 4; it++) {
            int idx = tid + it * 256;
            int j = idx >> 4;
            int dc = (idx & 15) << 2;
            float4 kv = *(const float4*)(kb + (size_t)(kt + j) * Cc + dc);
            Kt[(dc + 0) * FK_LD + j] = kv.x;
            Kt[(dc + 1) * FK_LD + j] = kv.y;
            Kt[(dc + 2) * FK_LD + j] = kv.z;
            Kt[(dc + 3) * FK_LD + j] = kv.w;
            float4 vv = *(const float4*)(vb + (size_t)(kt + j) * Cc + dc);
            *(float4*)&Vs[j * FK_LD + dc] = vv;
        }
        __syncthreads();

        float s[8][4];
        #pragma unroll
        for (int i = 0; i < 8; i++)
            s[i][0] = s[i][1] = s[i][2] = s[i][3] = 0.f;
        #pragma unroll 4
        for (int d = 0; d < 64; d++) {
            float4 qa = *(const float4*)&Qt[d * FQT_LD + r0];
            float4 qb4 = *(const float4*)&Qt[d * FQT_LD + r0 + 4];
            float4 kk = *(const float4*)&Kt[d * FK_LD + c4];
            float qr[8] = {qa.x, qa.y, qa.z, qa.w, qb4.x, qb4.y, qb4.z, qb4.w};
            float kr[4] = {kk.x, kk.y, kk.z, kk.w};
            #pragma unroll
            for (int i = 0; i < 8; i++)
                #pragma unroll
                for (int jj = 0; jj < 4; jj++)
                    s[i][jj] = fmaf(qr[i], kr[jj], s[i][jj]);
        }

        #pragma unroll
        for (int i = 0; i < 8; i++) {
            float mx = fmaxf(fmaxf(s[i][0], s[i][1]), fmaxf(s[i][2], s[i][3]));
            #pragma unroll
            for (int off = 1; off < 16; off <<= 1)
                mx = fmaxf(mx, __shfl_xor_sync(0xffffffffu, mx, off));
            float mnew = fmaxf(m_i[i], mx);
            float corr = __expf(m_i[i] - mnew);
            m_i[i] = mnew;
            float rs = 0.f;
            #pragma unroll
            for (int jj = 0; jj < 4; jj++) {
                float p = __expf(s[i][jj] - mnew);
                Ps[(r0 + i) * FK_LD + c4 + jj] = p;
                rs += p;
            }
            #pragma unroll
            for (int off = 1; off < 16; off <<= 1)
                rs += __shfl_xor_sync(0xffffffffu, rs, off);
            l_i[i] = l_i[i] * corr + rs;
            acc[i][0] *= corr; acc[i][1] *= corr;
            acc[i][2] *= corr; acc[i][3] *= corr;
        }
        __syncthreads();

        #pragma unroll 4
        for (int jc = 0; jc < 64; jc += 4) {
            float4 vv[4];
            #pragma unroll
            for (int u = 0; u < 4; u++)
                vv[u] = *(const float4*)&Vs[(jc + u) * FK_LD + c4];
            #pragma unroll
            for (int i = 0; i < 8; i++) {
                float4 pv = *(const float4*)&Ps[(r0 + i) * FK_LD + jc];
                float pvu[4] = {pv.x, pv.y, pv.z, pv.w};
                #pragma unroll
                for (int u = 0; u < 4; u++) {
                    acc[i][0] = fmaf(pvu[u], vv[u].x, acc[i][0]);
                    acc[i][1] = fmaf(pvu[u], vv[u].y, acc[i][1]);
                    acc[i][2] = fmaf(pvu[u], vv[u].z, acc[i][2]);
                    acc[i][3] = fmaf(pvu[u], vv[u].w, acc[i][3]);
                }
            }
        }
    }

    float* ob = o + (size_t)b * Tt * Cc + h * Dd;
    #pragma unroll
    for (int i = 0; i < 8; i++) {
        float inv = 1.0f / l_i[i];
        float4 res;
        res.x = acc[i][0] * inv; res.y = acc[i][1] * inv;
        res.z = acc[i][2] * inv; res.w = acc[i][3] * inv;
        *(float4*)(ob + (size_t)(q0 + r0 + i) * Cc + c4) = res;
    }
}

// ---------------- host driver -----------------------------------------------
extern "C" void kernel_launch(void* const* d_in, const int* in_sizes, int n_in,
                              void* d_out, int out_size)
{
    const float* x   = (const float*)d_in[0];
    const float* Wq  = (const float*)d_in[1];
    const float* bq  = (const float*)d_in[2];
    const float* Wk  = (const float*)d_in[3];
    const float* bk  = (const float*)d_in[4];
    const float* Wv  = (const float*)d_in[5];
    const float* bv  = (const float*)d_in[6];
    const float* Wo  = (const float*)d_in[7];
    const float* bo  = (const float*)d_in[8];
    const float* Wr1 = (const float*)d_in[9];
    const float* br1 = (const float*)d_in[10];
    const float* Wr2 = (const float*)d_in[11];
    const float* br2 = (const float*)d_in[12];
    float* out = (float*)d_out;

    float *r1, *routed, *qp, *kp, *vp, *att;
    cudaGetSymbolAddress((void**)&r1,     g_r1);
    cudaGetSymbolAddress((void**)&routed, g_routed);
    cudaGetSymbolAddress((void**)&qp,     g_q);
    cudaGetSymbolAddress((void**)&kp,     g_k);
    cudaGetSymbolAddress((void**)&vp,     g_v);
    cudaGetSymbolAddress((void**)&att,    g_att);

    __nv_bfloat16 *xhi, *xlo, *rthi, *rtlo, *athi, *atlo;
    __nv_bfloat16 *wqh, *wql, *wkh, *wkl, *wvh, *wvl, *woh, *wol, *wr1h, *wr1l;
    cudaGetSymbolAddress((void**)&xhi,  g_xhi);  cudaGetSymbolAddress((void**)&xlo,  g_xlo);
    cudaGetSymbolAddress((void**)&rthi, g_rthi); cudaGetSymbolAddress((void**)&rtlo, g_rtlo);
    cudaGetSymbolAddress((void**)&athi, g_athi); cudaGetSymbolAddress((void**)&atlo, g_atlo);
    cudaGetSymbolAddress((void**)&wqh, g_wq_hi); cudaGetSymbolAddress((void**)&wql, g_wq_lo);
    cudaGetSymbolAddress((void**)&wkh, g_wk_hi); cudaGetSymbolAddress((void**)&wkl, g_wk_lo);
    cudaGetSymbolAddress((void**)&wvh, g_wv_hi); cudaGetSymbolAddress((void**)&wvl, g_wv_lo);
    cudaGetSymbolAddress((void**)&woh, g_wo_hi); cudaGetSymbolAddress((void**)&wol, g_wo_lo);
    cudaGetSymbolAddress((void**)&wr1h, g_wr1_hi); cudaGetSymbolAddress((void**)&wr1l, g_wr1_lo);

    dim3 gemm_grid(Cc / 128, Mm / 128);   // (8, 32)
    int act4 = (Mm * Cc) / 4;
    int w4   = (Cc * Cc) / 4;

    // mean pool
    mean_part_kernel<<<dim3(Cc / 256, 16, Bb), 256>>>(x);
    mean_reduce_kernel<<<(Bb * Cc) / 256, 256>>>();

    // conversions (input + weights)
    cvt_hilo_kernel<<<act4 / 256, 256>>>(x, xhi, xlo, act4);
    cvt_hilo_kernel<<<w4 / 256, 256>>>(Wr1, wr1h, wr1l, w4);
    cvt_hilo_kernel<<<w4 / 256, 256>>>(Wq, wqh, wql, w4);
    cvt_hilo_kernel<<<w4 / 256, 256>>>(Wk, wkh, wkl, w4);
    cvt_hilo_kernel<<<w4 / 256, 256>>>(Wv, wvh, wvl, w4);
    cvt_hilo_kernel<<<w4 / 256, 256>>>(Wo, woh, wol, w4);

    // r1 = tanh(x @ Wr1^T + br1)
    gemm_mma<true><<<gemm_grid, 256>>>(xhi, xlo, wr1h, wr1l, br1, r1);

    // routing + routed memory
    routing_kernel<<<Mm, 128>>>(r1, Wr2, br2, x, routed);
    cvt_hilo_kernel<<<act4 / 256, 256>>>(routed, rthi, rtlo, act4);

    // Q, K, V projections
    gemm_mma<false><<<gemm_grid, 256>>>(xhi,  xlo,  wqh, wql, bq, qp);
    gemm_mma<false><<<gemm_grid, 256>>>(rthi, rtlo, wkh, wkl, bk, kp);
    gemm_mma<false><<<gemm_grid, 256>>>(rthi, rtlo, wvh, wvl, bv, vp);

    // attention (fp32 flash)
    int fsmem = FSMEM_FLOATS * (int)sizeof(float);
    cudaFuncSetAttribute(flash_kernel, cudaFuncAttributeMaxDynamicSharedMemorySize, fsmem);
    flash_kernel<<<dim3(Tt / 128, Hh, Bb), 256, fsmem>>>(qp, kp, vp, att);

    // output projection
    cvt_hilo_kernel<<<act4 / 256, 256>>>(att, athi, atlo, act4);
    gemm_mma<false><<<gemm_grid, 256>>>(athi, atlo, woh, wol, bo, out);
}

// round 4
// speedup vs baseline: 1.9363x; 1.4972x over previous
#include <cuda_runtime.h>
#include <cuda_bf16.h>
#include <math.h>
#include <stdint.h>

// Problem constants
#define Bb 2
#define Tt 2048
#define Cc 1024
#define Hh 16
#define Dd 64
#define Mm (Bb*Tt)           // 4096 tokens
#define ATT_SCALE 0.125f     // D^-0.5

// ---------------- scratch (device globals; no allocations allowed) ----------
__device__ float g_r1[Mm*Cc];
__device__ float g_routed[Mm*Cc];
__device__ float g_part[16*Bb*Cc];
__device__ float g_mean[Bb*Cc];

// bf16 hi/lo split buffers
__device__ __nv_bfloat16 g_xhi[Mm*Cc],  g_xlo[Mm*Cc];
__device__ __nv_bfloat16 g_rthi[Mm*Cc], g_rtlo[Mm*Cc];
__device__ __nv_bfloat16 g_athi[Mm*Cc], g_atlo[Mm*Cc];
__device__ __nv_bfloat16 g_qhi[Mm*Cc],  g_qlo[Mm*Cc];
__device__ __nv_bfloat16 g_khi[Mm*Cc],  g_klo[Mm*Cc];
__device__ __nv_bfloat16 g_vhi[Mm*Cc],  g_vlo[Mm*Cc];
__device__ __nv_bfloat16 g_wq_hi[Cc*Cc], g_wq_lo[Cc*Cc];
__device__ __nv_bfloat16 g_wk_hi[Cc*Cc], g_wk_lo[Cc*Cc];
__device__ __nv_bfloat16 g_wv_hi[Cc*Cc], g_wv_lo[Cc*Cc];
__device__ __nv_bfloat16 g_wo_hi[Cc*Cc], g_wo_lo[Cc*Cc];
__device__ __nv_bfloat16 g_wr1_hi[Cc*Cc], g_wr1_lo[Cc*Cc];

// ================= PTX helpers (sm_100 baseline ISA only) ====================
__device__ __forceinline__ uint32_t smem_u32(const void* p) {
    uint32_t a;
    asm("{ .reg .u64 t; cvta.to.shared.u64 t, %1; cvt.u32.u64 %0, t; }"
        : "=r"(a) : "l"(p));
    return a;
}
__device__ __forceinline__ void cpasync16(uint32_t dst, const void* src) {
    asm volatile("cp.async.cg.shared.global [%0], [%1], 16;" :: "r"(dst), "l"(src));
}
__device__ __forceinline__ void ldsm4(uint32_t& r0, uint32_t& r1, uint32_t& r2,
                                      uint32_t& r3, uint32_t addr) {
    asm volatile("ldmatrix.sync.aligned.m8n8.x4.shared.b16 {%0,%1,%2,%3}, [%4];"
        : "=r"(r0), "=r"(r1), "=r"(r2), "=r"(r3) : "r"(addr));
}
__device__ __forceinline__ void ldsm4t(uint32_t& r0, uint32_t& r1, uint32_t& r2,
                                       uint32_t& r3, uint32_t addr) {
    asm volatile("ldmatrix.sync.aligned.m8n8.x4.trans.shared.b16 {%0,%1,%2,%3}, [%4];"
        : "=r"(r0), "=r"(r1), "=r"(r2), "=r"(r3) : "r"(addr));
}
__device__ __forceinline__ void mma16816(float* d, const uint32_t* a, const uint32_t* b) {
    asm volatile(
        "mma.sync.aligned.m16n8k16.row.col.f32.bf16.bf16.f32 "
        "{%0,%1,%2,%3}, {%4,%5,%6,%7}, {%8,%9}, {%0,%1,%2,%3};"
        : "+f"(d[0]), "+f"(d[1]), "+f"(d[2]), "+f"(d[3])
        : "r"(a[0]), "r"(a[1]), "r"(a[2]), "r"(a[3]), "r"(b[0]), "r"(b[1]));
}
__device__ __forceinline__ uint32_t pack_bf2(float a, float b) {
    unsigned short lo = __bfloat16_as_ushort(__float2bfloat16_rn(a));
    unsigned short hi = __bfloat16_as_ushort(__float2bfloat16_rn(b));
    return ((uint32_t)hi << 16) | lo;
}

// ---------------- mean pool (deterministic two-stage) -----------------------
__global__ __launch_bounds__(256) void mean_part_kernel(const float* __restrict__ x) {
    int c  = blockIdx.x * 256 + threadIdx.x;
    int b  = blockIdx.z;
    int t0 = blockIdx.y * (Tt / 16);
    float s = 0.f;
    #pragma unroll 8
    for (int tt = 0; tt < Tt / 16; tt++)
        s += x[((size_t)b * Tt + t0 + tt) * Cc + c];
    g_part[((size_t)blockIdx.y * Bb + b) * Cc + c] = s;
}

__global__ __launch_bounds__(256) void mean_reduce_kernel() {
    int idx = blockIdx.x * 256 + threadIdx.x;
    if (idx < Bb * Cc) {
        float s = 0.f;
        #pragma unroll
        for (int u = 0; u < 16; u++) s += g_part[(size_t)u * Bb * Cc + idx];
        g_mean[idx] = s * (1.0f / (float)Tt);
    }
}

// ---------------- fp32 -> bf16 hi/lo split -----------------------------------
__global__ __launch_bounds__(256) void cvt_hilo_kernel(
    const float* __restrict__ x, __nv_bfloat16* __restrict__ hi,
    __nv_bfloat16* __restrict__ lo, int n4)
{
    int i = blockIdx.x * 256 + threadIdx.x;
    if (i >= n4) return;
    float4 v = ((const float4*)x)[i];
    __nv_bfloat16 h0 = __float2bfloat16(v.x);
    __nv_bfloat16 h1 = __float2bfloat16(v.y);
    __nv_bfloat16 h2 = __float2bfloat16(v.z);
    __nv_bfloat16 h3 = __float2bfloat16(v.w);
    __nv_bfloat16 l0 = __float2bfloat16(v.x - __bfloat162float(h0));
    __nv_bfloat16 l1 = __float2bfloat16(v.y - __bfloat162float(h1));
    __nv_bfloat16 l2 = __float2bfloat16(v.z - __bfloat162float(h2));
    __nv_bfloat16 l3 = __float2bfloat16(v.w - __bfloat162float(h3));
    __nv_bfloat162 hh0; hh0.x = h0; hh0.y = h1;
    __nv_bfloat162 hh1; hh1.x = h2; hh1.y = h3;
    __nv_bfloat162 ll0; ll0.x = l0; ll0.y = l1;
    __nv_bfloat162 ll1; ll1.x = l2; ll1.y = l3;
    ((__nv_bfloat162*)hi)[i*2]   = hh0;
    ((__nv_bfloat162*)hi)[i*2+1] = hh1;
    ((__nv_bfloat162*)lo)[i*2]   = ll0;
    ((__nv_bfloat162*)lo)[i*2+1] = ll1;
}

// ================= HMMA GEMM =================================================
// Y[M,N] = A[M,K] @ W[N,K]^T + bias, bf16 split: Ahi*Bhi + Alo*Bhi + Ahi*Blo
// MODE 0: fp32 out; MODE 1: tanh fp32 out; MODE 2: bf16 hi/lo out (x scale)
#define G_NCH 96
#define A_LD 40

template<int MODE>
__global__ __launch_bounds__(256, 1) void gemm_mma(
    const __nv_bfloat16* __restrict__ Ahi, const __nv_bfloat16* __restrict__ Alo,
    const __nv_bfloat16* __restrict__ Bhi, const __nv_bfloat16* __restrict__ Blo,
    const float* __restrict__ bias, float* __restrict__ out,
    __nv_bfloat16* __restrict__ outhi, __nv_bfloat16* __restrict__ outlo,
    float scale)
{
    __shared__ __nv_bfloat16 As[2][128 * A_LD];
    __shared__ __nv_bfloat16 Bs[2][128 * A_LD];

    int tid = threadIdx.x;
    int wid = tid >> 5;
    int l   = tid & 31;
    int wm  = wid >> 1;
    int wn  = wid & 1;
    int m0  = blockIdx.y * 128;
    int n0  = blockIdx.x * 128;

    uint32_t asb = smem_u32(&As[0][0]);
    uint32_t bsb = smem_u32(&Bs[0][0]);
    const uint32_t bufB = 128 * A_LD * 2;

    int lrow = tid >> 2;
    int lc16 = tid & 3;

    int arow = wm * 32 + (l & 15);
    int akc  = (l >> 4) * 8;
    int brow_in = (l & 7) + ((l >> 4) & 1) * 8;
    int bkc  = ((l >> 3) & 1) * 8;

    float acc[2][8][4];
    #pragma unroll
    for (int i = 0; i < 2; i++)
        #pragma unroll
        for (int j = 0; j < 8; j++)
            #pragma unroll
            for (int u = 0; u < 4; u++) acc[i][j][u] = 0.f;

    auto load_tile = [&](int c, int buf) {
        int p  = c >> 5;
        int k0 = (c & 31) * 32;
        const __nv_bfloat16* ap = (p == 1) ? Alo : Ahi;
        const __nv_bfloat16* bp = (p == 2) ? Blo : Bhi;
        #pragma unroll
        for (int it = 0; it < 2; it++) {
            int row = lrow + it * 64;
            uint32_t da = asb + buf * bufB + (row * A_LD + lc16 * 8) * 2;
            cpasync16(da, ap + (size_t)(m0 + row) * Cc + k0 + lc16 * 8);
            uint32_t db = bsb + buf * bufB + (row * A_LD + lc16 * 8) * 2;
            cpasync16(db, bp + (size_t)(n0 + row) * Cc + k0 + lc16 * 8);
        }
    };

    load_tile(0, 0);
    asm volatile("cp.async.commit_group;");

    for (int c = 0; c < G_NCH; c++) {
        int buf = c & 1;
        if (c + 1 < G_NCH) {
            load_tile(c + 1, (c + 1) & 1);
            asm volatile("cp.async.commit_group;");
            asm volatile("cp.async.wait_group 1;");
        } else {
            asm volatile("cp.async.wait_group 0;");
        }
        __syncthreads();

        uint32_t ab = asb + buf * bufB;
        uint32_t bb = bsb + buf * bufB;
        #pragma unroll
        for (int ks = 0; ks < 2; ks++) {
            uint32_t afr[2][4];
            #pragma unroll
            for (int i = 0; i < 2; i++)
                ldsm4(afr[i][0], afr[i][1], afr[i][2], afr[i][3],
                      ab + ((arow + i * 16) * A_LD + akc + ks * 16) * 2);
            uint32_t bfr[4][4];
            #pragma unroll
            for (int nn = 0; nn < 4; nn++)
                ldsm4(bfr[nn][0], bfr[nn][1], bfr[nn][2], bfr[nn][3],
                      bb + ((wn * 64 + nn * 16 + brow_in) * A_LD + bkc + ks * 16) * 2);
            #pragma unroll
            for (int i = 0; i < 2; i++)
                #pragma unroll
                for (int j = 0; j < 8; j++)
                    mma16816(acc[i][j], afr[i], &bfr[j >> 1][(j & 1) * 2]);
        }
        __syncthreads();
    }

    // epilogue
    #pragma unroll
    for (int i = 0; i < 2; i++) {
        int row = m0 + wm * 32 + i * 16 + (l >> 2);
        #pragma unroll
        for (int j = 0; j < 8; j++) {
            int col = n0 + wn * 64 + j * 8 + (l & 3) * 2;
            float b0v = __ldg(&bias[col]);
            float b1v = __ldg(&bias[col + 1]);
            float v0 = acc[i][j][0] + b0v;
            float v1 = acc[i][j][1] + b1v;
            float v2 = acc[i][j][2] + b0v;
            float v3 = acc[i][j][3] + b1v;
            if (MODE == 1) {
                v0 = tanhf(v0); v1 = tanhf(v1);
                v2 = tanhf(v2); v3 = tanhf(v3);
            }
            if (MODE == 2) {
                v0 *= scale; v1 *= scale; v2 *= scale; v3 *= scale;
                uint32_t h0 = pack_bf2(v0, v1);
                uint32_t h1 = pack_bf2(v2, v3);
                float r0 = v0 - __bfloat162float(__ushort_as_bfloat16((unsigned short)(h0 & 0xffff)));
                float r1 = v1 - __bfloat162float(__ushort_as_bfloat16((unsigned short)(h0 >> 16)));
                float r2 = v2 - __bfloat162float(__ushort_as_bfloat16((unsigned short)(h1 & 0xffff)));
                float r3 = v3 - __bfloat162float(__ushort_as_bfloat16((unsigned short)(h1 >> 16)));
                *(uint32_t*)(outhi + (size_t)row * Cc + col) = h0;
                *(uint32_t*)(outhi + (size_t)(row + 8) * Cc + col) = h1;
                *(uint32_t*)(outlo + (size_t)row * Cc + col) = pack_bf2(r0, r1);
                *(uint32_t*)(outlo + (size_t)(row + 8) * Cc + col) = pack_bf2(r2, r3);
            } else {
                float2 p0; p0.x = v0; p0.y = v1;
                float2 p1; p1.x = v2; p1.y = v3;
                *(float2*)(out + (size_t)row * Cc + col) = p0;
                *(float2*)(out + (size_t)(row + 8) * Cc + col) = p1;
            }
        }
    }
}

// ---------------- routing: logits -> softmax -> routed memory ---------------
__global__ __launch_bounds__(128) void routing_kernel(
    const float* __restrict__ r1, const float* __restrict__ Wr2,
    const float* __restrict__ br2, const float* __restrict__ x,
    float* __restrict__ routed)
{
    int t = blockIdx.x;
    int b = t >> 11;
    int tid = threadIdx.x;

    const float* rrow = r1 + (size_t)t * Cc;
    float s0 = 0.f, s1 = 0.f, s2 = 0.f;
    for (int c = tid; c < Cc; c += 128) {
        float vv = rrow[c];
        s0 = fmaf(vv, Wr2[c],          s0);
        s1 = fmaf(vv, Wr2[Cc + c],     s1);
        s2 = fmaf(vv, Wr2[2 * Cc + c], s2);
    }
    #pragma unroll
    for (int o = 16; o; o >>= 1) {
        s0 += __shfl_xor_sync(0xffffffffu, s0, o);
        s1 += __shfl_xor_sync(0xffffffffu, s1, o);
        s2 += __shfl_xor_sync(0xffffffffu, s2, o);
    }
    __shared__ float red[3][4];
    __shared__ float wsh[2];
    if ((tid & 31) == 0) {
        red[0][tid >> 5] = s0; red[1][tid >> 5] = s1; red[2][tid >> 5] = s2;
    }
    __syncthreads();
    if (tid == 0) {
        float l0 = red[0][0] + red[0][1] + red[0][2] + red[0][3] + br2[0];
        float l1 = red[1][0] + red[1][1] + red[1][2] + red[1][3] + br2[1];
        float l2 = red[2][0] + red[2][1] + red[2][2] + red[2][3] + br2[2];
        float mx = fmaxf(l0, fmaxf(l1, l2));
        float e0 = expf(l0 - mx), e1 = expf(l1 - mx), e2 = expf(l2 - mx);
        float inv = 1.0f / (e0 + e1 + e2);
        wsh[0] = e0 * inv; wsh[1] = e1 * inv;
    }
    __syncthreads();
    float w0 = wsh[0], w1 = wsh[1];

    const float4* x4 = (const float4*)(x + (size_t)t * Cc);
    const float4* m4 = (const float4*)(g_mean + (size_t)b * Cc);
    float4* o4 = (float4*)(routed + (size_t)t * Cc);
    for (int c4 = tid; c4 < Cc / 4; c4 += 128) {
        float4 xv = x4[c4], mv = m4[c4];
        float4 r;
        r.x = xv.x * w0 + mv.x * w1;
        r.y = xv.y * w0 + mv.y * w1;
        r.z = xv.z * w0 + mv.z * w1;
        r.w = xv.w * w0 + mv.w * w1;
        o4[c4] = r;
    }
}

// ================= tensor-core flash attention ===============================
// CTA: 128 Q rows (8 warps x 16), KV chunks of 64, D=64.
// S = 3-term bf16 split (Qhi*Khi + Qlo*Khi + Qhi*Klo); Q pre-scaled by 0.125.
// P@V = 3-term (Phi*Vhi + Plo*Vhi + Phi*Vlo), P split in registers.
#define F_LD 72
#define FQ_HALVES (128 * F_LD)
#define FS_HALVES (64 * F_LD)
// smem (halves): Qhi @0, Qlo @FQ_HALVES, stage s @ 2*FQ_HALVES + s*4*FS_HALVES
#define F_STAGE0 (2 * FQ_HALVES)
#define F_SMEM_BYTES ((2 * FQ_HALVES + 2 * 4 * FS_HALVES) * 2)

__global__ __launch_bounds__(256, 1) void flash_mma(
    const __nv_bfloat16* __restrict__ qhi, const __nv_bfloat16* __restrict__ qlo,
    const __nv_bfloat16* __restrict__ khi, const __nv_bfloat16* __restrict__ klo,
    const __nv_bfloat16* __restrict__ vhi, const __nv_bfloat16* __restrict__ vlo,
    __nv_bfloat16* __restrict__ ohi, __nv_bfloat16* __restrict__ olo)
{
    extern __shared__ __nv_bfloat16 fs[];
    uint32_t fsb = smem_u32(fs);

    int tid = threadIdx.x;
    int w   = tid >> 5;
    int l   = tid & 31;
    int q0  = blockIdx.x * 128;
    int h   = blockIdx.y;
    int b   = blockIdx.z;
    int tokb = b * Tt;
    int hoff = h * Dd;

    // ---- load Q (hi+lo) ----
    {
        const __nv_bfloat16* srcs[2] = {qhi, qlo};
        #pragma unroll
        for (int ten = 0; ten < 2; ten++) {
            #pragma unroll
            for (int it = 0; it < 4; it++) {
                int idx = tid + it * 256;          // [0,1024)
                int row = idx >> 3, c16 = idx & 7;
                uint32_t dst = fsb + ((ten * FQ_HALVES) + row * F_LD + c16 * 8) * 2;
                cpasync16(dst, srcs[ten] + (size_t)(tokb + q0 + row) * Cc + hoff + c16 * 8);
            }
        }
    }
    auto load_kv = [&](int c, int s) {
        int kt0 = c * 64;
        const __nv_bfloat16* srcs[4] = {khi, klo, vhi, vlo};
        #pragma unroll
        for (int ten = 0; ten < 4; ten++) {
            #pragma unroll
            for (int it = 0; it < 2; it++) {
                int idx = tid + it * 256;          // [0,512)
                int row = idx >> 3, c16 = idx & 7;
                uint32_t dst = fsb + ((F_STAGE0 + s * 4 * FS_HALVES + ten * FS_HALVES)
                                      + row * F_LD + c16 * 8) * 2;
                cpasync16(dst, srcs[ten] + (size_t)(tokb + kt0 + row) * Cc + hoff + c16 * 8);
            }
        }
    };

    load_kv(0, 0);
    asm volatile("cp.async.commit_group;");
    load_kv(1, 1);
    asm volatile("cp.async.commit_group;");

    // fragment geometry
    int arow = (l & 15);
    int akc  = (l >> 4) * 8;
    int brow_in = (l & 7) + ((l >> 4) & 1) * 8;
    int bkc  = ((l >> 3) & 1) * 8;
    int vrow = (l & 7) + ((l >> 3) & 1) * 8;
    int vcol = ((l >> 4) & 1) * 8;

    uint32_t qh[4][4], ql[4][4];
    float oacc[8][4];
    #pragma unroll
    for (int j = 0; j < 8; j++)
        #pragma unroll
        for (int u = 0; u < 4; u++) oacc[j][u] = 0.f;
    float m0r = -1e30f, m1r = -1e30f, l0r = 0.f, l1r = 0.f;

    bool qdone = false;

    for (int c = 0; c < Tt / 64; c++) {
        if (c + 1 < Tt / 64) asm volatile("cp.async.wait_group 1;");
        else                 asm volatile("cp.async.wait_group 0;");
        __syncthreads();

        if (!qdone) {
            // extract Q fragments once (Q + chunk0 arrived together)
            #pragma unroll
            for (int kt = 0; kt < 4; kt++) {
                ldsm4(qh[kt][0], qh[kt][1], qh[kt][2], qh[kt][3],
                      fsb + ((w * 16 + arow) * F_LD + kt * 16 + akc) * 2);
                ldsm4(ql[kt][0], ql[kt][1], ql[kt][2], ql[kt][3],
                      fsb + (FQ_HALVES + (w * 16 + arow) * F_LD + kt * 16 + akc) * 2);
            }
            qdone = true;
        }

        uint32_t SB = F_STAGE0 + (c & 1) * 4 * FS_HALVES;
        uint32_t KHI = SB, KLO = SB + FS_HALVES;
        uint32_t VHI = SB + 2 * FS_HALVES, VLO = SB + 3 * FS_HALVES;

        // ---- S = Q K^T (3-term split) ----
        float sacc[8][4];
        #pragma unroll
        for (int j = 0; j < 8; j++)
            #pragma unroll
            for (int u = 0; u < 4; u++) sacc[j][u] = 0.f;

        #pragma unroll
        for (int ks = 0; ks < 4; ks++) {
            uint32_t kh[4][4], klr[4][4];
            #pragma unroll
            for (int g = 0; g < 4; g++) {
                uint32_t ro = ((g * 16 + brow_in) * F_LD + bkc + ks * 16) * 2;
                ldsm4(kh[g][0], kh[g][1], kh[g][2], kh[g][3], fsb + KHI * 2 + ro);
                ldsm4(klr[g][0], klr[g][1], klr[g][2], klr[g][3], fsb + KLO * 2 + ro);
            }
            #pragma unroll
            for (int g = 0; g < 4; g++)
                #pragma unroll
                for (int sub = 0; sub < 2; sub++) {
                    int j = g * 2 + sub;
                    mma16816(sacc[j], qh[ks], &kh[g][sub * 2]);
                    mma16816(sacc[j], ql[ks], &kh[g][sub * 2]);
                    mma16816(sacc[j], qh[ks], &klr[g][sub * 2]);
                }
        }

        // ---- online softmax + P split (register-resident) ----
        float mx0 = -1e30f, mx1 = -1e30f;
        #pragma unroll
        for (int j = 0; j < 8; j++) {
            mx0 = fmaxf(mx0, fmaxf(sacc[j][0], sacc[j][1]));
            mx1 = fmaxf(mx1, fmaxf(sacc[j][2], sacc[j][3]));
        }
        mx0 = fmaxf(mx0, __shfl_xor_sync(0xffffffffu, mx0, 1));
        mx0 = fmaxf(mx0, __shfl_xor_sync(0xffffffffu, mx0, 2));
        mx1 = fmaxf(mx1, __shfl_xor_sync(0xffffffffu, mx1, 1));
        mx1 = fmaxf(mx1, __shfl_xor_sync(0xffffffffu, mx1, 2));
        float mn0 = fmaxf(m0r, mx0), mn1 = fmaxf(m1r, mx1);
        float cor0 = __expf(m0r - mn0), cor1 = __expf(m1r - mn1);
        m0r = mn0; m1r = mn1;

        uint32_t phi[4][4], plo[4][4];
        float rs0 = 0.f, rs1 = 0.f;
        #pragma unroll
        for (int j = 0; j < 8; j++) {
            float e0 = __expf(sacc[j][0] - mn0);
            float e1 = __expf(sacc[j][1] - mn0);
            float e2 = __expf(sacc[j][2] - mn1);
            float e3 = __expf(sacc[j][3] - mn1);
            rs0 += e0 + e1; rs1 += e2 + e3;
            int kt = j >> 1, sl = (j & 1) * 2;
            uint32_t h01 = pack_bf2(e0, e1);
            uint32_t h23 = pack_bf2(e2, e3);
            phi[kt][sl]     = h01;
            phi[kt][sl + 1] = h23;
            float r0 = e0 - __bfloat162float(__ushort_as_bfloat16((unsigned short)(h01 & 0xffff)));
            float r1 = e1 - __bfloat162float(__ushort_as_bfloat16((unsigned short)(h01 >> 16)));
            float r2 = e2 - __bfloat162float(__ushort_as_bfloat16((unsigned short)(h23 & 0xffff)));
            float r3 = e3 - __bfloat162float(__ushort_as_bfloat16((unsigned short)(h23 >> 16)));
            plo[kt][sl]     = pack_bf2(r0, r1);
            plo[kt][sl + 1] = pack_bf2(r2, r3);
        }
        rs0 += __shfl_xor_sync(0xffffffffu, rs0, 1);
        rs0 += __shfl_xor_sync(0xffffffffu, rs0, 2);
        rs1 += __shfl_xor_sync(0xffffffffu, rs1, 1);
        rs1 += __shfl_xor_sync(0xffffffffu, rs1, 2);
        l0r = l0r * cor0 + rs0;
        l1r = l1r * cor1 + rs1;
        #pragma unroll
        for (int j = 0; j < 8; j++) {
            oacc[j][0] *= cor0; oacc[j][1] *= cor0;
            oacc[j][2] *= cor1; oacc[j][3] *= cor1;
        }

        // ---- O += P V (3-term) ----
        #pragma unroll
        for (int kt = 0; kt < 4; kt++) {
            #pragma unroll
            for (int dg = 0; dg < 4; dg++) {
                uint32_t vh[4], vl[4];
                uint32_t ro = ((kt * 16 + vrow) * F_LD + dg * 16 + vcol) * 2;
                ldsm4t(vh[0], vh[1], vh[2], vh[3], fsb + VHI * 2 + ro);
                ldsm4t(vl[0], vl[1], vl[2], vl[3], fsb + VLO * 2 + ro);
                #pragma unroll
                for (int sub = 0; sub < 2; sub++) {
                    int dt = dg * 2 + sub;
                    mma16816(oacc[dt], phi[kt], &vh[sub * 2]);
                    mma16816(oacc[dt], plo[kt], &vh[sub * 2]);
                    mma16816(oacc[dt], phi[kt], &vl[sub * 2]);
                }
            }
        }

        __syncthreads();
        if (c + 2 < Tt / 64) {
            load_kv(c + 2, c & 1);
            asm volatile("cp.async.commit_group;");
        }
    }

    // ---- epilogue: normalize, hi/lo split, write ----
    float inv0 = 1.0f / l0r, inv1 = 1.0f / l1r;
    int row0 = tokb + q0 + w * 16 + (l >> 2);
    int row1 = row0 + 8;
    #pragma unroll
    for (int dt = 0; dt < 8; dt++) {
        int col = hoff + dt * 8 + (l & 3) * 2;
        float v0 = oacc[dt][0] * inv0, v1 = oacc[dt][1] * inv0;
        float v2 = oacc[dt][2] * inv1, v3 = oacc[dt][3] * inv1;
        uint32_t h0 = pack_bf2(v0, v1);
        uint32_t h1 = pack_bf2(v2, v3);
        float r0 = v0 - __bfloat162float(__ushort_as_bfloat16((unsigned short)(h0 & 0xffff)));
        float r1 = v1 - __bfloat162float(__ushort_as_bfloat16((unsigned short)(h0 >> 16)));
        float r2 = v2 - __bfloat162float(__ushort_as_bfloat16((unsigned short)(h1 & 0xffff)));
        float r3 = v3 - __bfloat162float(__ushort_as_bfloat16((unsigned short)(h1 >> 16)));
        *(uint32_t*)(ohi + (size_t)row0 * Cc + col) = h0;
        *(uint32_t*)(ohi + (size_t)row1 * Cc + col) = h1;
        *(uint32_t*)(olo + (size_t)row0 * Cc + col) = pack_bf2(r0, r1);
        *(uint32_t*)(olo + (size_t)row1 * Cc + col) = pack_bf2(r2, r3);
    }
}

// ---------------- host driver -----------------------------------------------
extern "C" void kernel_launch(void* const* d_in, const int* in_sizes, int n_in,
                              void* d_out, int out_size)
{
    const float* x   = (const float*)d_in[0];
    const float* Wq  = (const float*)d_in[1];
    const float* bq  = (const float*)d_in[2];
    const float* Wk  = (const float*)d_in[3];
    const float* bk  = (const float*)d_in[4];
    const float* Wv  = (const float*)d_in[5];
    const float* bv  = (const float*)d_in[6];
    const float* Wo  = (const float*)d_in[7];
    const float* bo  = (const float*)d_in[8];
    const float* Wr1 = (const float*)d_in[9];
    const float* br1 = (const float*)d_in[10];
    const float* Wr2 = (const float*)d_in[11];
    const float* br2 = (const float*)d_in[12];
    float* out = (float*)d_out;

    float *r1, *routed;
    cudaGetSymbolAddress((void**)&r1,     g_r1);
    cudaGetSymbolAddress((void**)&routed, g_routed);

    __nv_bfloat16 *xhi, *xlo, *rthi, *rtlo, *athi, *atlo;
    __nv_bfloat16 *qhi, *qlo, *khi, *klo, *vhi, *vlo;
    __nv_bfloat16 *wqh, *wql, *wkh, *wkl, *wvh, *wvl, *woh, *wol, *wr1h, *wr1l;
    cudaGetSymbolAddress((void**)&xhi,  g_xhi);  cudaGetSymbolAddress((void**)&xlo,  g_xlo);
    cudaGetSymbolAddress((void**)&rthi, g_rthi); cudaGetSymbolAddress((void**)&rtlo, g_rtlo);
    cudaGetSymbolAddress((void**)&athi, g_athi); cudaGetSymbolAddress((void**)&atlo, g_atlo);
    cudaGetSymbolAddress((void**)&qhi,  g_qhi);  cudaGetSymbolAddress((void**)&qlo,  g_qlo);
    cudaGetSymbolAddress((void**)&khi,  g_khi);  cudaGetSymbolAddress((void**)&klo,  g_klo);
    cudaGetSymbolAddress((void**)&vhi,  g_vhi);  cudaGetSymbolAddress((void**)&vlo,  g_vlo);
    cudaGetSymbolAddress((void**)&wqh, g_wq_hi); cudaGetSymbolAddress((void**)&wql, g_wq_lo);
    cudaGetSymbolAddress((void**)&wkh, g_wk_hi); cudaGetSymbolAddress((void**)&wkl, g_wk_lo);
    cudaGetSymbolAddress((void**)&wvh, g_wv_hi); cudaGetSymbolAddress((void**)&wvl, g_wv_lo);
    cudaGetSymbolAddress((void**)&woh, g_wo_hi); cudaGetSymbolAddress((void**)&wol, g_wo_lo);
    cudaGetSymbolAddress((void**)&wr1h, g_wr1_hi); cudaGetSymbolAddress((void**)&wr1l, g_wr1_lo);

    dim3 gemm_grid(Cc / 128, Mm / 128);   // (8, 32)
    int act4 = (Mm * Cc) / 4;
    int w4   = (Cc * Cc) / 4;

    // mean pool
    mean_part_kernel<<<dim3(Cc / 256, 16, Bb), 256>>>(x);
    mean_reduce_kernel<<<(Bb * Cc) / 256, 256>>>();

    // conversions (input + weights)
    cvt_hilo_kernel<<<act4 / 256, 256>>>(x, xhi, xlo, act4);
    cvt_hilo_kernel<<<w4 / 256, 256>>>(Wr1, wr1h, wr1l, w4);
    cvt_hilo_kernel<<<w4 / 256, 256>>>(Wq, wqh, wql, w4);
    cvt_hilo_kernel<<<w4 / 256, 256>>>(Wk, wkh, wkl, w4);
    cvt_hilo_kernel<<<w4 / 256, 256>>>(Wv, wvh, wvl, w4);
    cvt_hilo_kernel<<<w4 / 256, 256>>>(Wo, woh, wol, w4);

    // r1 = tanh(x @ Wr1^T + br1)   (fp32 out)
    gemm_mma<1><<<gemm_grid, 256>>>(xhi, xlo, wr1h, wr1l, br1, r1,
                                    nullptr, nullptr, 1.0f);

    // routing + routed memory
    routing_kernel<<<Mm, 128>>>(r1, Wr2, br2, x, routed);
    cvt_hilo_kernel<<<act4 / 256, 256>>>(routed, rthi, rtlo, act4);

    // Q (pre-scaled), K, V projections -> bf16 hi/lo directly
    gemm_mma<2><<<gemm_grid, 256>>>(xhi,  xlo,  wqh, wql, bq, nullptr,
                                    qhi, qlo, ATT_SCALE);
    gemm_mma<2><<<gemm_grid, 256>>>(rthi, rtlo, wkh, wkl, bk, nullptr,
                                    khi, klo, 1.0f);
    gemm_mma<2><<<gemm_grid, 256>>>(rthi, rtlo, wvh, wvl, bv, nullptr,
                                    vhi, vlo, 1.0f);

    // tensor-core flash attention -> att hi/lo
    cudaFuncSetAttribute(flash_mma, cudaFuncAttributeMaxDynamicSharedMemorySize,
                         F_SMEM_BYTES);
    flash_mma<<<dim3(Tt / 128, Hh, Bb), 256, F_SMEM_BYTES>>>(
        qhi, qlo, khi, klo, vhi, vlo, athi, atlo);

    // output projection (fp32 out)
    gemm_mma<0><<<gemm_grid, 256>>>(athi, atlo, woh, wol, bo, out,
                                    nullptr, nullptr, 1.0f);
}

// round 5
// speedup vs baseline: 2.5378x; 1.3107x over previous
#include <cuda_runtime.h>
#include <cuda_bf16.h>
#include <math.h>
#include <stdint.h>

// Problem constants
#define Bb 2
#define Tt 2048
#define Cc 1024
#define Hh 16
#define Dd 64
#define Mm (Bb*Tt)           // 4096 tokens
#define ATT_SCALE 0.125f     // D^-0.5

// ---------------- scratch (device globals; no allocations allowed) ----------
__device__ float g_r1[Mm*Cc];
__device__ float g_part[16*Bb*Cc];
__device__ float g_mean[Bb*Cc];

// bf16 hi/lo split buffers
__device__ __nv_bfloat16 g_xhi[Mm*Cc],  g_xlo[Mm*Cc];
__device__ __nv_bfloat16 g_rthi[Mm*Cc], g_rtlo[Mm*Cc];
__device__ __nv_bfloat16 g_athi[Mm*Cc], g_atlo[Mm*Cc];
__device__ __nv_bfloat16 g_qhi[Mm*Cc],  g_qlo[Mm*Cc];
__device__ __nv_bfloat16 g_khi[Mm*Cc],  g_klo[Mm*Cc];
__device__ __nv_bfloat16 g_vhi[Mm*Cc],  g_vlo[Mm*Cc];
__device__ __nv_bfloat16 g_wq_hi[Cc*Cc], g_wq_lo[Cc*Cc];
__device__ __nv_bfloat16 g_wk_hi[Cc*Cc], g_wk_lo[Cc*Cc];
__device__ __nv_bfloat16 g_wv_hi[Cc*Cc], g_wv_lo[Cc*Cc];
__device__ __nv_bfloat16 g_wo_hi[Cc*Cc], g_wo_lo[Cc*Cc];
__device__ __nv_bfloat16 g_wr1_hi[Cc*Cc], g_wr1_lo[Cc*Cc];

// ================= PTX helpers (sm_100 baseline ISA only) ====================
__device__ __forceinline__ uint32_t smem_u32(const void* p) {
    uint32_t a;
    asm("{ .reg .u64 t; cvta.to.shared.u64 t, %1; cvt.u32.u64 %0, t; }"
        : "=r"(a) : "l"(p));
    return a;
}
__device__ __forceinline__ void cpasync16(uint32_t dst, const void* src) {
    asm volatile("cp.async.cg.shared.global [%0], [%1], 16;" :: "r"(dst), "l"(src));
}
__device__ __forceinline__ void ldsm4(uint32_t& r0, uint32_t& r1, uint32_t& r2,
                                      uint32_t& r3, uint32_t addr) {
    asm volatile("ldmatrix.sync.aligned.m8n8.x4.shared.b16 {%0,%1,%2,%3}, [%4];"
        : "=r"(r0), "=r"(r1), "=r"(r2), "=r"(r3) : "r"(addr));
}
__device__ __forceinline__ void ldsm4t(uint32_t& r0, uint32_t& r1, uint32_t& r2,
                                       uint32_t& r3, uint32_t addr) {
    asm volatile("ldmatrix.sync.aligned.m8n8.x4.trans.shared.b16 {%0,%1,%2,%3}, [%4];"
        : "=r"(r0), "=r"(r1), "=r"(r2), "=r"(r3) : "r"(addr));
}
__device__ __forceinline__ void mma16816(float* d, const uint32_t* a, const uint32_t* b) {
    asm volatile(
        "mma.sync.aligned.m16n8k16.row.col.f32.bf16.bf16.f32 "
        "{%0,%1,%2,%3}, {%4,%5,%6,%7}, {%8,%9}, {%0,%1,%2,%3};"
        : "+f"(d[0]), "+f"(d[1]), "+f"(d[2]), "+f"(d[3])
        : "r"(a[0]), "r"(a[1]), "r"(a[2]), "r"(a[3]), "r"(b[0]), "r"(b[1]));
}
__device__ __forceinline__ uint32_t pack_bf2(float a, float b) {
    unsigned short lo = __bfloat16_as_ushort(__float2bfloat16_rn(a));
    unsigned short hi = __bfloat16_as_ushort(__float2bfloat16_rn(b));
    return ((uint32_t)hi << 16) | lo;
}
__device__ __forceinline__ float bf_lo_res(float v, uint32_t pk) {
    return v - __bfloat162float(__ushort_as_bfloat16((unsigned short)(pk & 0xffff)));
}
__device__ __forceinline__ float bf_hi_res(float v, uint32_t pk) {
    return v - __bfloat162float(__ushort_as_bfloat16((unsigned short)(pk >> 16)));
}

// ---------------- mean pool (deterministic two-stage) -----------------------
__global__ __launch_bounds__(256) void mean_part_kernel(const float* __restrict__ x) {
    int c  = blockIdx.x * 256 + threadIdx.x;
    int b  = blockIdx.z;
    int t0 = blockIdx.y * (Tt / 16);
    float s = 0.f;
    #pragma unroll 8
    for (int tt = 0; tt < Tt / 16; tt++)
        s += x[((size_t)b * Tt + t0 + tt) * Cc + c];
    g_part[((size_t)blockIdx.y * Bb + b) * Cc + c] = s;
}

__global__ __launch_bounds__(256) void mean_reduce_kernel() {
    int idx = blockIdx.x * 256 + threadIdx.x;
    if (idx < Bb * Cc) {
        float s = 0.f;
        #pragma unroll
        for (int u = 0; u < 16; u++) s += g_part[(size_t)u * Bb * Cc + idx];
        g_mean[idx] = s * (1.0f / (float)Tt);
    }
}

// ---------------- fp32 -> bf16 hi/lo split -----------------------------------
__device__ __forceinline__ void cvt_body(const float* __restrict__ x,
                                         __nv_bfloat16* __restrict__ hi,
                                         __nv_bfloat16* __restrict__ lo, int i) {
    float4 v = ((const float4*)x)[i];
    uint32_t h0 = pack_bf2(v.x, v.y);
    uint32_t h1 = pack_bf2(v.z, v.w);
    uint32_t l0 = pack_bf2(bf_lo_res(v.x, h0), bf_hi_res(v.y, h0));
    uint32_t l1 = pack_bf2(bf_lo_res(v.z, h1), bf_hi_res(v.w, h1));
    uint2 hh; hh.x = h0; hh.y = h1;
    uint2 ll; ll.x = l0; ll.y = l1;
    ((uint2*)hi)[i] = hh;
    ((uint2*)lo)[i] = ll;
}

__global__ __launch_bounds__(256) void cvt_hilo_kernel(
    const float* __restrict__ x, __nv_bfloat16* __restrict__ hi,
    __nv_bfloat16* __restrict__ lo, int n4)
{
    int i = blockIdx.x * 256 + threadIdx.x;
    if (i < n4) cvt_body(x, hi, lo, i);
}

struct CvtBatch3 {
    const float* src[3];
    __nv_bfloat16* hi[3];
    __nv_bfloat16* lo[3];
};
__global__ __launch_bounds__(256) void cvt_batch_kernel(CvtBatch3 b, int n4) {
    int t = blockIdx.y;
    int i = blockIdx.x * 256 + threadIdx.x;
    if (i < n4) cvt_body(b.src[t], b.hi[t], b.lo[t], i);
}

// ================= HMMA GEMM =================================================
// Y[M,N] = A[M,K] @ W[N,K]^T + bias, bf16 split: Ahi*Bhi + Alo*Bhi + Ahi*Blo
// CTA tile 128x128, BK=64, 3-stage cp.async pipeline, 2 CTAs/SM, 1 sync/chunk.
// MODE 0: fp32 out; MODE 1: tanh fp32 out; MODE 2: bf16 hi/lo out (x scale)
#define G_NCH 48
#define G_LD 72
#define G_ABYTES (128 * G_LD * 2)           // 18432
#define G_STAGE_BYTES (2 * G_ABYTES)        // 36864
#define G_SMEM_BYTES (3 * G_STAGE_BYTES)    // 110592

template<int MODE>
__global__ __launch_bounds__(256, 2) void gemm_mma(
    const __nv_bfloat16* __restrict__ Ahi, const __nv_bfloat16* __restrict__ Alo,
    const __nv_bfloat16* __restrict__ Bhi, const __nv_bfloat16* __restrict__ Blo,
    const float* __restrict__ bias, float* __restrict__ out,
    __nv_bfloat16* __restrict__ outhi, __nv_bfloat16* __restrict__ outlo,
    float scale)
{
    extern __shared__ __align__(16) uint8_t gsm[];
    uint32_t base = smem_u32(gsm);

    int tid = threadIdx.x;
    int wid = tid >> 5;
    int l   = tid & 31;
    int wm  = wid >> 1;
    int wn  = wid & 1;
    int m0  = blockIdx.y * 128;
    int n0  = blockIdx.x * 128;

    int lrow = tid >> 3;        // 0..31 (+k*32)
    int lc16 = tid & 7;         // 16B chunk within 64-half row

    int arow = wm * 32 + (l & 15);
    int akc  = (l >> 4) * 8;
    int brow_in = (l & 7) + ((l >> 4) & 1) * 8;
    int bkc  = ((l >> 3) & 1) * 8;

    float acc[2][8][4];
    #pragma unroll
    for (int i = 0; i < 2; i++)
        #pragma unroll
        for (int j = 0; j < 8; j++)
            #pragma unroll
            for (int u = 0; u < 4; u++) acc[i][j][u] = 0.f;

    auto load_tile = [&](int c, int s) {
        int p  = c >> 4;                 // 0: hi*hi, 1: lo*hi, 2: hi*lo
        int k0 = (c & 15) * 64;
        const __nv_bfloat16* ap = (p == 1) ? Alo : Ahi;
        const __nv_bfloat16* bp = (p == 2) ? Blo : Bhi;
        uint32_t sb = base + s * G_STAGE_BYTES;
        #pragma unroll
        for (int it = 0; it < 4; it++) {
            int row = lrow + it * 32;
            uint32_t off = (row * G_LD + lc16 * 8) * 2;
            cpasync16(sb + off, ap + (size_t)(m0 + row) * Cc + k0 + lc16 * 8);
            cpasync16(sb + G_ABYTES + off, bp + (size_t)(n0 + row) * Cc + k0 + lc16 * 8);
        }
    };

    load_tile(0, 0);
    asm volatile("cp.async.commit_group;");
    load_tile(1, 1);
    asm volatile("cp.async.commit_group;");

    for (int c = 0; c < G_NCH; c++) {
        if (c < G_NCH - 1) asm volatile("cp.async.wait_group 1;");
        else               asm volatile("cp.async.wait_group 0;");
        __syncthreads();
        if (c + 2 < G_NCH) {
            load_tile(c + 2, (c + 2) % 3);
            asm volatile("cp.async.commit_group;");
        }

        uint32_t ab = base + (c % 3) * G_STAGE_BYTES;
        uint32_t bb = ab + G_ABYTES;
        #pragma unroll
        for (int ks = 0; ks < 4; ks++) {
            uint32_t afr[2][4];
            #pragma unroll
            for (int i = 0; i < 2; i++)
                ldsm4(afr[i][0], afr[i][1], afr[i][2], afr[i][3],
                      ab + ((arow + i * 16) * G_LD + akc + ks * 16) * 2);
            uint32_t bfr[4][4];
            #pragma unroll
            for (int nn = 0; nn < 4; nn++)
                ldsm4(bfr[nn][0], bfr[nn][1], bfr[nn][2], bfr[nn][3],
                      bb + ((wn * 64 + nn * 16 + brow_in) * G_LD + bkc + ks * 16) * 2);
            #pragma unroll
            for (int i = 0; i < 2; i++)
                #pragma unroll
                for (int j = 0; j < 8; j++)
                    mma16816(acc[i][j], afr[i], &bfr[j >> 1][(j & 1) * 2]);
        }
    }

    // epilogue
    #pragma unroll
    for (int i = 0; i < 2; i++) {
        int row = m0 + wm * 32 + i * 16 + (l >> 2);
        #pragma unroll
        for (int j = 0; j < 8; j++) {
            int col = n0 + wn * 64 + j * 8 + (l & 3) * 2;
            float b0v = __ldg(&bias[col]);
            float b1v = __ldg(&bias[col + 1]);
            float v0 = acc[i][j][0] + b0v;
            float v1 = acc[i][j][1] + b1v;
            float v2 = acc[i][j][2] + b0v;
            float v3 = acc[i][j][3] + b1v;
            if (MODE == 1) {
                v0 = tanhf(v0); v1 = tanhf(v1);
                v2 = tanhf(v2); v3 = tanhf(v3);
            }
            if (MODE == 2) {
                v0 *= scale; v1 *= scale; v2 *= scale; v3 *= scale;
                uint32_t h0 = pack_bf2(v0, v1);
                uint32_t h1 = pack_bf2(v2, v3);
                *(uint32_t*)(outhi + (size_t)row * Cc + col) = h0;
                *(uint32_t*)(outhi + (size_t)(row + 8) * Cc + col) = h1;
                *(uint32_t*)(outlo + (size_t)row * Cc + col) =
                    pack_bf2(bf_lo_res(v0, h0), bf_hi_res(v1, h0));
                *(uint32_t*)(outlo + (size_t)(row + 8) * Cc + col) =
                    pack_bf2(bf_lo_res(v2, h1), bf_hi_res(v3, h1));
            } else {
                float2 p0; p0.x = v0; p0.y = v1;
                float2 p1; p1.x = v2; p1.y = v3;
                *(float2*)(out + (size_t)row * Cc + col) = p0;
                *(float2*)(out + (size_t)(row + 8) * Cc + col) = p1;
            }
        }
    }
}

// ---------------- routing: logits -> softmax -> routed (bf16 hi/lo) ---------
__global__ __launch_bounds__(128) void routing_kernel(
    const float* __restrict__ r1, const float* __restrict__ Wr2,
    const float* __restrict__ br2, const float* __restrict__ x,
    __nv_bfloat16* __restrict__ rthi, __nv_bfloat16* __restrict__ rtlo)
{
    int t = blockIdx.x;
    int b = t >> 11;
    int tid = threadIdx.x;

    const float* rrow = r1 + (size_t)t * Cc;
    float s0 = 0.f, s1 = 0.f, s2 = 0.f;
    for (int c = tid; c < Cc; c += 128) {
        float vv = rrow[c];
        s0 = fmaf(vv, Wr2[c],          s0);
        s1 = fmaf(vv, Wr2[Cc + c],     s1);
        s2 = fmaf(vv, Wr2[2 * Cc + c], s2);
    }
    #pragma unroll
    for (int o = 16; o; o >>= 1) {
        s0 += __shfl_xor_sync(0xffffffffu, s0, o);
        s1 += __shfl_xor_sync(0xffffffffu, s1, o);
        s2 += __shfl_xor_sync(0xffffffffu, s2, o);
    }
    __shared__ float red[3][4];
    __shared__ float wsh[2];
    if ((tid & 31) == 0) {
        red[0][tid >> 5] = s0; red[1][tid >> 5] = s1; red[2][tid >> 5] = s2;
    }
    __syncthreads();
    if (tid == 0) {
        float l0 = red[0][0] + red[0][1] + red[0][2] + red[0][3] + br2[0];
        float l1 = red[1][0] + red[1][1] + red[1][2] + red[1][3] + br2[1];
        float l2 = red[2][0] + red[2][1] + red[2][2] + red[2][3] + br2[2];
        float mx = fmaxf(l0, fmaxf(l1, l2));
        float e0 = expf(l0 - mx), e1 = expf(l1 - mx), e2 = expf(l2 - mx);
        float inv = 1.0f / (e0 + e1 + e2);
        wsh[0] = e0 * inv; wsh[1] = e1 * inv;
    }
    __syncthreads();
    float w0 = wsh[0], w1 = wsh[1];

    const float4* x4 = (const float4*)(x + (size_t)t * Cc);
    const float4* m4 = (const float4*)(g_mean + (size_t)b * Cc);
    uint2* ho = (uint2*)(rthi + (size_t)t * Cc);
    uint2* lo = (uint2*)(rtlo + (size_t)t * Cc);
    for (int c4 = tid; c4 < Cc / 4; c4 += 128) {
        float4 xv = x4[c4], mv = m4[c4];
        float r0 = xv.x * w0 + mv.x * w1;
        float r1v = xv.y * w0 + mv.y * w1;
        float r2 = xv.z * w0 + mv.z * w1;
        float r3 = xv.w * w0 + mv.w * w1;
        uint32_t h0 = pack_bf2(r0, r1v);
        uint32_t h1 = pack_bf2(r2, r3);
        uint2 hh; hh.x = h0; hh.y = h1;
        uint2 ll;
        ll.x = pack_bf2(bf_lo_res(r0, h0), bf_hi_res(r1v, h0));
        ll.y = pack_bf2(bf_lo_res(r2, h1), bf_hi_res(r3, h1));
        ho[c4] = hh;
        lo[c4] = ll;
    }
}

// ================= tensor-core flash attention ===============================
// CTA: 128 Q rows (8 warps x 16), KV chunks of 64, D=64, 3-stage pipeline.
#define F_LD 72
#define FQ_HALVES (128 * F_LD)
#define FS_HALVES (64 * F_LD)
#define F_STAGE0 (2 * FQ_HALVES)
#define F_SMEM_BYTES ((2 * FQ_HALVES + 3 * 4 * FS_HALVES) * 2)   // 147456

__global__ __launch_bounds__(256, 1) void flash_mma(
    const __nv_bfloat16* __restrict__ qhi, const __nv_bfloat16* __restrict__ qlo,
    const __nv_bfloat16* __restrict__ khi, const __nv_bfloat16* __restrict__ klo,
    const __nv_bfloat16* __restrict__ vhi, const __nv_bfloat16* __restrict__ vlo,
    __nv_bfloat16* __restrict__ ohi, __nv_bfloat16* __restrict__ olo)
{
    extern __shared__ __nv_bfloat16 fs[];
    uint32_t fsb = smem_u32(fs);

    int tid = threadIdx.x;
    int w   = tid >> 5;
    int l   = tid & 31;
    int q0  = blockIdx.x * 128;
    int h   = blockIdx.y;
    int b   = blockIdx.z;
    int tokb = b * Tt;
    int hoff = h * Dd;

    // ---- load Q (hi+lo), goes into chunk-0 commit group ----
    {
        const __nv_bfloat16* srcs[2] = {qhi, qlo};
        #pragma unroll
        for (int ten = 0; ten < 2; ten++) {
            #pragma unroll
            for (int it = 0; it < 4; it++) {
                int idx = tid + it * 256;
                int row = idx >> 3, c16 = idx & 7;
                uint32_t dst = fsb + ((ten * FQ_HALVES) + row * F_LD + c16 * 8) * 2;
                cpasync16(dst, srcs[ten] + (size_t)(tokb + q0 + row) * Cc + hoff + c16 * 8);
            }
        }
    }
    auto load_kv = [&](int c, int s) {
        int kt0 = c * 64;
        const __nv_bfloat16* srcs[4] = {khi, klo, vhi, vlo};
        #pragma unroll
        for (int ten = 0; ten < 4; ten++) {
            #pragma unroll
            for (int it = 0; it < 2; it++) {
                int idx = tid + it * 256;
                int row = idx >> 3, c16 = idx & 7;
                uint32_t dst = fsb + ((F_STAGE0 + s * 4 * FS_HALVES + ten * FS_HALVES)
                                      + row * F_LD + c16 * 8) * 2;
                cpasync16(dst, srcs[ten] + (size_t)(tokb + kt0 + row) * Cc + hoff + c16 * 8);
            }
        }
    };

    load_kv(0, 0);
    asm volatile("cp.async.commit_group;");
    load_kv(1, 1);
    asm volatile("cp.async.commit_group;");

    int arow = (l & 15);
    int akc  = (l >> 4) * 8;
    int brow_in = (l & 7) + ((l >> 4) & 1) * 8;
    int bkc  = ((l >> 3) & 1) * 8;
    int vrow = (l & 7) + ((l >> 3) & 1) * 8;
    int vcol = ((l >> 4) & 1) * 8;

    uint32_t qh[4][4], ql[4][4];
    float oacc[8][4];
    #pragma unroll
    for (int j = 0; j < 8; j++)
        #pragma unroll
        for (int u = 0; u < 4; u++) oacc[j][u] = 0.f;
    float m0r = -1e30f, m1r = -1e30f, l0r = 0.f, l1r = 0.f;

    const int NCH = Tt / 64;
    for (int c = 0; c < NCH; c++) {
        if (c < NCH - 1) asm volatile("cp.async.wait_group 1;");
        else             asm volatile("cp.async.wait_group 0;");
        __syncthreads();

        if (c == 0) {
            #pragma unroll
            for (int kt = 0; kt < 4; kt++) {
                ldsm4(qh[kt][0], qh[kt][1], qh[kt][2], qh[kt][3],
                      fsb + ((w * 16 + arow) * F_LD + kt * 16 + akc) * 2);
                ldsm4(ql[kt][0], ql[kt][1], ql[kt][2], ql[kt][3],
                      fsb + (FQ_HALVES + (w * 16 + arow) * F_LD + kt * 16 + akc) * 2);
            }
        }

        if (c + 2 < NCH) {
            load_kv(c + 2, (c + 2) % 3);
            asm volatile("cp.async.commit_group;");
        }

        uint32_t SB = F_STAGE0 + (c % 3) * 4 * FS_HALVES;
        uint32_t KHI = SB, KLO = SB + FS_HALVES;
        uint32_t VHI = SB + 2 * FS_HALVES, VLO = SB + 3 * FS_HALVES;

        // ---- S = Q K^T (3-term split) ----
        float sacc[8][4];
        #pragma unroll
        for (int j = 0; j < 8; j++)
            #pragma unroll
            for (int u = 0; u < 4; u++) sacc[j][u] = 0.f;

        #pragma unroll
        for (int ks = 0; ks < 4; ks++) {
            uint32_t kh[4][4], klr[4][4];
            #pragma unroll
            for (int g = 0; g < 4; g++) {
                uint32_t ro = ((g * 16 + brow_in) * F_LD + bkc + ks * 16) * 2;
                ldsm4(kh[g][0], kh[g][1], kh[g][2], kh[g][3], fsb + KHI * 2 + ro);
                ldsm4(klr[g][0], klr[g][1], klr[g][2], klr[g][3], fsb + KLO * 2 + ro);
            }
            #pragma unroll
            for (int g = 0; g < 4; g++)
                #pragma unroll
                for (int sub = 0; sub < 2; sub++) {
                    int j = g * 2 + sub;
                    mma16816(sacc[j], qh[ks], &kh[g][sub * 2]);
                    mma16816(sacc[j], ql[ks], &kh[g][sub * 2]);
                    mma16816(sacc[j], qh[ks], &klr[g][sub * 2]);
                }
        }

        // ---- online softmax + register-resident P split ----
        float mx0 = -1e30f, mx1 = -1e30f;
        #pragma unroll
        for (int j = 0; j < 8; j++) {
            mx0 = fmaxf(mx0, fmaxf(sacc[j][0], sacc[j][1]));
            mx1 = fmaxf(mx1, fmaxf(sacc[j][2], sacc[j][3]));
        }
        mx0 = fmaxf(mx0, __shfl_xor_sync(0xffffffffu, mx0, 1));
        mx0 = fmaxf(mx0, __shfl_xor_sync(0xffffffffu, mx0, 2));
        mx1 = fmaxf(mx1, __shfl_xor_sync(0xffffffffu, mx1, 1));
        mx1 = fmaxf(mx1, __shfl_xor_sync(0xffffffffu, mx1, 2));
        float mn0 = fmaxf(m0r, mx0), mn1 = fmaxf(m1r, mx1);
        float cor0 = __expf(m0r - mn0), cor1 = __expf(m1r - mn1);
        m0r = mn0; m1r = mn1;

        uint32_t phi[4][4], plo[4][4];
        float rs0 = 0.f, rs1 = 0.f;
        #pragma unroll
        for (int j = 0; j < 8; j++) {
            float e0 = __expf(sacc[j][0] - mn0);
            float e1 = __expf(sacc[j][1] - mn0);
            float e2 = __expf(sacc[j][2] - mn1);
            float e3 = __expf(sacc[j][3] - mn1);
            rs0 += e0 + e1; rs1 += e2 + e3;
            int kt = j >> 1, sl = (j & 1) * 2;
            uint32_t h01 = pack_bf2(e0, e1);
            uint32_t h23 = pack_bf2(e2, e3);
            phi[kt][sl]     = h01;
            phi[kt][sl + 1] = h23;
            plo[kt][sl]     = pack_bf2(bf_lo_res(e0, h01), bf_hi_res(e1, h01));
            plo[kt][sl + 1] = pack_bf2(bf_lo_res(e2, h23), bf_hi_res(e3, h23));
        }
        rs0 += __shfl_xor_sync(0xffffffffu, rs0, 1);
        rs0 += __shfl_xor_sync(0xffffffffu, rs0, 2);
        rs1 += __shfl_xor_sync(0xffffffffu, rs1, 1);
        rs1 += __shfl_xor_sync(0xffffffffu, rs1, 2);
        l0r = l0r * cor0 + rs0;
        l1r = l1r * cor1 + rs1;
        #pragma unroll
        for (int j = 0; j < 8; j++) {
            oacc[j][0] *= cor0; oacc[j][1] *= cor0;
            oacc[j][2] *= cor1; oacc[j][3] *= cor1;
        }

        // ---- O += P V (3-term) ----
        #pragma unroll
        for (int kt = 0; kt < 4; kt++) {
            #pragma unroll
            for (int dg = 0; dg < 4; dg++) {
                uint32_t vh[4], vl[4];
                uint32_t ro = ((kt * 16 + vrow) * F_LD + dg * 16 + vcol) * 2;
                ldsm4t(vh[0], vh[1], vh[2], vh[3], fsb + VHI * 2 + ro);
                ldsm4t(vl[0], vl[1], vl[2], vl[3], fsb + VLO * 2 + ro);
                #pragma unroll
                for (int sub = 0; sub < 2; sub++) {
                    int dt = dg * 2 + sub;
                    mma16816(oacc[dt], phi[kt], &vh[sub * 2]);
                    mma16816(oacc[dt], plo[kt], &vh[sub * 2]);
                    mma16816(oacc[dt], phi[kt], &vl[sub * 2]);
                }
            }
        }
    }

    // ---- epilogue: normalize, hi/lo split, write ----
    float inv0 = 1.0f / l0r, inv1 = 1.0f / l1r;
    int row0 = tokb + q0 + w * 16 + (l >> 2);
    int row1 = row0 + 8;
    #pragma unroll
    for (int dt = 0; dt < 8; dt++) {
        int col = hoff + dt * 8 + (l & 3) * 2;
        float v0 = oacc[dt][0] * inv0, v1 = oacc[dt][1] * inv0;
        float v2 = oacc[dt][2] * inv1, v3 = oacc[dt][3] * inv1;
        uint32_t h0 = pack_bf2(v0, v1);
        uint32_t h1 = pack_bf2(v2, v3);
        *(uint32_t*)(ohi + (size_t)row0 * Cc + col) = h0;
        *(uint32_t*)(ohi + (size_t)row1 * Cc + col) = h1;
        *(uint32_t*)(olo + (size_t)row0 * Cc + col) =
            pack_bf2(bf_lo_res(v0, h0), bf_hi_res(v1, h0));
        *(uint32_t*)(olo + (size_t)row1 * Cc + col) =
            pack_bf2(bf_lo_res(v2, h1), bf_hi_res(v3, h1));
    }
}

// ---------------- host driver -----------------------------------------------
extern "C" void kernel_launch(void* const* d_in, const int* in_sizes, int n_in,
                              void* d_out, int out_size)
{
    const float* x   = (const float*)d_in[0];
    const float* Wq  = (const float*)d_in[1];
    const float* bq  = (const float*)d_in[2];
    const float* Wk  = (const float*)d_in[3];
    const float* bk  = (const float*)d_in[4];
    const float* Wv  = (const float*)d_in[5];
    const float* bv  = (const float*)d_in[6];
    const float* Wo  = (const float*)d_in[7];
    const float* bo  = (const float*)d_in[8];
    const float* Wr1 = (const float*)d_in[9];
    const float* br1 = (const float*)d_in[10];
    const float* Wr2 = (const float*)d_in[11];
    const float* br2 = (const float*)d_in[12];
    float* out = (float*)d_out;

    float* r1;
    cudaGetSymbolAddress((void**)&r1, g_r1);

    __nv_bfloat16 *xhi, *xlo, *rthi, *rtlo, *athi, *atlo;
    __nv_bfloat16 *qhi, *qlo, *khi, *klo, *vhi, *vlo;
    __nv_bfloat16 *wqh, *wql, *wkh, *wkl, *wvh, *wvl, *woh, *wol, *wr1h, *wr1l;
    cudaGetSymbolAddress((void**)&xhi,  g_xhi);  cudaGetSymbolAddress((void**)&xlo,  g_xlo);
    cudaGetSymbolAddress((void**)&rthi, g_rthi); cudaGetSymbolAddress((void**)&rtlo, g_rtlo);
    cudaGetSymbolAddress((void**)&athi, g_athi); cudaGetSymbolAddress((void**)&atlo, g_atlo);
    cudaGetSymbolAddress((void**)&qhi,  g_qhi);  cudaGetSymbolAddress((void**)&qlo,  g_qlo);
    cudaGetSymbolAddress((void**)&khi,  g_khi);  cudaGetSymbolAddress((void**)&klo,  g_klo);
    cudaGetSymbolAddress((void**)&vhi,  g_vhi);  cudaGetSymbolAddress((void**)&vlo,  g_vlo);
    cudaGetSymbolAddress((void**)&wqh, g_wq_hi); cudaGetSymbolAddress((void**)&wql, g_wq_lo);
    cudaGetSymbolAddress((void**)&wkh, g_wk_hi); cudaGetSymbolAddress((void**)&wkl, g_wk_lo);
    cudaGetSymbolAddress((void**)&wvh, g_wv_hi); cudaGetSymbolAddress((void**)&wvl, g_wv_lo);
    cudaGetSymbolAddress((void**)&woh, g_wo_hi); cudaGetSymbolAddress((void**)&wol, g_wo_lo);
    cudaGetSymbolAddress((void**)&wr1h, g_wr1_hi); cudaGetSymbolAddress((void**)&wr1l, g_wr1_lo);

    cudaFuncSetAttribute(gemm_mma<0>, cudaFuncAttributeMaxDynamicSharedMemorySize, G_SMEM_BYTES);
    cudaFuncSetAttribute(gemm_mma<1>, cudaFuncAttributeMaxDynamicSharedMemorySize, G_SMEM_BYTES);
    cudaFuncSetAttribute(gemm_mma<2>, cudaFuncAttributeMaxDynamicSharedMemorySize, G_SMEM_BYTES);
    cudaFuncSetAttribute(flash_mma, cudaFuncAttributeMaxDynamicSharedMemorySize, F_SMEM_BYTES);

    dim3 gemm_grid(Cc / 128, Mm / 128);   // (8, 32)
    int act4 = (Mm * Cc) / 4;
    int w4   = (Cc * Cc) / 4;

    // launch #1: weights batch 1 (Wr1, Wq, Wk)
    CvtBatch3 bat1;
    bat1.src[0] = Wr1; bat1.hi[0] = wr1h; bat1.lo[0] = wr1l;
    bat1.src[1] = Wq;  bat1.hi[1] = wqh;  bat1.lo[1] = wql;
    bat1.src[2] = Wk;  bat1.hi[2] = wkh;  bat1.lo[2] = wkl;
    cvt_batch_kernel<<<dim3(w4 / 256, 3), 256>>>(bat1, w4);

    // launch #2: weights batch 2 (Wv, Wo)
    CvtBatch3 bat2;
    bat2.src[0] = Wv; bat2.hi[0] = wvh; bat2.lo[0] = wvl;
    bat2.src[1] = Wo; bat2.hi[1] = woh; bat2.lo[1] = wol;
    bat2.src[2] = Wo; bat2.hi[2] = woh; bat2.lo[2] = wol;   // unused lane
    cvt_batch_kernel<<<dim3(w4 / 256, 2), 256>>>(bat2, w4);

    // launch #3: x -> hi/lo
    cvt_hilo_kernel<<<act4 / 256, 256>>>(x, xhi, xlo, act4);

    // launches #4, #5: mean pool
    mean_part_kernel<<<dim3(Cc / 256, 16, Bb), 256>>>(x);
    mean_reduce_kernel<<<(Bb * Cc) / 256, 256>>>();

    // launch #6 (ncu -s 5 target): r1 = tanh(x @ Wr1^T + br1)
    gemm_mma<1><<<gemm_grid, 256, G_SMEM_BYTES>>>(xhi, xlo, wr1h, wr1l, br1, r1,
                                                  nullptr, nullptr, 1.0f);

    // routing -> routed bf16 hi/lo directly
    routing_kernel<<<Mm, 128>>>(r1, Wr2, br2, x, rthi, rtlo);

    // Q (pre-scaled), K, V projections -> bf16 hi/lo
    gemm_mma<2><<<gemm_grid, 256, G_SMEM_BYTES>>>(xhi,  xlo,  wqh, wql, bq, nullptr,
                                                  qhi, qlo, ATT_SCALE);
    gemm_mma<2><<<gemm_grid, 256, G_SMEM_BYTES>>>(rthi, rtlo, wkh, wkl, bk, nullptr,
                                                  khi, klo, 1.0f);
    gemm_mma<2><<<gemm_grid, 256, G_SMEM_BYTES>>>(rthi, rtlo, wvh, wvl, bv, nullptr,
                                                  vhi, vlo, 1.0f);

    // tensor-core flash attention -> att hi/lo
    flash_mma<<<dim3(Tt / 128, Hh, Bb), 256, F_SMEM_BYTES>>>(
        qhi, qlo, khi, klo, vhi, vlo, athi, atlo);

    // output projection (fp32 out)
    gemm_mma<0><<<gemm_grid, 256, G_SMEM_BYTES>>>(athi, atlo, woh, wol, bo, out,
                                                  nullptr, nullptr, 1.0f);
}

// round 6
// speedup vs baseline: 2.8696x; 1.1307x over previous
#include <cuda_runtime.h>
#include <cuda_bf16.h>
#include <cuda_fp16.h>
#include <math.h>
#include <stdint.h>

// Problem constants
#define Bb 2
#define Tt 2048
#define Cc 1024
#define Hh 16
#define Dd 64
#define Mm (Bb*Tt)           // 4096 tokens
#define ATT_SCALE 0.125f     // D^-0.5

// ---------------- scratch (device globals; no allocations allowed) ----------
__device__ float g_r1[Mm*Cc];
__device__ float g_part[64*Bb*Cc];
__device__ float g_mean[Bb*Cc];

// bf16 hi/lo split buffers
__device__ __nv_bfloat16 g_xhi[Mm*Cc],  g_xlo[Mm*Cc];
__device__ __nv_bfloat16 g_rthi[Mm*Cc], g_rtlo[Mm*Cc];
__device__ __nv_bfloat16 g_athi[Mm*Cc], g_atlo[Mm*Cc];
__device__ __nv_bfloat16 g_qhi[Mm*Cc],  g_qlo[Mm*Cc];
__device__ __nv_bfloat16 g_khi[Mm*Cc],  g_klo[Mm*Cc];
__device__ __half        g_vf16[Mm*Cc];
__device__ __nv_bfloat16 g_wq_hi[Cc*Cc], g_wq_lo[Cc*Cc];
__device__ __nv_bfloat16 g_wk_hi[Cc*Cc], g_wk_lo[Cc*Cc];
__device__ __nv_bfloat16 g_wv_hi[Cc*Cc], g_wv_lo[Cc*Cc];
__device__ __nv_bfloat16 g_wo_hi[Cc*Cc], g_wo_lo[Cc*Cc];
__device__ __nv_bfloat16 g_wr1_hi[Cc*Cc], g_wr1_lo[Cc*Cc];

// ================= PTX helpers (sm_100 baseline ISA only) ====================
__device__ __forceinline__ uint32_t smem_u32(const void* p) {
    uint32_t a;
    asm("{ .reg .u64 t; cvta.to.shared.u64 t, %1; cvt.u32.u64 %0, t; }"
        : "=r"(a) : "l"(p));
    return a;
}
__device__ __forceinline__ void cpasync16(uint32_t dst, const void* src) {
    asm volatile("cp.async.cg.shared.global [%0], [%1], 16;" :: "r"(dst), "l"(src));
}
__device__ __forceinline__ void ldsm4(uint32_t& r0, uint32_t& r1, uint32_t& r2,
                                      uint32_t& r3, uint32_t addr) {
    asm volatile("ldmatrix.sync.aligned.m8n8.x4.shared.b16 {%0,%1,%2,%3}, [%4];"
        : "=r"(r0), "=r"(r1), "=r"(r2), "=r"(r3) : "r"(addr));
}
__device__ __forceinline__ void ldsm4t(uint32_t& r0, uint32_t& r1, uint32_t& r2,
                                       uint32_t& r3, uint32_t addr) {
    asm volatile("ldmatrix.sync.aligned.m8n8.x4.trans.shared.b16 {%0,%1,%2,%3}, [%4];"
        : "=r"(r0), "=r"(r1), "=r"(r2), "=r"(r3) : "r"(addr));
}
__device__ __forceinline__ void mma16816(float* d, const uint32_t* a, const uint32_t* b) {
    asm volatile(
        "mma.sync.aligned.m16n8k16.row.col.f32.bf16.bf16.f32 "
        "{%0,%1,%2,%3}, {%4,%5,%6,%7}, {%8,%9}, {%0,%1,%2,%3};"
        : "+f"(d[0]), "+f"(d[1]), "+f"(d[2]), "+f"(d[3])
        : "r"(a[0]), "r"(a[1]), "r"(a[2]), "r"(a[3]), "r"(b[0]), "r"(b[1]));
}
__device__ __forceinline__ void mma16816h(float* d, const uint32_t* a, const uint32_t* b) {
    asm volatile(
        "mma.sync.aligned.m16n8k16.row.col.f32.f16.f16.f32 "
        "{%0,%1,%2,%3}, {%4,%5,%6,%7}, {%8,%9}, {%0,%1,%2,%3};"
        : "+f"(d[0]), "+f"(d[1]), "+f"(d[2]), "+f"(d[3])
        : "r"(a[0]), "r"(a[1]), "r"(a[2]), "r"(a[3]), "r"(b[0]), "r"(b[1]));
}
__device__ __forceinline__ uint32_t pack_bf2(float a, float b) {
    unsigned short lo = __bfloat16_as_ushort(__float2bfloat16_rn(a));
    unsigned short hi = __bfloat16_as_ushort(__float2bfloat16_rn(b));
    return ((uint32_t)hi << 16) | lo;
}
__device__ __forceinline__ uint32_t pack_h2(float a, float b) {
    __half2 h = __floats2half2_rn(a, b);
    return *(uint32_t*)&h;
}
__device__ __forceinline__ float bf_lo_res(float v, uint32_t pk) {
    return v - __bfloat162float(__ushort_as_bfloat16((unsigned short)(pk & 0xffff)));
}
__device__ __forceinline__ float bf_hi_res(float v, uint32_t pk) {
    return v - __bfloat162float(__ushort_as_bfloat16((unsigned short)(pk >> 16)));
}

// ---------------- mean pool (deterministic two-stage) -----------------------
__global__ __launch_bounds__(256) void mean_part_kernel(const float* __restrict__ x) {
    int c  = blockIdx.x * 256 + threadIdx.x;
    int b  = blockIdx.z;
    int t0 = blockIdx.y * (Tt / 64);
    float s = 0.f;
    #pragma unroll 8
    for (int tt = 0; tt < Tt / 64; tt++)
        s += x[((size_t)b * Tt + t0 + tt) * Cc + c];
    g_part[((size_t)blockIdx.y * Bb + b) * Cc + c] = s;
}

__global__ __launch_bounds__(256) void mean_reduce_kernel() {
    int idx = blockIdx.x * 256 + threadIdx.x;
    if (idx < Bb * Cc) {
        float s = 0.f;
        #pragma unroll
        for (int u = 0; u < 64; u++) s += g_part[(size_t)u * Bb * Cc + idx];
        g_mean[idx] = s * (1.0f / (float)Tt);
    }
}

// ---------------- fp32 -> bf16 hi/lo split -----------------------------------
__device__ __forceinline__ void cvt_body(const float* __restrict__ x,
                                         __nv_bfloat16* __restrict__ hi,
                                         __nv_bfloat16* __restrict__ lo, int i) {
    float4 v = ((const float4*)x)[i];
    uint32_t h0 = pack_bf2(v.x, v.y);
    uint32_t h1 = pack_bf2(v.z, v.w);
    uint32_t l0 = pack_bf2(bf_lo_res(v.x, h0), bf_hi_res(v.y, h0));
    uint32_t l1 = pack_bf2(bf_lo_res(v.z, h1), bf_hi_res(v.w, h1));
    uint2 hh; hh.x = h0; hh.y = h1;
    uint2 ll; ll.x = l0; ll.y = l1;
    ((uint2*)hi)[i] = hh;
    ((uint2*)lo)[i] = ll;
}

__global__ __launch_bounds__(256) void cvt_hilo_kernel(
    const float* __restrict__ x, __nv_bfloat16* __restrict__ hi,
    __nv_bfloat16* __restrict__ lo, int n4)
{
    int i = blockIdx.x * 256 + threadIdx.x;
    if (i < n4) cvt_body(x, hi, lo, i);
}

struct CvtBatch5 {
    const float* src[5];
    __nv_bfloat16* hi[5];
    __nv_bfloat16* lo[5];
};
__global__ __launch_bounds__(256) void cvt_batch_kernel(CvtBatch5 b, int n4) {
    int t = blockIdx.y;
    int i = blockIdx.x * 256 + threadIdx.x;
    if (i < n4) cvt_body(b.src[t], b.hi[t], b.lo[t], i);
}

// ================= HMMA GEMM =================================================
// Y[M,N] = A[M,K] @ W[N,K]^T + bias, bf16 split: Ahi*Bhi + Alo*Bhi + Ahi*Blo
// CTA 128x128, BK=64, 3-stage cp.async, 2 CTAs/SM, 1 sync/chunk.
// MODE 0: fp32; MODE 1: tanh fp32; MODE 2: bf16 hi/lo (x scale); MODE 3: fp16
#define G_NCH 48
#define G_LD 72
#define G_ABYTES (128 * G_LD * 2)
#define G_STAGE_BYTES (2 * G_ABYTES)
#define G_SMEM_BYTES (3 * G_STAGE_BYTES)    // 110592

template<int MODE>
__global__ __launch_bounds__(256, 2) void gemm_mma(
    const __nv_bfloat16* __restrict__ Ahi, const __nv_bfloat16* __restrict__ Alo,
    const __nv_bfloat16* __restrict__ Bhi, const __nv_bfloat16* __restrict__ Blo,
    const float* __restrict__ bias, float* __restrict__ out,
    __nv_bfloat16* __restrict__ outhi, __nv_bfloat16* __restrict__ outlo,
    float scale)
{
    extern __shared__ __align__(16) uint8_t gsm[];
    uint32_t base = smem_u32(gsm);

    int tid = threadIdx.x;
    int wid = tid >> 5;
    int l   = tid & 31;
    int wm  = wid >> 1;
    int wn  = wid & 1;
    int m0  = blockIdx.y * 128;
    int n0  = blockIdx.x * 128;

    int lrow = tid >> 3;
    int lc16 = tid & 7;

    int arow = wm * 32 + (l & 15);
    int akc  = (l >> 4) * 8;
    int brow_in = (l & 7) + ((l >> 4) & 1) * 8;
    int bkc  = ((l >> 3) & 1) * 8;

    float acc[2][8][4];
    #pragma unroll
    for (int i = 0; i < 2; i++)
        #pragma unroll
        for (int j = 0; j < 8; j++)
            #pragma unroll
            for (int u = 0; u < 4; u++) acc[i][j][u] = 0.f;

    auto load_tile = [&](int c, int s) {
        int p  = c >> 4;
        int k0 = (c & 15) * 64;
        const __nv_bfloat16* ap = (p == 1) ? Alo : Ahi;
        const __nv_bfloat16* bp = (p == 2) ? Blo : Bhi;
        uint32_t sb = base + s * G_STAGE_BYTES;
        #pragma unroll
        for (int it = 0; it < 4; it++) {
            int row = lrow + it * 32;
            uint32_t off = (row * G_LD + lc16 * 8) * 2;
            cpasync16(sb + off, ap + (size_t)(m0 + row) * Cc + k0 + lc16 * 8);
            cpasync16(sb + G_ABYTES + off, bp + (size_t)(n0 + row) * Cc + k0 + lc16 * 8);
        }
    };

    load_tile(0, 0);
    asm volatile("cp.async.commit_group;");
    load_tile(1, 1);
    asm volatile("cp.async.commit_group;");

    for (int c = 0; c < G_NCH; c++) {
        if (c < G_NCH - 1) asm volatile("cp.async.wait_group 1;");
        else               asm volatile("cp.async.wait_group 0;");
        __syncthreads();
        if (c + 2 < G_NCH) {
            load_tile(c + 2, (c + 2) % 3);
            asm volatile("cp.async.commit_group;");
        }

        uint32_t ab = base + (c % 3) * G_STAGE_BYTES;
        uint32_t bb = ab + G_ABYTES;
        #pragma unroll
        for (int ks = 0; ks < 4; ks++) {
            uint32_t afr[2][4];
            #pragma unroll
            for (int i = 0; i < 2; i++)
                ldsm4(afr[i][0], afr[i][1], afr[i][2], afr[i][3],
                      ab + ((arow + i * 16) * G_LD + akc + ks * 16) * 2);
            uint32_t bfr[4][4];
            #pragma unroll
            for (int nn = 0; nn < 4; nn++)
                ldsm4(bfr[nn][0], bfr[nn][1], bfr[nn][2], bfr[nn][3],
                      bb + ((wn * 64 + nn * 16 + brow_in) * G_LD + bkc + ks * 16) * 2);
            #pragma unroll
            for (int i = 0; i < 2; i++)
                #pragma unroll
                for (int j = 0; j < 8; j++)
                    mma16816(acc[i][j], afr[i], &bfr[j >> 1][(j & 1) * 2]);
        }
    }

    // epilogue
    #pragma unroll
    for (int i = 0; i < 2; i++) {
        int row = m0 + wm * 32 + i * 16 + (l >> 2);
        #pragma unroll
        for (int j = 0; j < 8; j++) {
            int col = n0 + wn * 64 + j * 8 + (l & 3) * 2;
            float b0v = __ldg(&bias[col]);
            float b1v = __ldg(&bias[col + 1]);
            float v0 = acc[i][j][0] + b0v;
            float v1 = acc[i][j][1] + b1v;
            float v2 = acc[i][j][2] + b0v;
            float v3 = acc[i][j][3] + b1v;
            if (MODE == 1) {
                v0 = tanhf(v0); v1 = tanhf(v1);
                v2 = tanhf(v2); v3 = tanhf(v3);
            }
            if (MODE == 2) {
                v0 *= scale; v1 *= scale; v2 *= scale; v3 *= scale;
                uint32_t h0 = pack_bf2(v0, v1);
                uint32_t h1 = pack_bf2(v2, v3);
                *(uint32_t*)(outhi + (size_t)row * Cc + col) = h0;
                *(uint32_t*)(outhi + (size_t)(row + 8) * Cc + col) = h1;
                *(uint32_t*)(outlo + (size_t)row * Cc + col) =
                    pack_bf2(bf_lo_res(v0, h0), bf_hi_res(v1, h0));
                *(uint32_t*)(outlo + (size_t)(row + 8) * Cc + col) =
                    pack_bf2(bf_lo_res(v2, h1), bf_hi_res(v3, h1));
            } else if (MODE == 3) {
                __half* oh = (__half*)outhi;
                *(uint32_t*)(oh + (size_t)row * Cc + col) = pack_h2(v0, v1);
                *(uint32_t*)(oh + (size_t)(row + 8) * Cc + col) = pack_h2(v2, v3);
            } else {
                float2 p0; p0.x = v0; p0.y = v1;
                float2 p1; p1.x = v2; p1.y = v3;
                *(float2*)(out + (size_t)row * Cc + col) = p0;
                *(float2*)(out + (size_t)(row + 8) * Cc + col) = p1;
            }
        }
    }
}

// ---------------- routing: logits -> softmax -> routed (bf16 hi/lo) ---------
__global__ __launch_bounds__(128) void routing_kernel(
    const float* __restrict__ r1, const float* __restrict__ Wr2,
    const float* __restrict__ br2, const float* __restrict__ x,
    __nv_bfloat16* __restrict__ rthi, __nv_bfloat16* __restrict__ rtlo)
{
    int t = blockIdx.x;
    int b = t >> 11;
    int tid = threadIdx.x;

    const float* rrow = r1 + (size_t)t * Cc;
    float s0 = 0.f, s1 = 0.f, s2 = 0.f;
    for (int c = tid; c < Cc; c += 128) {
        float vv = rrow[c];
        s0 = fmaf(vv, Wr2[c],          s0);
        s1 = fmaf(vv, Wr2[Cc + c],     s1);
        s2 = fmaf(vv, Wr2[2 * Cc + c], s2);
    }
    #pragma unroll
    for (int o = 16; o; o >>= 1) {
        s0 += __shfl_xor_sync(0xffffffffu, s0, o);
        s1 += __shfl_xor_sync(0xffffffffu, s1, o);
        s2 += __shfl_xor_sync(0xffffffffu, s2, o);
    }
    __shared__ float red[3][4];
    __shared__ float wsh[2];
    if ((tid & 31) == 0) {
        red[0][tid >> 5] = s0; red[1][tid >> 5] = s1; red[2][tid >> 5] = s2;
    }
    __syncthreads();
    if (tid == 0) {
        float l0 = red[0][0] + red[0][1] + red[0][2] + red[0][3] + br2[0];
        float l1 = red[1][0] + red[1][1] + red[1][2] + red[1][3] + br2[1];
        float l2 = red[2][0] + red[2][1] + red[2][2] + red[2][3] + br2[2];
        float mx = fmaxf(l0, fmaxf(l1, l2));
        float e0 = expf(l0 - mx), e1 = expf(l1 - mx), e2 = expf(l2 - mx);
        float inv = 1.0f / (e0 + e1 + e2);
        wsh[0] = e0 * inv; wsh[1] = e1 * inv;
    }
    __syncthreads();
    float w0 = wsh[0], w1 = wsh[1];

    const float4* x4 = (const float4*)(x + (size_t)t * Cc);
    const float4* m4 = (const float4*)(g_mean + (size_t)b * Cc);
    uint2* ho = (uint2*)(rthi + (size_t)t * Cc);
    uint2* lo = (uint2*)(rtlo + (size_t)t * Cc);
    for (int c4 = tid; c4 < Cc / 4; c4 += 128) {
        float4 xv = x4[c4], mv = m4[c4];
        float r0 = xv.x * w0 + mv.x * w1;
        float r1v = xv.y * w0 + mv.y * w1;
        float r2 = xv.z * w0 + mv.z * w1;
        float r3 = xv.w * w0 + mv.w * w1;
        uint32_t h0 = pack_bf2(r0, r1v);
        uint32_t h1 = pack_bf2(r2, r3);
        uint2 hh; hh.x = h0; hh.y = h1;
        uint2 ll;
        ll.x = pack_bf2(bf_lo_res(r0, h0), bf_hi_res(r1v, h0));
        ll.y = pack_bf2(bf_lo_res(r2, h1), bf_hi_res(r3, h1));
        ho[c4] = hh;
        lo[c4] = ll;
    }
}

// ================= tensor-core flash attention ===============================
// CTA: 128 Q rows (8 warps x 16), KV chunks of 64, D=64, 3-stage pipeline.
// S: bf16 3-term. PV: P fp16 single x V fp16 single (1 MMA term).
#define F_LD 72
#define FQ_HALVES (128 * F_LD)
#define FS_HALVES (64 * F_LD)
#define F_TSTAGE (3 * FS_HALVES)            // Khi, Klo, Vf16
#define F_STAGE0 (2 * FQ_HALVES)
#define F_SMEM_BYTES ((2 * FQ_HALVES + 3 * F_TSTAGE) * 2)   // 119808

__global__ __launch_bounds__(256, 1) void flash_mma(
    const __nv_bfloat16* __restrict__ qhi, const __nv_bfloat16* __restrict__ qlo,
    const __nv_bfloat16* __restrict__ khi, const __nv_bfloat16* __restrict__ klo,
    const __half* __restrict__ vf16,
    __nv_bfloat16* __restrict__ ohi, __nv_bfloat16* __restrict__ olo)
{
    extern __shared__ __nv_bfloat16 fs[];
    uint32_t fsb = smem_u32(fs);

    int tid = threadIdx.x;
    int w   = tid >> 5;
    int l   = tid & 31;
    int q0  = blockIdx.x * 128;
    int h   = blockIdx.y;
    int b   = blockIdx.z;
    int tokb = b * Tt;
    int hoff = h * Dd;

    // ---- load Q (hi+lo), rides with chunk-0's commit group ----
    {
        const __nv_bfloat16* srcs[2] = {qhi, qlo};
        #pragma unroll
        for (int ten = 0; ten < 2; ten++) {
            #pragma unroll
            for (int it = 0; it < 4; it++) {
                int idx = tid + it * 256;
                int row = idx >> 3, c16 = idx & 7;
                uint32_t dst = fsb + ((ten * FQ_HALVES) + row * F_LD + c16 * 8) * 2;
                cpasync16(dst, srcs[ten] + (size_t)(tokb + q0 + row) * Cc + hoff + c16 * 8);
            }
        }
    }
    auto load_kv = [&](int c, int s) {
        int kt0 = c * 64;
        uint32_t sb = fsb + (F_STAGE0 + s * F_TSTAGE) * 2;
        #pragma unroll
        for (int it = 0; it < 2; it++) {
            int idx = tid + it * 256;
            int row = idx >> 3, c16 = idx & 7;
            uint32_t off = (row * F_LD + c16 * 8) * 2;
            const __nv_bfloat16* ksrc = khi + (size_t)(tokb + kt0 + row) * Cc + hoff + c16 * 8;
            cpasync16(sb + off, ksrc);
            cpasync16(sb + FS_HALVES * 2 + off,
                      klo + (size_t)(tokb + kt0 + row) * Cc + hoff + c16 * 8);
            cpasync16(sb + 2 * FS_HALVES * 2 + off,
                      vf16 + (size_t)(tokb + kt0 + row) * Cc + hoff + c16 * 8);
        }
    };

    load_kv(0, 0);
    asm volatile("cp.async.commit_group;");
    load_kv(1, 1);
    asm volatile("cp.async.commit_group;");

    int arow = (l & 15);
    int akc  = (l >> 4) * 8;
    int brow_in = (l & 7) + ((l >> 4) & 1) * 8;
    int bkc  = ((l >> 3) & 1) * 8;
    int vrow = (l & 7) + ((l >> 3) & 1) * 8;
    int vcol = ((l >> 4) & 1) * 8;

    uint32_t qh[4][4], ql[4][4];
    float oacc[8][4];
    #pragma unroll
    for (int j = 0; j < 8; j++)
        #pragma unroll
        for (int u = 0; u < 4; u++) oacc[j][u] = 0.f;
    float m0r = -1e30f, m1r = -1e30f, l0r = 0.f, l1r = 0.f;

    const int NCH = Tt / 64;
    for (int c = 0; c < NCH; c++) {
        if (c < NCH - 1) asm volatile("cp.async.wait_group 1;");
        else             asm volatile("cp.async.wait_group 0;");
        __syncthreads();

        if (c == 0) {
            #pragma unroll
            for (int kt = 0; kt < 4; kt++) {
                ldsm4(qh[kt][0], qh[kt][1], qh[kt][2], qh[kt][3],
                      fsb + ((w * 16 + arow) * F_LD + kt * 16 + akc) * 2);
                ldsm4(ql[kt][0], ql[kt][1], ql[kt][2], ql[kt][3],
                      fsb + (FQ_HALVES + (w * 16 + arow) * F_LD + kt * 16 + akc) * 2);
            }
        }

        if (c + 2 < NCH) {
            load_kv(c + 2, (c + 2) % 3);
            asm volatile("cp.async.commit_group;");
        }

        uint32_t SB  = F_STAGE0 + (c % 3) * F_TSTAGE;
        uint32_t KHI = SB, KLO = SB + FS_HALVES, VF = SB + 2 * FS_HALVES;

        // ---- S = Q K^T (bf16 3-term) ----
        float sacc[8][4];
        #pragma unroll
        for (int j = 0; j < 8; j++)
            #pragma unroll
            for (int u = 0; u < 4; u++) sacc[j][u] = 0.f;

        #pragma unroll
        for (int ks = 0; ks < 4; ks++) {
            uint32_t kh[4][4], klr[4][4];
            #pragma unroll
            for (int g = 0; g < 4; g++) {
                uint32_t ro = ((g * 16 + brow_in) * F_LD + bkc + ks * 16) * 2;
                ldsm4(kh[g][0], kh[g][1], kh[g][2], kh[g][3], fsb + KHI * 2 + ro);
                ldsm4(klr[g][0], klr[g][1], klr[g][2], klr[g][3], fsb + KLO * 2 + ro);
            }
            #pragma unroll
            for (int g = 0; g < 4; g++)
                #pragma unroll
                for (int sub = 0; sub < 2; sub++) {
                    int j = g * 2 + sub;
                    mma16816(sacc[j], qh[ks], &kh[g][sub * 2]);
                    mma16816(sacc[j], ql[ks], &kh[g][sub * 2]);
                    mma16816(sacc[j], qh[ks], &klr[g][sub * 2]);
                }
        }

        // ---- online softmax, P packed fp16 ----
        float mx0 = -1e30f, mx1 = -1e30f;
        #pragma unroll
        for (int j = 0; j < 8; j++) {
            mx0 = fmaxf(mx0, fmaxf(sacc[j][0], sacc[j][1]));
            mx1 = fmaxf(mx1, fmaxf(sacc[j][2], sacc[j][3]));
        }
        mx0 = fmaxf(mx0, __shfl_xor_sync(0xffffffffu, mx0, 1));
        mx0 = fmaxf(mx0, __shfl_xor_sync(0xffffffffu, mx0, 2));
        mx1 = fmaxf(mx1, __shfl_xor_sync(0xffffffffu, mx1, 1));
        mx1 = fmaxf(mx1, __shfl_xor_sync(0xffffffffu, mx1, 2));
        float mn0 = fmaxf(m0r, mx0), mn1 = fmaxf(m1r, mx1);
        float cor0 = __expf(m0r - mn0), cor1 = __expf(m1r - mn1);
        m0r = mn0; m1r = mn1;

        uint32_t phf[4][4];
        float rs0 = 0.f, rs1 = 0.f;
        #pragma unroll
        for (int j = 0; j < 8; j++) {
            float e0 = __expf(sacc[j][0] - mn0);
            float e1 = __expf(sacc[j][1] - mn0);
            float e2 = __expf(sacc[j][2] - mn1);
            float e3 = __expf(sacc[j][3] - mn1);
            rs0 += e0 + e1; rs1 += e2 + e3;
            int kt = j >> 1, sl = (j & 1) * 2;
            phf[kt][sl]     = pack_h2(e0, e1);
            phf[kt][sl + 1] = pack_h2(e2, e3);
        }
        rs0 += __shfl_xor_sync(0xffffffffu, rs0, 1);
        rs0 += __shfl_xor_sync(0xffffffffu, rs0, 2);
        rs1 += __shfl_xor_sync(0xffffffffu, rs1, 1);
        rs1 += __shfl_xor_sync(0xffffffffu, rs1, 2);
        l0r = l0r * cor0 + rs0;
        l1r = l1r * cor1 + rs1;
        #pragma unroll
        for (int j = 0; j < 8; j++) {
            oacc[j][0] *= cor0; oacc[j][1] *= cor0;
            oacc[j][2] *= cor1; oacc[j][3] *= cor1;
        }

        // ---- O += P V (fp16, single term) ----
        #pragma unroll
        for (int kt = 0; kt < 4; kt++) {
            #pragma unroll
            for (int dg = 0; dg < 4; dg++) {
                uint32_t vh[4];
                uint32_t ro = ((kt * 16 + vrow) * F_LD + dg * 16 + vcol) * 2;
                ldsm4t(vh[0], vh[1], vh[2], vh[3], fsb + VF * 2 + ro);
                #pragma unroll
                for (int sub = 0; sub < 2; sub++)
                    mma16816h(oacc[dg * 2 + sub], phf[kt], &vh[sub * 2]);
            }
        }
    }

    // ---- epilogue: normalize, hi/lo split, write ----
    float inv0 = 1.0f / l0r, inv1 = 1.0f / l1r;
    int row0 = tokb + q0 + w * 16 + (l >> 2);
    int row1 = row0 + 8;
    #pragma unroll
    for (int dt = 0; dt < 8; dt++) {
        int col = hoff + dt * 8 + (l & 3) * 2;
        float v0 = oacc[dt][0] * inv0, v1 = oacc[dt][1] * inv0;
        float v2 = oacc[dt][2] * inv1, v3 = oacc[dt][3] * inv1;
        uint32_t h0 = pack_bf2(v0, v1);
        uint32_t h1 = pack_bf2(v2, v3);
        *(uint32_t*)(ohi + (size_t)row0 * Cc + col) = h0;
        *(uint32_t*)(ohi + (size_t)row1 * Cc + col) = h1;
        *(uint32_t*)(olo + (size_t)row0 * Cc + col) =
            pack_bf2(bf_lo_res(v0, h0), bf_hi_res(v1, h0));
        *(uint32_t*)(olo + (size_t)row1 * Cc + col) =
            pack_bf2(bf_lo_res(v2, h1), bf_hi_res(v3, h1));
    }
}

// ---------------- host driver -----------------------------------------------
extern "C" void kernel_launch(void* const* d_in, const int* in_sizes, int n_in,
                              void* d_out, int out_size)
{
    const float* x   = (const float*)d_in[0];
    const float* Wq  = (const float*)d_in[1];
    const float* bq  = (const float*)d_in[2];
    const float* Wk  = (const float*)d_in[3];
    const float* bk  = (const float*)d_in[4];
    const float* Wv  = (const float*)d_in[5];
    const float* bv  = (const float*)d_in[6];
    const float* Wo  = (const float*)d_in[7];
    const float* bo  = (const float*)d_in[8];
    const float* Wr1 = (const float*)d_in[9];
    const float* br1 = (const float*)d_in[10];
    const float* Wr2 = (const float*)d_in[11];
    const float* br2 = (const float*)d_in[12];
    float* out = (float*)d_out;

    float* r1;
    cudaGetSymbolAddress((void**)&r1, g_r1);

    __nv_bfloat16 *xhi, *xlo, *rthi, *rtlo, *athi, *atlo;
    __nv_bfloat16 *qhi, *qlo, *khi, *klo;
    __half *vf16;
    __nv_bfloat16 *wqh, *wql, *wkh, *wkl, *wvh, *wvl, *woh, *wol, *wr1h, *wr1l;
    cudaGetSymbolAddress((void**)&xhi,  g_xhi);  cudaGetSymbolAddress((void**)&xlo,  g_xlo);
    cudaGetSymbolAddress((void**)&rthi, g_rthi); cudaGetSymbolAddress((void**)&rtlo, g_rtlo);
    cudaGetSymbolAddress((void**)&athi, g_athi); cudaGetSymbolAddress((void**)&atlo, g_atlo);
    cudaGetSymbolAddress((void**)&qhi,  g_qhi);  cudaGetSymbolAddress((void**)&qlo,  g_qlo);
    cudaGetSymbolAddress((void**)&khi,  g_khi);  cudaGetSymbolAddress((void**)&klo,  g_klo);
    cudaGetSymbolAddress((void**)&vf16, g_vf16);
    cudaGetSymbolAddress((void**)&wqh, g_wq_hi); cudaGetSymbolAddress((void**)&wql, g_wq_lo);
    cudaGetSymbolAddress((void**)&wkh, g_wk_hi); cudaGetSymbolAddress((void**)&wkl, g_wk_lo);
    cudaGetSymbolAddress((void**)&wvh, g_wv_hi); cudaGetSymbolAddress((void**)&wvl, g_wv_lo);
    cudaGetSymbolAddress((void**)&woh, g_wo_hi); cudaGetSymbolAddress((void**)&wol, g_wo_lo);
    cudaGetSymbolAddress((void**)&wr1h, g_wr1_hi); cudaGetSymbolAddress((void**)&wr1l, g_wr1_lo);

    cudaFuncSetAttribute(gemm_mma<0>, cudaFuncAttributeMaxDynamicSharedMemorySize, G_SMEM_BYTES);
    cudaFuncSetAttribute(gemm_mma<1>, cudaFuncAttributeMaxDynamicSharedMemorySize, G_SMEM_BYTES);
    cudaFuncSetAttribute(gemm_mma<2>, cudaFuncAttributeMaxDynamicSharedMemorySize, G_SMEM_BYTES);
    cudaFuncSetAttribute(gemm_mma<3>, cudaFuncAttributeMaxDynamicSharedMemorySize, G_SMEM_BYTES);
    cudaFuncSetAttribute(flash_mma, cudaFuncAttributeMaxDynamicSharedMemorySize, F_SMEM_BYTES);

    dim3 gemm_grid(Cc / 128, Mm / 128);   // (8, 32)
    int act4 = (Mm * Cc) / 4;
    int w4   = (Cc * Cc) / 4;

    // launch #1: all 5 weight conversions, one batched launch
    CvtBatch5 bat;
    bat.src[0] = Wr1; bat.hi[0] = wr1h; bat.lo[0] = wr1l;
    bat.src[1] = Wq;  bat.hi[1] = wqh;  bat.lo[1] = wql;
    bat.src[2] = Wk;  bat.hi[2] = wkh;  bat.lo[2] = wkl;
    bat.src[3] = Wv;  bat.hi[3] = wvh;  bat.lo[3] = wvl;
    bat.src[4] = Wo;  bat.hi[4] = woh;  bat.lo[4] = wol;
    cvt_batch_kernel<<<dim3(w4 / 256, 5), 256>>>(bat, w4);

    // launch #2: x -> hi/lo
    cvt_hilo_kernel<<<act4 / 256, 256>>>(x, xhi, xlo, act4);

    // launches #3, #4: mean pool (wide grid)
    mean_part_kernel<<<dim3(Cc / 256, 64, Bb), 256>>>(x);
    mean_reduce_kernel<<<(Bb * Cc) / 256, 256>>>();

    // launch #5 (ncu -s 5 target): r1 = tanh(x @ Wr1^T + br1)
    gemm_mma<1><<<gemm_grid, 256, G_SMEM_BYTES>>>(xhi, xlo, wr1h, wr1l, br1, r1,
                                                  nullptr, nullptr, 1.0f);

    // routing -> routed bf16 hi/lo
    routing_kernel<<<Mm, 128>>>(r1, Wr2, br2, x, rthi, rtlo);

    // Q (pre-scaled), K -> bf16 hi/lo; V -> fp16 single
    gemm_mma<2><<<gemm_grid, 256, G_SMEM_BYTES>>>(xhi,  xlo,  wqh, wql, bq, nullptr,
                                                  qhi, qlo, ATT_SCALE);
    gemm_mma<2><<<gemm_grid, 256, G_SMEM_BYTES>>>(rthi, rtlo, wkh, wkl, bk, nullptr,
                                                  khi, klo, 1.0f);
    gemm_mma<3><<<gemm_grid, 256, G_SMEM_BYTES>>>(rthi, rtlo, wvh, wvl, bv, nullptr,
                                                  (__nv_bfloat16*)vf16, nullptr, 1.0f);

    // tensor-core flash attention -> att hi/lo
    flash_mma<<<dim3(Tt / 128, Hh, Bb), 256, F_SMEM_BYTES>>>(
        qhi, qlo, khi, klo, vf16, athi, atlo);

    // output projection (fp32 out)
    gemm_mma<0><<<gemm_grid, 256, G_SMEM_BYTES>>>(athi, atlo, woh, wol, bo, out,
                                                  nullptr, nullptr, 1.0f);
}

// round 7
// speedup vs baseline: 4.2873x; 1.4941x over previous
#include <cuda_runtime.h>
#include <cuda_bf16.h>
#include <cuda_fp16.h>
#include <math.h>
#include <stdint.h>

// Problem constants
#define Bb 2
#define Tt 2048
#define Cc 1024
#define Hh 16
#define Dd 64
#define Mm (Bb*Tt)           // 4096 tokens
#define ATT_SCALE 0.125f     // D^-0.5

// ---------------- scratch (device globals; no allocations allowed) ----------
__device__ float g_r1[Mm*Cc];
__device__ float g_part[64*Bb*Cc];
__device__ float g_mean[Bb*Cc];

// fp16 buffers (activations hi/lo, weights single)
__device__ __half g_xh[Mm*Cc],  g_xl[Mm*Cc];
__device__ __half g_rth[Mm*Cc], g_rtl[Mm*Cc];
__device__ __half g_ath[Mm*Cc], g_atl[Mm*Cc];
__device__ __half g_qh[Mm*Cc],  g_ql[Mm*Cc];
__device__ __half g_kf[Mm*Cc],  g_vf[Mm*Cc];
__device__ __half g_wq[Cc*Cc], g_wk[Cc*Cc], g_wv[Cc*Cc];
__device__ __half g_wo[Cc*Cc], g_wr1[Cc*Cc];

// ================= PTX helpers (sm_100 baseline ISA only) ====================
__device__ __forceinline__ uint32_t smem_u32(const void* p) {
    uint32_t a;
    asm("{ .reg .u64 t; cvta.to.shared.u64 t, %1; cvt.u32.u64 %0, t; }"
        : "=r"(a) : "l"(p));
    return a;
}
__device__ __forceinline__ void cpasync16(uint32_t dst, const void* src) {
    asm volatile("cp.async.cg.shared.global [%0], [%1], 16;" :: "r"(dst), "l"(src));
}
__device__ __forceinline__ void ldsm4(uint32_t& r0, uint32_t& r1, uint32_t& r2,
                                      uint32_t& r3, uint32_t addr) {
    asm volatile("ldmatrix.sync.aligned.m8n8.x4.shared.b16 {%0,%1,%2,%3}, [%4];"
        : "=r"(r0), "=r"(r1), "=r"(r2), "=r"(r3) : "r"(addr));
}
__device__ __forceinline__ void ldsm4t(uint32_t& r0, uint32_t& r1, uint32_t& r2,
                                       uint32_t& r3, uint32_t addr) {
    asm volatile("ldmatrix.sync.aligned.m8n8.x4.trans.shared.b16 {%0,%1,%2,%3}, [%4];"
        : "=r"(r0), "=r"(r1), "=r"(r2), "=r"(r3) : "r"(addr));
}
__device__ __forceinline__ void mma16816h(float* d, const uint32_t* a, const uint32_t* b) {
    asm volatile(
        "mma.sync.aligned.m16n8k16.row.col.f32.f16.f16.f32 "
        "{%0,%1,%2,%3}, {%4,%5,%6,%7}, {%8,%9}, {%0,%1,%2,%3};"
        : "+f"(d[0]), "+f"(d[1]), "+f"(d[2]), "+f"(d[3])
        : "r"(a[0]), "r"(a[1]), "r"(a[2]), "r"(a[3]), "r"(b[0]), "r"(b[1]));
}
__device__ __forceinline__ uint32_t pack_h2(float a, float b) {
    __half2 h = __floats2half2_rn(a, b);
    return *(uint32_t*)&h;
}
__device__ __forceinline__ float h_lo_res(float v, uint32_t pk) {
    __half2 h2 = *(__half2*)&pk;
    return v - __low2float(h2);
}
__device__ __forceinline__ float h_hi_res(float v, uint32_t pk) {
    __half2 h2 = *(__half2*)&pk;
    return v - __high2float(h2);
}

// ---------------- mean pool (deterministic two-stage) -----------------------
__global__ __launch_bounds__(256) void mean_part_kernel(const float* __restrict__ x) {
    int c  = blockIdx.x * 256 + threadIdx.x;
    int b  = blockIdx.z;
    int t0 = blockIdx.y * (Tt / 64);
    float s = 0.f;
    #pragma unroll 8
    for (int tt = 0; tt < Tt / 64; tt++)
        s += x[((size_t)b * Tt + t0 + tt) * Cc + c];
    g_part[((size_t)blockIdx.y * Bb + b) * Cc + c] = s;
}

__global__ __launch_bounds__(256) void mean_reduce_kernel() {
    int idx = blockIdx.x * 256 + threadIdx.x;
    if (idx < Bb * Cc) {
        float s = 0.f;
        #pragma unroll
        for (int u = 0; u < 64; u++) s += g_part[(size_t)u * Bb * Cc + idx];
        g_mean[idx] = s * (1.0f / (float)Tt);
    }
}

// ---------------- conversions ------------------------------------------------
__global__ __launch_bounds__(256) void cvt_hilo16_kernel(
    const float* __restrict__ x, __half* __restrict__ hi,
    __half* __restrict__ lo, int n4)
{
    int i = blockIdx.x * 256 + threadIdx.x;
    if (i >= n4) return;
    float4 v = ((const float4*)x)[i];
    uint32_t h0 = pack_h2(v.x, v.y);
    uint32_t h1 = pack_h2(v.z, v.w);
    uint2 hh; hh.x = h0; hh.y = h1;
    uint2 ll;
    ll.x = pack_h2(h_lo_res(v.x, h0), h_hi_res(v.y, h0));
    ll.y = pack_h2(h_lo_res(v.z, h1), h_hi_res(v.w, h1));
    ((uint2*)hi)[i] = hh;
    ((uint2*)lo)[i] = ll;
}

struct CvtW5 {
    const float* src[5];
    __half* dst[5];
};
__global__ __launch_bounds__(256) void cvt_w_kernel(CvtW5 b, int n4) {
    int t = blockIdx.y;
    int i = blockIdx.x * 256 + threadIdx.x;
    if (i >= n4) return;
    float4 v = ((const float4*)b.src[t])[i];
    uint2 o;
    o.x = pack_h2(v.x, v.y);
    o.y = pack_h2(v.z, v.w);
    ((uint2*)b.dst[t])[i] = o;
}

// ================= HMMA GEMM (fp16 2-term) ===================================
// Y[M,N] = A[M,K] @ W[N,K]^T + bias,  A = Ah + Al (fp16 split), W fp16 single.
// CTA 128x128, BK=64, stage {Ah,Al,W}, 2-stage cp.async, 2 CTAs/SM.
// MODE 0: fp32; MODE 1: tanh fp32; MODE 2: fp16 hi/lo (x scale); MODE 3: fp16
#define G_NCH 16
#define G_LD 72
#define G_TILE (128 * G_LD * 2)             // 18432 bytes per tensor tile
#define G_STAGE_BYTES (3 * G_TILE)          // 55296
#define G_SMEM_BYTES (2 * G_STAGE_BYTES)    // 110592

template<int MODE>
__global__ __launch_bounds__(256, 2) void gemm_mma(
    const __half* __restrict__ Ah, const __half* __restrict__ Al,
    const __half* __restrict__ W,
    const float* __restrict__ bias, float* __restrict__ out,
    __half* __restrict__ outh, __half* __restrict__ outl, float scale)
{
    extern __shared__ __align__(16) uint8_t gsm[];
    uint32_t base = smem_u32(gsm);

    int tid = threadIdx.x;
    int wid = tid >> 5;
    int l   = tid & 31;
    int wm  = wid >> 1;
    int wn  = wid & 1;
    int m0  = blockIdx.y * 128;
    int n0  = blockIdx.x * 128;

    int lrow = tid >> 3;        // 0..31
    int lc16 = tid & 7;

    int arow = wm * 32 + (l & 15);
    int akc  = (l >> 4) * 8;
    int brow_in = (l & 7) + ((l >> 4) & 1) * 8;
    int bkc  = ((l >> 3) & 1) * 8;

    float acc[2][8][4];
    #pragma unroll
    for (int i = 0; i < 2; i++)
        #pragma unroll
        for (int j = 0; j < 8; j++)
            #pragma unroll
            for (int u = 0; u < 4; u++) acc[i][j][u] = 0.f;

    auto load_tile = [&](int c, int s) {
        int k0 = c * 64;
        uint32_t sb = base + s * G_STAGE_BYTES;
        #pragma unroll
        for (int it = 0; it < 4; it++) {
            int row = lrow + it * 32;
            uint32_t off = (row * G_LD + lc16 * 8) * 2;
            cpasync16(sb + off, Ah + (size_t)(m0 + row) * Cc + k0 + lc16 * 8);
            cpasync16(sb + G_TILE + off, Al + (size_t)(m0 + row) * Cc + k0 + lc16 * 8);
            cpasync16(sb + 2 * G_TILE + off, W + (size_t)(n0 + row) * Cc + k0 + lc16 * 8);
        }
    };

    load_tile(0, 0);
    asm volatile("cp.async.commit_group;");

    for (int c = 0; c < G_NCH; c++) {
        asm volatile("cp.async.wait_group 0;");
        __syncthreads();
        if (c + 1 < G_NCH) {
            load_tile(c + 1, (c + 1) & 1);
            asm volatile("cp.async.commit_group;");
        }

        uint32_t ab = base + (c & 1) * G_STAGE_BYTES;
        uint32_t lb = ab + G_TILE;
        uint32_t wb = ab + 2 * G_TILE;
        #pragma unroll
        for (int ks = 0; ks < 4; ks++) {
            uint32_t ah[2][4], al[2][4];
            #pragma unroll
            for (int i = 0; i < 2; i++) {
                uint32_t ro = ((arow + i * 16) * G_LD + akc + ks * 16) * 2;
                ldsm4(ah[i][0], ah[i][1], ah[i][2], ah[i][3], ab + ro);
                ldsm4(al[i][0], al[i][1], al[i][2], al[i][3], lb + ro);
            }
            uint32_t wf[4][4];
            #pragma unroll
            for (int nn = 0; nn < 4; nn++)
                ldsm4(wf[nn][0], wf[nn][1], wf[nn][2], wf[nn][3],
                      wb + ((wn * 64 + nn * 16 + brow_in) * G_LD + bkc + ks * 16) * 2);
            #pragma unroll
            for (int i = 0; i < 2; i++)
                #pragma unroll
                for (int j = 0; j < 8; j++) {
                    mma16816h(acc[i][j], ah[i], &wf[j >> 1][(j & 1) * 2]);
                    mma16816h(acc[i][j], al[i], &wf[j >> 1][(j & 1) * 2]);
                }
        }
    }

    // epilogue
    #pragma unroll
    for (int i = 0; i < 2; i++) {
        int row = m0 + wm * 32 + i * 16 + (l >> 2);
        #pragma unroll
        for (int j = 0; j < 8; j++) {
            int col = n0 + wn * 64 + j * 8 + (l & 3) * 2;
            float b0v = __ldg(&bias[col]);
            float b1v = __ldg(&bias[col + 1]);
            float v0 = acc[i][j][0] + b0v;
            float v1 = acc[i][j][1] + b1v;
            float v2 = acc[i][j][2] + b0v;
            float v3 = acc[i][j][3] + b1v;
            if (MODE == 1) {
                v0 = tanhf(v0); v1 = tanhf(v1);
                v2 = tanhf(v2); v3 = tanhf(v3);
            }
            if (MODE == 2) {
                v0 *= scale; v1 *= scale; v2 *= scale; v3 *= scale;
                uint32_t h0 = pack_h2(v0, v1);
                uint32_t h1 = pack_h2(v2, v3);
                *(uint32_t*)(outh + (size_t)row * Cc + col) = h0;
                *(uint32_t*)(outh + (size_t)(row + 8) * Cc + col) = h1;
                *(uint32_t*)(outl + (size_t)row * Cc + col) =
                    pack_h2(h_lo_res(v0, h0), h_hi_res(v1, h0));
                *(uint32_t*)(outl + (size_t)(row + 8) * Cc + col) =
                    pack_h2(h_lo_res(v2, h1), h_hi_res(v3, h1));
            } else if (MODE == 3) {
                *(uint32_t*)(outh + (size_t)row * Cc + col) = pack_h2(v0, v1);
                *(uint32_t*)(outh + (size_t)(row + 8) * Cc + col) = pack_h2(v2, v3);
            } else if (MODE != 2 && MODE != 3) {
                float2 p0; p0.x = v0; p0.y = v1;
                float2 p1; p1.x = v2; p1.y = v3;
                *(float2*)(out + (size_t)row * Cc + col) = p0;
                *(float2*)(out + (size_t)(row + 8) * Cc + col) = p1;
            }
        }
    }
}

// ---------------- routing: logits -> softmax -> routed (fp16 hi/lo) ---------
__global__ __launch_bounds__(128) void routing_kernel(
    const float* __restrict__ r1, const float* __restrict__ Wr2,
    const float* __restrict__ br2, const float* __restrict__ x,
    __half* __restrict__ rth, __half* __restrict__ rtl)
{
    int t = blockIdx.x;
    int b = t >> 11;
    int tid = threadIdx.x;

    const float* rrow = r1 + (size_t)t * Cc;
    float s0 = 0.f, s1 = 0.f, s2 = 0.f;
    for (int c = tid; c < Cc; c += 128) {
        float vv = rrow[c];
        s0 = fmaf(vv, Wr2[c],          s0);
        s1 = fmaf(vv, Wr2[Cc + c],     s1);
        s2 = fmaf(vv, Wr2[2 * Cc + c], s2);
    }
    #pragma unroll
    for (int o = 16; o; o >>= 1) {
        s0 += __shfl_xor_sync(0xffffffffu, s0, o);
        s1 += __shfl_xor_sync(0xffffffffu, s1, o);
        s2 += __shfl_xor_sync(0xffffffffu, s2, o);
    }
    __shared__ float red[3][4];
    __shared__ float wsh[2];
    if ((tid & 31) == 0) {
        red[0][tid >> 5] = s0; red[1][tid >> 5] = s1; red[2][tid >> 5] = s2;
    }
    __syncthreads();
    if (tid == 0) {
        float l0 = red[0][0] + red[0][1] + red[0][2] + red[0][3] + br2[0];
        float l1 = red[1][0] + red[1][1] + red[1][2] + red[1][3] + br2[1];
        float l2 = red[2][0] + red[2][1] + red[2][2] + red[2][3] + br2[2];
        float mx = fmaxf(l0, fmaxf(l1, l2));
        float e0 = expf(l0 - mx), e1 = expf(l1 - mx), e2 = expf(l2 - mx);
        float inv = 1.0f / (e0 + e1 + e2);
        wsh[0] = e0 * inv; wsh[1] = e1 * inv;
    }
    __syncthreads();
    float w0 = wsh[0], w1 = wsh[1];

    const float4* x4 = (const float4*)(x + (size_t)t * Cc);
    const float4* m4 = (const float4*)(g_mean + (size_t)b * Cc);
    uint2* ho = (uint2*)(rth + (size_t)t * Cc);
    uint2* lo = (uint2*)(rtl + (size_t)t * Cc);
    for (int c4 = tid; c4 < Cc / 4; c4 += 128) {
        float4 xv = x4[c4], mv = m4[c4];
        float r0 = xv.x * w0 + mv.x * w1;
        float r1v = xv.y * w0 + mv.y * w1;
        float r2 = xv.z * w0 + mv.z * w1;
        float r3 = xv.w * w0 + mv.w * w1;
        uint32_t h0 = pack_h2(r0, r1v);
        uint32_t h1 = pack_h2(r2, r3);
        uint2 hh; hh.x = h0; hh.y = h1;
        uint2 ll;
        ll.x = pack_h2(h_lo_res(r0, h0), h_hi_res(r1v, h0));
        ll.y = pack_h2(h_lo_res(r2, h1), h_hi_res(r3, h1));
        ho[c4] = hh;
        lo[c4] = ll;
    }
}

// ================= tensor-core flash attention (all fp16) ====================
// CTA: 128 Q rows (8 warps x 16), KV chunks of 64, D=64, 3-stage pipeline.
// S = Qh*K + Ql*K (fp16 2-term); PV = P(fp16) x V(fp16) single term.
#define F_LD 72
#define FQ_HALVES (128 * F_LD)
#define FS_HALVES (64 * F_LD)
#define F_TSTAGE (2 * FS_HALVES)            // K, V
#define F_STAGE0 (2 * FQ_HALVES)
#define F_SMEM_BYTES ((2 * FQ_HALVES + 3 * F_TSTAGE) * 2)   // 92160

__global__ __launch_bounds__(256, 1) void flash_mma(
    const __half* __restrict__ qhp, const __half* __restrict__ qlp,
    const __half* __restrict__ kf, const __half* __restrict__ vf,
    __half* __restrict__ oh, __half* __restrict__ ol)
{
    extern __shared__ __half fsh[];
    uint32_t fsb = smem_u32(fsh);

    int tid = threadIdx.x;
    int w   = tid >> 5;
    int l   = tid & 31;
    int q0  = blockIdx.x * 128;
    int h   = blockIdx.y;
    int b   = blockIdx.z;
    int tokb = b * Tt;
    int hoff = h * Dd;

    // ---- load Q (hi+lo), rides with chunk-0's commit group ----
    {
        const __half* srcs[2] = {qhp, qlp};
        #pragma unroll
        for (int ten = 0; ten < 2; ten++) {
            #pragma unroll
            for (int it = 0; it < 4; it++) {
                int idx = tid + it * 256;
                int row = idx >> 3, c16 = idx & 7;
                uint32_t dst = fsb + ((ten * FQ_HALVES) + row * F_LD + c16 * 8) * 2;
                cpasync16(dst, srcs[ten] + (size_t)(tokb + q0 + row) * Cc + hoff + c16 * 8);
            }
        }
    }
    auto load_kv = [&](int c, int s) {
        int kt0 = c * 64;
        uint32_t sb = fsb + (F_STAGE0 + s * F_TSTAGE) * 2;
        #pragma unroll
        for (int it = 0; it < 2; it++) {
            int idx = tid + it * 256;
            int row = idx >> 3, c16 = idx & 7;
            uint32_t off = (row * F_LD + c16 * 8) * 2;
            cpasync16(sb + off, kf + (size_t)(tokb + kt0 + row) * Cc + hoff + c16 * 8);
            cpasync16(sb + FS_HALVES * 2 + off,
                      vf + (size_t)(tokb + kt0 + row) * Cc + hoff + c16 * 8);
        }
    };

    load_kv(0, 0);
    asm volatile("cp.async.commit_group;");
    load_kv(1, 1);
    asm volatile("cp.async.commit_group;");

    int arow = (l & 15);
    int akc  = (l >> 4) * 8;
    int brow_in = (l & 7) + ((l >> 4) & 1) * 8;
    int bkc  = ((l >> 3) & 1) * 8;
    int vrow = (l & 7) + ((l >> 3) & 1) * 8;
    int vcol = ((l >> 4) & 1) * 8;

    uint32_t qh[4][4], ql[4][4];
    float oacc[8][4];
    #pragma unroll
    for (int j = 0; j < 8; j++)
        #pragma unroll
        for (int u = 0; u < 4; u++) oacc[j][u] = 0.f;
    float m0r = -1e30f, m1r = -1e30f, l0r = 0.f, l1r = 0.f;

    const int NCH = Tt / 64;
    for (int c = 0; c < NCH; c++) {
        if (c < NCH - 1) asm volatile("cp.async.wait_group 1;");
        else             asm volatile("cp.async.wait_group 0;");
        __syncthreads();

        if (c == 0) {
            #pragma unroll
            for (int kt = 0; kt < 4; kt++) {
                ldsm4(qh[kt][0], qh[kt][1], qh[kt][2], qh[kt][3],
                      fsb + ((w * 16 + arow) * F_LD + kt * 16 + akc) * 2);
                ldsm4(ql[kt][0], ql[kt][1], ql[kt][2], ql[kt][3],
                      fsb + (FQ_HALVES + (w * 16 + arow) * F_LD + kt * 16 + akc) * 2);
            }
        }

        if (c + 2 < NCH) {
            load_kv(c + 2, (c + 2) % 3);
            asm volatile("cp.async.commit_group;");
        }

        uint32_t SB = F_STAGE0 + (c % 3) * F_TSTAGE;
        uint32_t KF = SB, VF = SB + FS_HALVES;

        // ---- S = Q K^T (fp16 2-term) ----
        float sacc[8][4];
        #pragma unroll
        for (int j = 0; j < 8; j++)
            #pragma unroll
            for (int u = 0; u < 4; u++) sacc[j][u] = 0.f;

        #pragma unroll
        for (int ks = 0; ks < 4; ks++) {
            uint32_t kh[4][4];
            #pragma unroll
            for (int g = 0; g < 4; g++) {
                uint32_t ro = ((g * 16 + brow_in) * F_LD + bkc + ks * 16) * 2;
                ldsm4(kh[g][0], kh[g][1], kh[g][2], kh[g][3], fsb + KF * 2 + ro);
            }
            #pragma unroll
            for (int g = 0; g < 4; g++)
                #pragma unroll
                for (int sub = 0; sub < 2; sub++) {
                    int j = g * 2 + sub;
                    mma16816h(sacc[j], qh[ks], &kh[g][sub * 2]);
                    mma16816h(sacc[j], ql[ks], &kh[g][sub * 2]);
                }
        }

        // ---- online softmax, P packed fp16 ----
        float mx0 = -1e30f, mx1 = -1e30f;
        #pragma unroll
        for (int j = 0; j < 8; j++) {
            mx0 = fmaxf(mx0, fmaxf(sacc[j][0], sacc[j][1]));
            mx1 = fmaxf(mx1, fmaxf(sacc[j][2], sacc[j][3]));
        }
        mx0 = fmaxf(mx0, __shfl_xor_sync(0xffffffffu, mx0, 1));
        mx0 = fmaxf(mx0, __shfl_xor_sync(0xffffffffu, mx0, 2));
        mx1 = fmaxf(mx1, __shfl_xor_sync(0xffffffffu, mx1, 1));
        mx1 = fmaxf(mx1, __shfl_xor_sync(0xffffffffu, mx1, 2));
        float mn0 = fmaxf(m0r, mx0), mn1 = fmaxf(m1r, mx1);
        float cor0 = __expf(m0r - mn0), cor1 = __expf(m1r - mn1);
        m0r = mn0; m1r = mn1;

        uint32_t phf[4][4];
        float rs0 = 0.f, rs1 = 0.f;
        #pragma unroll
        for (int j = 0; j < 8; j++) {
            float e0 = __expf(sacc[j][0] - mn0);
            float e1 = __expf(sacc[j][1] - mn0);
            float e2 = __expf(sacc[j][2] - mn1);
            float e3 = __expf(sacc[j][3] - mn1);
            rs0 += e0 + e1; rs1 += e2 + e3;
            int kt = j >> 1, sl = (j & 1) * 2;
            phf[kt][sl]     = pack_h2(e0, e1);
            phf[kt][sl + 1] = pack_h2(e2, e3);
        }
        rs0 += __shfl_xor_sync(0xffffffffu, rs0, 1);
        rs0 += __shfl_xor_sync(0xffffffffu, rs0, 2);
        rs1 += __shfl_xor_sync(0xffffffffu, rs1, 1);
        rs1 += __shfl_xor_sync(0xffffffffu, rs1, 2);
        l0r = l0r * cor0 + rs0;
        l1r = l1r * cor1 + rs1;
        #pragma unroll
        for (int j = 0; j < 8; j++) {
            oacc[j][0] *= cor0; oacc[j][1] *= cor0;
            oacc[j][2] *= cor1; oacc[j][3] *= cor1;
        }

        // ---- O += P V (fp16, single term) ----
        #pragma unroll
        for (int kt = 0; kt < 4; kt++) {
            #pragma unroll
            for (int dg = 0; dg < 4; dg++) {
                uint32_t vh[4];
                uint32_t ro = ((kt * 16 + vrow) * F_LD + dg * 16 + vcol) * 2;
                ldsm4t(vh[0], vh[1], vh[2], vh[3], fsb + VF * 2 + ro);
                #pragma unroll
                for (int sub = 0; sub < 2; sub++)
                    mma16816h(oacc[dg * 2 + sub], phf[kt], &vh[sub * 2]);
            }
        }
    }

    // ---- epilogue: normalize, fp16 hi/lo split, write ----
    float inv0 = 1.0f / l0r, inv1 = 1.0f / l1r;
    int row0 = tokb + q0 + w * 16 + (l >> 2);
    int row1 = row0 + 8;
    #pragma unroll
    for (int dt = 0; dt < 8; dt++) {
        int col = hoff + dt * 8 + (l & 3) * 2;
        float v0 = oacc[dt][0] * inv0, v1 = oacc[dt][1] * inv0;
        float v2 = oacc[dt][2] * inv1, v3 = oacc[dt][3] * inv1;
        uint32_t h0 = pack_h2(v0, v1);
        uint32_t h1 = pack_h2(v2, v3);
        *(uint32_t*)(oh + (size_t)row0 * Cc + col) = h0;
        *(uint32_t*)(oh + (size_t)row1 * Cc + col) = h1;
        *(uint32_t*)(ol + (size_t)row0 * Cc + col) =
            pack_h2(h_lo_res(v0, h0), h_hi_res(v1, h0));
        *(uint32_t*)(ol + (size_t)row1 * Cc + col) =
            pack_h2(h_lo_res(v2, h1), h_hi_res(v3, h1));
    }
}

// ---------------- host driver -----------------------------------------------
extern "C" void kernel_launch(void* const* d_in, const int* in_sizes, int n_in,
                              void* d_out, int out_size)
{
    const float* x   = (const float*)d_in[0];
    const float* Wq  = (const float*)d_in[1];
    const float* bq  = (const float*)d_in[2];
    const float* Wk  = (const float*)d_in[3];
    const float* bk  = (const float*)d_in[4];
    const float* Wv  = (const float*)d_in[5];
    const float* bv  = (const float*)d_in[6];
    const float* Wo  = (const float*)d_in[7];
    const float* bo  = (const float*)d_in[8];
    const float* Wr1 = (const float*)d_in[9];
    const float* br1 = (const float*)d_in[10];
    const float* Wr2 = (const float*)d_in[11];
    const float* br2 = (const float*)d_in[12];
    float* out = (float*)d_out;

    float* r1;
    cudaGetSymbolAddress((void**)&r1, g_r1);

    __half *xh, *xl, *rth, *rtl, *ath, *atl, *qh, *ql, *kf, *vf;
    __half *wq, *wk, *wv, *wo, *wr1;
    cudaGetSymbolAddress((void**)&xh,  g_xh);  cudaGetSymbolAddress((void**)&xl,  g_xl);
    cudaGetSymbolAddress((void**)&rth, g_rth); cudaGetSymbolAddress((void**)&rtl, g_rtl);
    cudaGetSymbolAddress((void**)&ath, g_ath); cudaGetSymbolAddress((void**)&atl, g_atl);
    cudaGetSymbolAddress((void**)&qh,  g_qh);  cudaGetSymbolAddress((void**)&ql,  g_ql);
    cudaGetSymbolAddress((void**)&kf,  g_kf);  cudaGetSymbolAddress((void**)&vf,  g_vf);
    cudaGetSymbolAddress((void**)&wq,  g_wq);  cudaGetSymbolAddress((void**)&wk,  g_wk);
    cudaGetSymbolAddress((void**)&wv,  g_wv);  cudaGetSymbolAddress((void**)&wo,  g_wo);
    cudaGetSymbolAddress((void**)&wr1, g_wr1);

    cudaFuncSetAttribute(gemm_mma<0>, cudaFuncAttributeMaxDynamicSharedMemorySize, G_SMEM_BYTES);
    cudaFuncSetAttribute(gemm_mma<1>, cudaFuncAttributeMaxDynamicSharedMemorySize, G_SMEM_BYTES);
    cudaFuncSetAttribute(gemm_mma<2>, cudaFuncAttributeMaxDynamicSharedMemorySize, G_SMEM_BYTES);
    cudaFuncSetAttribute(gemm_mma<3>, cudaFuncAttributeMaxDynamicSharedMemorySize, G_SMEM_BYTES);
    cudaFuncSetAttribute(flash_mma, cudaFuncAttributeMaxDynamicSharedMemorySize, F_SMEM_BYTES);

    dim3 gemm_grid(Cc / 128, Mm / 128);   // (8, 32)
    int act4 = (Mm * Cc) / 4;
    int w4   = (Cc * Cc) / 4;

    // weight conversions (one batched launch, fp16 single)
    CvtW5 bat;
    bat.src[0] = Wr1; bat.dst[0] = wr1;
    bat.src[1] = Wq;  bat.dst[1] = wq;
    bat.src[2] = Wk;  bat.dst[2] = wk;
    bat.src[3] = Wv;  bat.dst[3] = wv;
    bat.src[4] = Wo;  bat.dst[4] = wo;
    cvt_w_kernel<<<dim3(w4 / 256, 5), 256>>>(bat, w4);

    // x -> fp16 hi/lo
    cvt_hilo16_kernel<<<act4 / 256, 256>>>(x, xh, xl, act4);

    // mean pool
    mean_part_kernel<<<dim3(Cc / 256, 64, Bb), 256>>>(x);
    mean_reduce_kernel<<<(Bb * Cc) / 256, 256>>>();

    // r1 = tanh(x @ Wr1^T + br1)
    gemm_mma<1><<<gemm_grid, 256, G_SMEM_BYTES>>>(xh, xl, wr1, br1, r1,
                                                  nullptr, nullptr, 1.0f);

    // routing -> routed fp16 hi/lo
    routing_kernel<<<Mm, 128>>>(r1, Wr2, br2, x, rth, rtl);

    // Q (pre-scaled, fp16 hi/lo), K (fp16), V (fp16)
    gemm_mma<2><<<gemm_grid, 256, G_SMEM_BYTES>>>(xh, xl, wq, bq, nullptr,
                                                  qh, ql, ATT_SCALE);
    gemm_mma<3><<<gemm_grid, 256, G_SMEM_BYTES>>>(rth, rtl, wk, bk, nullptr,
                                                  kf, nullptr, 1.0f);
    gemm_mma<3><<<gemm_grid, 256, G_SMEM_BYTES>>>(rth, rtl, wv, bv, nullptr,
                                                  vf, nullptr, 1.0f);

    // flash attention -> att fp16 hi/lo
    flash_mma<<<dim3(Tt / 128, Hh, Bb), 256, F_SMEM_BYTES>>>(
        qh, ql, kf, vf, ath, atl);

    // output projection (fp32 out)
    gemm_mma<0><<<gemm_grid, 256, G_SMEM_BYTES>>>(ath, atl, wo, bo, out,
                                                  nullptr, nullptr, 1.0f);
}

// round 8
// speedup vs baseline: 4.5970x; 1.0722x over previous
#include <cuda_runtime.h>
#include <cuda_bf16.h>
#include <cuda_fp16.h>
#include <math.h>
#include <stdint.h>

// Problem constants
#define Bb 2
#define Tt 2048
#define Cc 1024
#define Hh 16
#define Dd 64
#define Mm (Bb*Tt)           // 4096 tokens
#define ATT_SCALE 0.125f     // D^-0.5

// ---------------- scratch (device globals; no allocations allowed) ----------
__device__ float g_r1[Mm*Cc];
__device__ float g_part[64*Bb*Cc];
__device__ float g_mean[Bb*Cc];

// fp16 buffers (activations hi/lo, weights single)
__device__ __half g_xh[Mm*Cc],  g_xl[Mm*Cc];
__device__ __half g_rth[Mm*Cc], g_rtl[Mm*Cc];
__device__ __half g_ath[Mm*Cc], g_atl[Mm*Cc];
__device__ __half g_qh[Mm*Cc],  g_ql[Mm*Cc];
__device__ __half g_kf[Mm*Cc],  g_vf[Mm*Cc];
__device__ __half g_wq[Cc*Cc], g_wk[Cc*Cc], g_wv[Cc*Cc];
__device__ __half g_wo[Cc*Cc], g_wr1[Cc*Cc];

// ================= PTX helpers (sm_100 baseline ISA only) ====================
__device__ __forceinline__ uint32_t smem_u32(const void* p) {
    uint32_t a;
    asm("{ .reg .u64 t; cvta.to.shared.u64 t, %1; cvt.u32.u64 %0, t; }"
        : "=r"(a) : "l"(p));
    return a;
}
__device__ __forceinline__ void cpasync16(uint32_t dst, const void* src) {
    asm volatile("cp.async.cg.shared.global [%0], [%1], 16;" :: "r"(dst), "l"(src));
}
__device__ __forceinline__ void ldsm4(uint32_t& r0, uint32_t& r1, uint32_t& r2,
                                      uint32_t& r3, uint32_t addr) {
    asm volatile("ldmatrix.sync.aligned.m8n8.x4.shared.b16 {%0,%1,%2,%3}, [%4];"
        : "=r"(r0), "=r"(r1), "=r"(r2), "=r"(r3) : "r"(addr));
}
__device__ __forceinline__ void ldsm4t(uint32_t& r0, uint32_t& r1, uint32_t& r2,
                                       uint32_t& r3, uint32_t addr) {
    asm volatile("ldmatrix.sync.aligned.m8n8.x4.trans.shared.b16 {%0,%1,%2,%3}, [%4];"
        : "=r"(r0), "=r"(r1), "=r"(r2), "=r"(r3) : "r"(addr));
}
__device__ __forceinline__ void mma16816h(float* d, const uint32_t* a, const uint32_t* b) {
    asm volatile(
        "mma.sync.aligned.m16n8k16.row.col.f32.f16.f16.f32 "
        "{%0,%1,%2,%3}, {%4,%5,%6,%7}, {%8,%9}, {%0,%1,%2,%3};"
        : "+f"(d[0]), "+f"(d[1]), "+f"(d[2]), "+f"(d[3])
        : "r"(a[0]), "r"(a[1]), "r"(a[2]), "r"(a[3]), "r"(b[0]), "r"(b[1]));
}
__device__ __forceinline__ uint32_t pack_h2(float a, float b) {
    __half2 h = __floats2half2_rn(a, b);
    return *(uint32_t*)&h;
}
__device__ __forceinline__ float h_lo_res(float v, uint32_t pk) {
    __half2 h2 = *(__half2*)&pk;
    return v - __low2float(h2);
}
__device__ __forceinline__ float h_hi_res(float v, uint32_t pk) {
    __half2 h2 = *(__half2*)&pk;
    return v - __high2float(h2);
}

// ---------------- mean pool (deterministic two-stage) -----------------------
__global__ __launch_bounds__(256) void mean_part_kernel(const float* __restrict__ x) {
    int c  = blockIdx.x * 256 + threadIdx.x;
    int b  = blockIdx.z;
    int t0 = blockIdx.y * (Tt / 64);
    float s = 0.f;
    #pragma unroll 8
    for (int tt = 0; tt < Tt / 64; tt++)
        s += x[((size_t)b * Tt + t0 + tt) * Cc + c];
    g_part[((size_t)blockIdx.y * Bb + b) * Cc + c] = s;
}

__global__ __launch_bounds__(256) void mean_reduce_kernel() {
    int idx = blockIdx.x * 256 + threadIdx.x;
    if (idx < Bb * Cc) {
        float s = 0.f;
        #pragma unroll
        for (int u = 0; u < 64; u++) s += g_part[(size_t)u * Bb * Cc + idx];
        g_mean[idx] = s * (1.0f / (float)Tt);
    }
}

// ---------------- conversions ------------------------------------------------
__global__ __launch_bounds__(256) void cvt_hilo16_kernel(
    const float* __restrict__ x, __half* __restrict__ hi,
    __half* __restrict__ lo, int n4)
{
    int i = blockIdx.x * 256 + threadIdx.x;
    if (i >= n4) return;
    float4 v = ((const float4*)x)[i];
    uint32_t h0 = pack_h2(v.x, v.y);
    uint32_t h1 = pack_h2(v.z, v.w);
    uint2 hh; hh.x = h0; hh.y = h1;
    uint2 ll;
    ll.x = pack_h2(h_lo_res(v.x, h0), h_hi_res(v.y, h0));
    ll.y = pack_h2(h_lo_res(v.z, h1), h_hi_res(v.w, h1));
    ((uint2*)hi)[i] = hh;
    ((uint2*)lo)[i] = ll;
}

struct CvtW5 {
    const float* src[5];
    __half* dst[5];
};
__global__ __launch_bounds__(256) void cvt_w_kernel(CvtW5 b, int n4) {
    int t = blockIdx.y;
    int i = blockIdx.x * 256 + threadIdx.x;
    if (i >= n4) return;
    float4 v = ((const float4*)b.src[t])[i];
    uint2 o;
    o.x = pack_h2(v.x, v.y);
    o.y = pack_h2(v.z, v.w);
    ((uint2*)b.dst[t])[i] = o;
}

// ================= HMMA GEMM (fp16 2-term) ===================================
// Y[M,N] = A[M,K] @ W[N,K]^T + bias,  A = Ah + Al (fp16 split), W fp16 single.
// CTA 128x128, BK=64, stage {Ah,Al,W}, 2-stage cp.async, 2 CTAs/SM.
// MODE 0: fp32; MODE 1: tanh fp32; MODE 2: fp16 hi/lo (x scale); MODE 3: fp16
#define G_NCH 16
#define G_LD 72
#define G_TILE (128 * G_LD * 2)             // 18432 bytes per tensor tile
#define G_STAGE_BYTES (3 * G_TILE)          // 55296
#define G_SMEM_BYTES (2 * G_STAGE_BYTES)    // 110592

template<int MODE>
__global__ __launch_bounds__(256, 2) void gemm_mma(
    const __half* __restrict__ Ah, const __half* __restrict__ Al,
    const __half* __restrict__ W,
    const float* __restrict__ bias, float* __restrict__ out,
    __half* __restrict__ outh, __half* __restrict__ outl, float scale)
{
    extern __shared__ __align__(16) uint8_t gsm[];
    uint32_t base = smem_u32(gsm);

    int tid = threadIdx.x;
    int wid = tid >> 5;
    int l   = tid & 31;
    int wm  = wid >> 1;
    int wn  = wid & 1;
    int m0  = blockIdx.y * 128;
    int n0  = blockIdx.x * 128;

    int lrow = tid >> 3;        // 0..31
    int lc16 = tid & 7;

    int arow = wm * 32 + (l & 15);
    int akc  = (l >> 4) * 8;
    int brow_in = (l & 7) + ((l >> 4) & 1) * 8;
    int bkc  = ((l >> 3) & 1) * 8;

    float acc[2][8][4];
    #pragma unroll
    for (int i = 0; i < 2; i++)
        #pragma unroll
        for (int j = 0; j < 8; j++)
            #pragma unroll
            for (int u = 0; u < 4; u++) acc[i][j][u] = 0.f;

    auto load_tile = [&](int c, int s) {
        int k0 = c * 64;
        uint32_t sb = base + s * G_STAGE_BYTES;
        #pragma unroll
        for (int it = 0; it < 4; it++) {
            int row = lrow + it * 32;
            uint32_t off = (row * G_LD + lc16 * 8) * 2;
            cpasync16(sb + off, Ah + (size_t)(m0 + row) * Cc + k0 + lc16 * 8);
            cpasync16(sb + G_TILE + off, Al + (size_t)(m0 + row) * Cc + k0 + lc16 * 8);
            cpasync16(sb + 2 * G_TILE + off, W + (size_t)(n0 + row) * Cc + k0 + lc16 * 8);
        }
    };

    load_tile(0, 0);
    asm volatile("cp.async.commit_group;");

    for (int c = 0; c < G_NCH; c++) {
        asm volatile("cp.async.wait_group 0;");
        __syncthreads();
        if (c + 1 < G_NCH) {
            load_tile(c + 1, (c + 1) & 1);
            asm volatile("cp.async.commit_group;");
        }

        uint32_t ab = base + (c & 1) * G_STAGE_BYTES;
        uint32_t lb = ab + G_TILE;
        uint32_t wb = ab + 2 * G_TILE;
        #pragma unroll
        for (int ks = 0; ks < 4; ks++) {
            uint32_t ah[2][4], al[2][4];
            #pragma unroll
            for (int i = 0; i < 2; i++) {
                uint32_t ro = ((arow + i * 16) * G_LD + akc + ks * 16) * 2;
                ldsm4(ah[i][0], ah[i][1], ah[i][2], ah[i][3], ab + ro);
                ldsm4(al[i][0], al[i][1], al[i][2], al[i][3], lb + ro);
            }
            uint32_t wf[4][4];
            #pragma unroll
            for (int nn = 0; nn < 4; nn++)
                ldsm4(wf[nn][0], wf[nn][1], wf[nn][2], wf[nn][3],
                      wb + ((wn * 64 + nn * 16 + brow_in) * G_LD + bkc + ks * 16) * 2);
            #pragma unroll
            for (int i = 0; i < 2; i++)
                #pragma unroll
                for (int j = 0; j < 8; j++) {
                    mma16816h(acc[i][j], ah[i], &wf[j >> 1][(j & 1) * 2]);
                    mma16816h(acc[i][j], al[i], &wf[j >> 1][(j & 1) * 2]);
                }
        }
    }

    // epilogue
    #pragma unroll
    for (int i = 0; i < 2; i++) {
        int row = m0 + wm * 32 + i * 16 + (l >> 2);
        #pragma unroll
        for (int j = 0; j < 8; j++) {
            int col = n0 + wn * 64 + j * 8 + (l & 3) * 2;
            float b0v = __ldg(&bias[col]);
            float b1v = __ldg(&bias[col + 1]);
            float v0 = acc[i][j][0] + b0v;
            float v1 = acc[i][j][1] + b1v;
            float v2 = acc[i][j][2] + b0v;
            float v3 = acc[i][j][3] + b1v;
            if (MODE == 1) {
                v0 = tanhf(v0); v1 = tanhf(v1);
                v2 = tanhf(v2); v3 = tanhf(v3);
            }
            if (MODE == 2) {
                v0 *= scale; v1 *= scale; v2 *= scale; v3 *= scale;
                uint32_t h0 = pack_h2(v0, v1);
                uint32_t h1 = pack_h2(v2, v3);
                *(uint32_t*)(outh + (size_t)row * Cc + col) = h0;
                *(uint32_t*)(outh + (size_t)(row + 8) * Cc + col) = h1;
                *(uint32_t*)(outl + (size_t)row * Cc + col) =
                    pack_h2(h_lo_res(v0, h0), h_hi_res(v1, h0));
                *(uint32_t*)(outl + (size_t)(row + 8) * Cc + col) =
                    pack_h2(h_lo_res(v2, h1), h_hi_res(v3, h1));
            } else if (MODE == 3) {
                *(uint32_t*)(outh + (size_t)row * Cc + col) = pack_h2(v0, v1);
                *(uint32_t*)(outh + (size_t)(row + 8) * Cc + col) = pack_h2(v2, v3);
            } else if (MODE != 2 && MODE != 3) {
                float2 p0; p0.x = v0; p0.y = v1;
                float2 p1; p1.x = v2; p1.y = v3;
                *(float2*)(out + (size_t)row * Cc + col) = p0;
                *(float2*)(out + (size_t)(row + 8) * Cc + col) = p1;
            }
        }
    }
}

// ---------------- routing: logits -> softmax -> routed (fp16 hi/lo) ---------
__global__ __launch_bounds__(128) void routing_kernel(
    const float* __restrict__ r1, const float* __restrict__ Wr2,
    const float* __restrict__ br2, const float* __restrict__ x,
    __half* __restrict__ rth, __half* __restrict__ rtl)
{
    int t = blockIdx.x;
    int b = t >> 11;
    int tid = threadIdx.x;

    const float* rrow = r1 + (size_t)t * Cc;
    float s0 = 0.f, s1 = 0.f, s2 = 0.f;
    for (int c = tid; c < Cc; c += 128) {
        float vv = rrow[c];
        s0 = fmaf(vv, Wr2[c],          s0);
        s1 = fmaf(vv, Wr2[Cc + c],     s1);
        s2 = fmaf(vv, Wr2[2 * Cc + c], s2);
    }
    #pragma unroll
    for (int o = 16; o; o >>= 1) {
        s0 += __shfl_xor_sync(0xffffffffu, s0, o);
        s1 += __shfl_xor_sync(0xffffffffu, s1, o);
        s2 += __shfl_xor_sync(0xffffffffu, s2, o);
    }
    __shared__ float red[3][4];
    __shared__ float wsh[2];
    if ((tid & 31) == 0) {
        red[0][tid >> 5] = s0; red[1][tid >> 5] = s1; red[2][tid >> 5] = s2;
    }
    __syncthreads();
    if (tid == 0) {
        float l0 = red[0][0] + red[0][1] + red[0][2] + red[0][3] + br2[0];
        float l1 = red[1][0] + red[1][1] + red[1][2] + red[1][3] + br2[1];
        float l2 = red[2][0] + red[2][1] + red[2][2] + red[2][3] + br2[2];
        float mx = fmaxf(l0, fmaxf(l1, l2));
        float e0 = expf(l0 - mx), e1 = expf(l1 - mx), e2 = expf(l2 - mx);
        float inv = 1.0f / (e0 + e1 + e2);
        wsh[0] = e0 * inv; wsh[1] = e1 * inv;
    }
    __syncthreads();
    float w0 = wsh[0], w1 = wsh[1];

    const float4* x4 = (const float4*)(x + (size_t)t * Cc);
    const float4* m4 = (const float4*)(g_mean + (size_t)b * Cc);
    uint2* ho = (uint2*)(rth + (size_t)t * Cc);
    uint2* lo = (uint2*)(rtl + (size_t)t * Cc);
    for (int c4 = tid; c4 < Cc / 4; c4 += 128) {
        float4 xv = x4[c4], mv = m4[c4];
        float r0 = xv.x * w0 + mv.x * w1;
        float r1v = xv.y * w0 + mv.y * w1;
        float r2 = xv.z * w0 + mv.z * w1;
        float r3 = xv.w * w0 + mv.w * w1;
        uint32_t h0 = pack_h2(r0, r1v);
        uint32_t h1 = pack_h2(r2, r3);
        uint2 hh; hh.x = h0; hh.y = h1;
        uint2 ll;
        ll.x = pack_h2(h_lo_res(r0, h0), h_hi_res(r1v, h0));
        ll.y = pack_h2(h_lo_res(r2, h1), h_hi_res(r3, h1));
        ho[c4] = hh;
        lo[c4] = ll;
    }
}

// ================= tensor-core flash attention (all fp16) ====================
// CTA: 64 Q rows (4 warps x 16), 128 threads, KV chunks of 64, 3-stage pipe.
// 2 CTAs/SM so one CTA's softmax overlaps the other's MMA phase.
// S = Qh*K + Ql*K (fp16 2-term); PV = P(fp16) x V(fp16) single term.
#define F_LD 72
#define FQ_HALVES (64 * F_LD)
#define FS_HALVES (64 * F_LD)
#define F_TSTAGE (2 * FS_HALVES)            // K, V
#define F_STAGE0 (2 * FQ_HALVES)
#define F_SMEM_BYTES ((2 * FQ_HALVES + 3 * F_TSTAGE) * 2)   // 73728

__global__ __launch_bounds__(128, 2) void flash_mma(
    const __half* __restrict__ qhp, const __half* __restrict__ qlp,
    const __half* __restrict__ kf, const __half* __restrict__ vf,
    __half* __restrict__ oh, __half* __restrict__ ol)
{
    extern __shared__ __half fsh[];
    uint32_t fsb = smem_u32(fsh);

    int tid = threadIdx.x;
    int w   = tid >> 5;            // 0..3
    int l   = tid & 31;
    int q0  = blockIdx.x * 64;
    int h   = blockIdx.y;
    int b   = blockIdx.z;
    int tokb = b * Tt;
    int hoff = h * Dd;

    // ---- load Q (hi+lo), rides with chunk-0's commit group ----
    {
        const __half* srcs[2] = {qhp, qlp};
        #pragma unroll
        for (int ten = 0; ten < 2; ten++) {
            #pragma unroll
            for (int it = 0; it < 4; it++) {
                int idx = tid + it * 128;          // [0,512)
                int row = idx >> 3, c16 = idx & 7;
                uint32_t dst = fsb + ((ten * FQ_HALVES) + row * F_LD + c16 * 8) * 2;
                cpasync16(dst, srcs[ten] + (size_t)(tokb + q0 + row) * Cc + hoff + c16 * 8);
            }
        }
    }
    auto load_kv = [&](int c, int s) {
        int kt0 = c * 64;
        uint32_t sb = fsb + (F_STAGE0 + s * F_TSTAGE) * 2;
        #pragma unroll
        for (int it = 0; it < 4; it++) {
            int idx = tid + it * 128;              // [0,512)
            int row = idx >> 3, c16 = idx & 7;
            uint32_t off = (row * F_LD + c16 * 8) * 2;
            cpasync16(sb + off, kf + (size_t)(tokb + kt0 + row) * Cc + hoff + c16 * 8);
            cpasync16(sb + FS_HALVES * 2 + off,
                      vf + (size_t)(tokb + kt0 + row) * Cc + hoff + c16 * 8);
        }
    };

    load_kv(0, 0);
    asm volatile("cp.async.commit_group;");
    load_kv(1, 1);
    asm volatile("cp.async.commit_group;");

    int arow = (l & 15);
    int akc  = (l >> 4) * 8;
    int brow_in = (l & 7) + ((l >> 4) & 1) * 8;
    int bkc  = ((l >> 3) & 1) * 8;
    int vrow = (l & 7) + ((l >> 3) & 1) * 8;
    int vcol = ((l >> 4) & 1) * 8;

    uint32_t qh[4][4], ql[4][4];
    float oacc[8][4];
    #pragma unroll
    for (int j = 0; j < 8; j++)
        #pragma unroll
        for (int u = 0; u < 4; u++) oacc[j][u] = 0.f;
    float m0r = -1e30f, m1r = -1e30f, l0r = 0.f, l1r = 0.f;

    const int NCH = Tt / 64;
    for (int c = 0; c < NCH; c++) {
        if (c < NCH - 1) asm volatile("cp.async.wait_group 1;");
        else             asm volatile("cp.async.wait_group 0;");
        __syncthreads();

        if (c == 0) {
            #pragma unroll
            for (int kt = 0; kt < 4; kt++) {
                ldsm4(qh[kt][0], qh[kt][1], qh[kt][2], qh[kt][3],
                      fsb + ((w * 16 + arow) * F_LD + kt * 16 + akc) * 2);
                ldsm4(ql[kt][0], ql[kt][1], ql[kt][2], ql[kt][3],
                      fsb + (FQ_HALVES + (w * 16 + arow) * F_LD + kt * 16 + akc) * 2);
            }
        }

        if (c + 2 < NCH) {
            load_kv(c + 2, (c + 2) % 3);
            asm volatile("cp.async.commit_group;");
        }

        uint32_t SB = F_STAGE0 + (c % 3) * F_TSTAGE;
        uint32_t KF = SB, VF = SB + FS_HALVES;

        // ---- S = Q K^T (fp16 2-term) ----
        float sacc[8][4];
        #pragma unroll
        for (int j = 0; j < 8; j++)
            #pragma unroll
            for (int u = 0; u < 4; u++) sacc[j][u] = 0.f;

        #pragma unroll
        for (int ks = 0; ks < 4; ks++) {
            uint32_t kh[4][4];
            #pragma unroll
            for (int g = 0; g < 4; g++) {
                uint32_t ro = ((g * 16 + brow_in) * F_LD + bkc + ks * 16) * 2;
                ldsm4(kh[g][0], kh[g][1], kh[g][2], kh[g][3], fsb + KF * 2 + ro);
            }
            #pragma unroll
            for (int g = 0; g < 4; g++)
                #pragma unroll
                for (int sub = 0; sub < 2; sub++) {
                    int j = g * 2 + sub;
                    mma16816h(sacc[j], qh[ks], &kh[g][sub * 2]);
                    mma16816h(sacc[j], ql[ks], &kh[g][sub * 2]);
                }
        }

        // ---- online softmax, P packed fp16 ----
        float mx0 = -1e30f, mx1 = -1e30f;
        #pragma unroll
        for (int j = 0; j < 8; j++) {
            mx0 = fmaxf(mx0, fmaxf(sacc[j][0], sacc[j][1]));
            mx1 = fmaxf(mx1, fmaxf(sacc[j][2], sacc[j][3]));
        }
        mx0 = fmaxf(mx0, __shfl_xor_sync(0xffffffffu, mx0, 1));
        mx0 = fmaxf(mx0, __shfl_xor_sync(0xffffffffu, mx0, 2));
        mx1 = fmaxf(mx1, __shfl_xor_sync(0xffffffffu, mx1, 1));
        mx1 = fmaxf(mx1, __shfl_xor_sync(0xffffffffu, mx1, 2));
        float mn0 = fmaxf(m0r, mx0), mn1 = fmaxf(m1r, mx1);
        float cor0 = __expf(m0r - mn0), cor1 = __expf(m1r - mn1);
        m0r = mn0; m1r = mn1;

        uint32_t phf[4][4];
        float rs0 = 0.f, rs1 = 0.f;
        #pragma unroll
        for (int j = 0; j < 8; j++) {
            float e0 = __expf(sacc[j][0] - mn0);
            float e1 = __expf(sacc[j][1] - mn0);
            float e2 = __expf(sacc[j][2] - mn1);
            float e3 = __expf(sacc[j][3] - mn1);
            rs0 += e0 + e1; rs1 += e2 + e3;
            int kt = j >> 1, sl = (j & 1) * 2;
            phf[kt][sl]     = pack_h2(e0, e1);
            phf[kt][sl + 1] = pack_h2(e2, e3);
        }
        rs0 += __shfl_xor_sync(0xffffffffu, rs0, 1);
        rs0 += __shfl_xor_sync(0xffffffffu, rs0, 2);
        rs1 += __shfl_xor_sync(0xffffffffu, rs1, 1);
        rs1 += __shfl_xor_sync(0xffffffffu, rs1, 2);
        l0r = l0r * cor0 + rs0;
        l1r = l1r * cor1 + rs1;
        #pragma unroll
        for (int j = 0; j < 8; j++) {
            oacc[j][0] *= cor0; oacc[j][1] *= cor0;
            oacc[j][2] *= cor1; oacc[j][3] *= cor1;
        }

        // ---- O += P V (fp16, single term) ----
        #pragma unroll
        for (int kt = 0; kt < 4; kt++) {
            #pragma unroll
            for (int dg = 0; dg < 4; dg++) {
                uint32_t vh[4];
                uint32_t ro = ((kt * 16 + vrow) * F_LD + dg * 16 + vcol) * 2;
                ldsm4t(vh[0], vh[1], vh[2], vh[3], fsb + VF * 2 + ro);
                #pragma unroll
                for (int sub = 0; sub < 2; sub++)
                    mma16816h(oacc[dg * 2 + sub], phf[kt], &vh[sub * 2]);
            }
        }
    }

    // ---- epilogue: normalize, fp16 hi/lo split, write ----
    float inv0 = 1.0f / l0r, inv1 = 1.0f / l1r;
    int row0 = tokb + q0 + w * 16 + (l >> 2);
    int row1 = row0 + 8;
    #pragma unroll
    for (int dt = 0; dt < 8; dt++) {
        int col = hoff + dt * 8 + (l & 3) * 2;
        float v0 = oacc[dt][0] * inv0, v1 = oacc[dt][1] * inv0;
        float v2 = oacc[dt][2] * inv1, v3 = oacc[dt][3] * inv1;
        uint32_t h0 = pack_h2(v0, v1);
        uint32_t h1 = pack_h2(v2, v3);
        *(uint32_t*)(oh + (size_t)row0 * Cc + col) = h0;
        *(uint32_t*)(oh + (size_t)row1 * Cc + col) = h1;
        *(uint32_t*)(ol + (size_t)row0 * Cc + col) =
            pack_h2(h_lo_res(v0, h0), h_hi_res(v1, h0));
        *(uint32_t*)(ol + (size_t)row1 * Cc + col) =
            pack_h2(h_lo_res(v2, h1), h_hi_res(v3, h1));
    }
}

// ---------------- host driver -----------------------------------------------
extern "C" void kernel_launch(void* const* d_in, const int* in_sizes, int n_in,
                              void* d_out, int out_size)
{
    const float* x   = (const float*)d_in[0];
    const float* Wq  = (const float*)d_in[1];
    const float* bq  = (const float*)d_in[2];
    const float* Wk  = (const float*)d_in[3];
    const float* bk  = (const float*)d_in[4];
    const float* Wv  = (const float*)d_in[5];
    const float* bv  = (const float*)d_in[6];
    const float* Wo  = (const float*)d_in[7];
    const float* bo  = (const float*)d_in[8];
    const float* Wr1 = (const float*)d_in[9];
    const float* br1 = (const float*)d_in[10];
    const float* Wr2 = (const float*)d_in[11];
    const float* br2 = (const float*)d_in[12];
    float* out = (float*)d_out;

    float* r1;
    cudaGetSymbolAddress((void**)&r1, g_r1);

    __half *xh, *xl, *rth, *rtl, *ath, *atl, *qh, *ql, *kf, *vf;
    __half *wq, *wk, *wv, *wo, *wr1;
    cudaGetSymbolAddress((void**)&xh,  g_xh);  cudaGetSymbolAddress((void**)&xl,  g_xl);
    cudaGetSymbolAddress((void**)&rth, g_rth); cudaGetSymbolAddress((void**)&rtl, g_rtl);
    cudaGetSymbolAddress((void**)&ath, g_ath); cudaGetSymbolAddress((void**)&atl, g_atl);
    cudaGetSymbolAddress((void**)&qh,  g_qh);  cudaGetSymbolAddress((void**)&ql,  g_ql);
    cudaGetSymbolAddress((void**)&kf,  g_kf);  cudaGetSymbolAddress((void**)&vf,  g_vf);
    cudaGetSymbolAddress((void**)&wq,  g_wq);  cudaGetSymbolAddress((void**)&wk,  g_wk);
    cudaGetSymbolAddress((void**)&wv,  g_wv);  cudaGetSymbolAddress((void**)&wo,  g_wo);
    cudaGetSymbolAddress((void**)&wr1, g_wr1);

    cudaFuncSetAttribute(gemm_mma<0>, cudaFuncAttributeMaxDynamicSharedMemorySize, G_SMEM_BYTES);
    cudaFuncSetAttribute(gemm_mma<1>, cudaFuncAttributeMaxDynamicSharedMemorySize, G_SMEM_BYTES);
    cudaFuncSetAttribute(gemm_mma<2>, cudaFuncAttributeMaxDynamicSharedMemorySize, G_SMEM_BYTES);
    cudaFuncSetAttribute(gemm_mma<3>, cudaFuncAttributeMaxDynamicSharedMemorySize, G_SMEM_BYTES);
    cudaFuncSetAttribute(flash_mma, cudaFuncAttributeMaxDynamicSharedMemorySize, F_SMEM_BYTES);

    dim3 gemm_grid(Cc / 128, Mm / 128);   // (8, 32)
    int act4 = (Mm * Cc) / 4;
    int w4   = (Cc * Cc) / 4;

    // weight conversions (one batched launch, fp16 single)
    CvtW5 bat;
    bat.src[0] = Wr1; bat.dst[0] = wr1;
    bat.src[1] = Wq;  bat.dst[1] = wq;
    bat.src[2] = Wk;  bat.dst[2] = wk;
    bat.src[3] = Wv;  bat.dst[3] = wv;
    bat.src[4] = Wo;  bat.dst[4] = wo;
    cvt_w_kernel<<<dim3(w4 / 256, 5), 256>>>(bat, w4);

    // x -> fp16 hi/lo
    cvt_hilo16_kernel<<<act4 / 256, 256>>>(x, xh, xl, act4);

    // mean pool
    mean_part_kernel<<<dim3(Cc / 256, 64, Bb), 256>>>(x);
    mean_reduce_kernel<<<(Bb * Cc) / 256, 256>>>();

    // r1 = tanh(x @ Wr1^T + br1)
    gemm_mma<1><<<gemm_grid, 256, G_SMEM_BYTES>>>(xh, xl, wr1, br1, r1,
                                                  nullptr, nullptr, 1.0f);

    // routing -> routed fp16 hi/lo
    routing_kernel<<<Mm, 128>>>(r1, Wr2, br2, x, rth, rtl);

    // Q (pre-scaled, fp16 hi/lo), K (fp16), V (fp16)
    gemm_mma<2><<<gemm_grid, 256, G_SMEM_BYTES>>>(xh, xl, wq, bq, nullptr,
                                                  qh, ql, ATT_SCALE);
    gemm_mma<3><<<gemm_grid, 256, G_SMEM_BYTES>>>(rth, rtl, wk, bk, nullptr,
                                                  kf, nullptr, 1.0f);
    gemm_mma<3><<<gemm_grid, 256, G_SMEM_BYTES>>>(rth, rtl, wv, bv, nullptr,
                                                  vf, nullptr, 1.0f);

    // flash attention (64-row CTAs, 2/SM) -> att fp16 hi/lo
    flash_mma<<<dim3(Tt / 64, Hh, Bb), 128, F_SMEM_BYTES>>>(
        qh, ql, kf, vf, ath, atl);

    // output projection (fp32 out)
    gemm_mma<0><<<gemm_grid, 256, G_SMEM_BYTES>>>(ath, atl, wo, bo, out,
                                                  nullptr, nullptr, 1.0f);
}